// round 1
// baseline (speedup 1.0000x reference)
#include <cuda_runtime.h>
#include <cstdint>

// ---------------- problem constants ----------------
#define B_   2
#define S_   2048
#define DIM_ 2048
#define NH_  32
#define NKV_ 8
#define HD_  64
#define QKVN 3072            // (32 + 16) * 64
#define M_   (B_ * S_)       // 4096 rows

// ---------------- scratch (static device globals; no allocation) ------------
__device__ float g_qkv[(size_t)M_ * QKVN];   // qkv projection output (rope applied in place)
__device__ float g_att[(size_t)M_ * DIM_];   // attention output (b,s,h,d) flattened

// ============================================================================
// SGEMM: C[M][N] = A[M][K] @ B[K][N], all row-major, fp32.
// 128x128 block tile, 8x8 per-thread microtile, BK=8, 256 threads.
// All dims divisible by tile sizes for this problem (no bounds checks).
// ============================================================================
#define BM 128
#define BN 128
#define BK 8
#define TM 8
#define TN 8

__global__ __launch_bounds__(256) void sgemm_kernel(
    const float* __restrict__ A, const float* __restrict__ B,
    float* __restrict__ C, int M, int N, int K)
{
    __shared__ float As[BK][BM];
    __shared__ float Bs[BK][BN];

    const int tid  = threadIdx.x;
    const int brow = blockIdx.y;
    const int bcol = blockIdx.x;

    const float* Ab = A + (size_t)brow * BM * K;
    const float* Bb = B + (size_t)bcol * BN;

    const int arow  = tid & 127;          // 0..127
    const int acol  = (tid >> 7) * 4;     // 0 or 4
    const int brl   = tid >> 5;           // 0..7
    const int bcl   = (tid & 31) * 4;     // 0..124

    const int trow = (tid / 16) * TM;
    const int tcol = (tid % 16) * TN;

    float acc[TM][TN];
#pragma unroll
    for (int i = 0; i < TM; i++)
#pragma unroll
        for (int j = 0; j < TN; j++) acc[i][j] = 0.f;

    for (int k0 = 0; k0 < K; k0 += BK) {
        float4 av = *(const float4*)(Ab + (size_t)arow * K + k0 + acol);
        As[acol + 0][arow] = av.x;
        As[acol + 1][arow] = av.y;
        As[acol + 2][arow] = av.z;
        As[acol + 3][arow] = av.w;
        *(float4*)(&Bs[brl][bcl]) = *(const float4*)(Bb + (size_t)(k0 + brl) * N + bcl);
        __syncthreads();

#pragma unroll
        for (int k = 0; k < BK; k++) {
            float a[TM], b[TN];
            *(float4*)(a)     = *(const float4*)(&As[k][trow]);
            *(float4*)(a + 4) = *(const float4*)(&As[k][trow + 4]);
            *(float4*)(b)     = *(const float4*)(&Bs[k][tcol]);
            *(float4*)(b + 4) = *(const float4*)(&Bs[k][tcol + 4]);
#pragma unroll
            for (int i = 0; i < TM; i++)
#pragma unroll
                for (int j = 0; j < TN; j++)
                    acc[i][j] += a[i] * b[j];
        }
        __syncthreads();
    }

    float* Cb = C + (size_t)(brow * BM + trow) * N + bcol * BN + tcol;
#pragma unroll
    for (int i = 0; i < TM; i++) {
#pragma unroll
        for (int j = 0; j < TN; j += 4) {
            float4 v = make_float4(acc[i][j], acc[i][j + 1], acc[i][j + 2], acc[i][j + 3]);
            *(float4*)(Cb + (size_t)i * N + j) = v;
        }
    }
}

// ============================================================================
// RoPE, in place on g_qkv. Applies to q heads (cols 0..2047) and k heads
// (cols 2048..2559). One thread per (row, head, pair).
// ============================================================================
__global__ __launch_bounds__(256) void rope_kernel(float* __restrict__ qkv,
                                                   const float* __restrict__ fc)
{
    const int NPAIR = M_ * (NH_ + NKV_) * (HD_ / 2);   // 4096*40*32
    int idx = blockIdx.x * blockDim.x + threadIdx.x;
    if (idx >= NPAIR) return;
    int p   = idx & 31;
    int hh  = (idx >> 5) % (NH_ + NKV_);
    int row = idx / ((NH_ + NKV_) * 32);
    int s   = row & (S_ - 1);

    float2 f = *(const float2*)(fc + (size_t)s * HD_ + p * 2);
    float* ptr = qkv + (size_t)row * QKVN + hh * HD_ + p * 2;
    float2 x = *(float2*)ptr;
    float2 o;
    o.x = x.x * f.x - x.y * f.y;
    o.y = x.y * f.x + x.x * f.y;
    *(float2*)ptr = o;
}

// ============================================================================
// Flash attention, fp32, causal, GQA (kvh = h/4).
// Grid (S/64, NH, B), 256 threads. BQ = BKV = 64, D = 64.
// Phase A (scores): thread -> 4 q-rows x 4 k-cols (k interleaved by 16).
// Phase B (PV + output): thread -> 1 q-row x 16 d (d interleaved 4x16).
// ============================================================================
#define FS 68   // smem row stride (floats): 68*4 bytes = 272, 16B aligned, low conflicts

__global__ __launch_bounds__(256) void flash_kernel(const float* __restrict__ qkv,
                                                    float* __restrict__ att)
{
    extern __shared__ float sm[];
    float* Qs       = sm;                    // 64*FS
    float* Ks       = Qs + 64 * FS;
    float* Vs       = Ks + 64 * FS;
    float* Ps       = Vs + 64 * FS;
    float* row_m    = Ps + 64 * FS;          // 64
    float* row_l    = row_m + 64;            // 64
    float* row_mnew = row_l + 64;            // 64
    float* row_sc   = row_mnew + 64;         // 64
    float* part     = row_sc + 64;           // 64*16

    const int tid   = threadIdx.x;
    const int qtile = blockIdx.x;
    const int h     = blockIdx.y;
    const int b     = blockIdx.z;
    const int kvh   = h >> 2;
    const int q0    = qtile * 64;

    const float* qbase = qkv + (size_t)(b * S_ + q0) * QKVN + h * HD_;
    const float* kbase = qkv + (size_t)(b * S_) * QKVN + DIM_ + kvh * HD_;
    const float* vbase = kbase + NKV_ * HD_;

    // load Q tile (64 x 64)
#pragma unroll
    for (int i = 0; i < 4; i++) {
        int idx = tid + 256 * i;            // 0..1023 float4 slots
        int r   = idx >> 4;
        int c4  = (idx & 15) << 2;
        float4 v = *(const float4*)(qbase + (size_t)r * QKVN + c4);
        *(float4*)(Qs + r * FS + c4) = v;
    }
    if (tid < 64) { row_m[tid] = -1e30f; row_l[tid] = 0.f; }

    // phase A mapping
    const int qa = (tid >> 4) << 2;   // 0,4,...,60
    const int kb = tid & 15;          // 0..15
    // phase B mapping
    const int qr2 = tid >> 2;         // 0..63
    const int tq  = tid & 3;          // 0..3

    float4 acc[4];
#pragma unroll
    for (int i = 0; i < 4; i++) acc[i] = make_float4(0.f, 0.f, 0.f, 0.f);

    for (int j = 0; j <= qtile; j++) {
        __syncthreads();   // prev PV done; safe to overwrite K/V/part

        const float* kt = kbase + (size_t)(j * 64) * QKVN;
        const float* vt = vbase + (size_t)(j * 64) * QKVN;
#pragma unroll
        for (int i = 0; i < 4; i++) {
            int idx = tid + 256 * i;
            int r   = idx >> 4;
            int c4  = (idx & 15) << 2;
            *(float4*)(Ks + r * FS + c4) = *(const float4*)(kt + (size_t)r * QKVN + c4);
            *(float4*)(Vs + r * FS + c4) = *(const float4*)(vt + (size_t)r * QKVN + c4);
        }
        __syncthreads();

        // ---- scores: s[qq][jj] for q rows qa..qa+3, k cols kb + 16*jj ----
        float s[4][4];
#pragma unroll
        for (int a = 0; a < 4; a++)
#pragma unroll
            for (int c = 0; c < 4; c++) s[a][c] = 0.f;

#pragma unroll 4
        for (int d4 = 0; d4 < 16; d4++) {
            float4 q4[4], k4[4];
#pragma unroll
            for (int a = 0; a < 4; a++)
                q4[a] = *(const float4*)(Qs + (qa + a) * FS + d4 * 4);
#pragma unroll
            for (int c = 0; c < 4; c++)
                k4[c] = *(const float4*)(Ks + (kb + 16 * c) * FS + d4 * 4);
#pragma unroll
            for (int a = 0; a < 4; a++)
#pragma unroll
                for (int c = 0; c < 4; c++)
                    s[a][c] += q4[a].x * k4[c].x + q4[a].y * k4[c].y +
                               q4[a].z * k4[c].z + q4[a].w * k4[c].w;
        }

        // mask + scale + per-thread row max
#pragma unroll
        for (int a = 0; a < 4; a++) {
            float pm = -1e30f;
            int qi = q0 + qa + a;
#pragma unroll
            for (int c = 0; c < 4; c++) {
                int kj = j * 64 + kb + 16 * c;
                float sv = (kj <= qi) ? s[a][c] * 0.125f : -1e30f;
                s[a][c] = sv;
                pm = fmaxf(pm, sv);
            }
            part[(qa + a) * 16 + kb] = pm;
        }
        __syncthreads();

        if (kb == 0) {
#pragma unroll
            for (int a = 0; a < 4; a++) {
                int r = qa + a;
                float rm = part[r * 16];
#pragma unroll
                for (int g = 1; g < 16; g++) rm = fmaxf(rm, part[r * 16 + g]);
                float mo = row_m[r];
                float mn = fmaxf(mo, rm);
                row_mnew[r] = mn;
                row_sc[r]   = __expf(mo - mn);
                row_m[r]    = mn;
            }
        }
        __syncthreads();

        // exp, write P, partial sums
#pragma unroll
        for (int a = 0; a < 4; a++) {
            int r = qa + a;
            float mn = row_mnew[r];
            float ps = 0.f;
#pragma unroll
            for (int c = 0; c < 4; c++) {
                float p = __expf(s[a][c] - mn);
                ps += p;
                Ps[r * FS + kb + 16 * c] = p;
            }
            part[r * 16 + kb] = ps;
        }
        __syncthreads();

        if (kb == 0) {
#pragma unroll
            for (int a = 0; a < 4; a++) {
                int r = qa + a;
                float sum = 0.f;
#pragma unroll
                for (int g = 0; g < 16; g++) sum += part[r * 16 + g];
                row_l[r] = row_l[r] * row_sc[r] + sum;
            }
        }

        // ---- phase B: rescale accumulators, accumulate P @ V ----
        float sc = row_sc[qr2];
#pragma unroll
        for (int i = 0; i < 4; i++) {
            acc[i].x *= sc; acc[i].y *= sc; acc[i].z *= sc; acc[i].w *= sc;
        }
#pragma unroll 8
        for (int k = 0; k < 64; k++) {
            float p = Ps[qr2 * FS + k];
#pragma unroll
            for (int i = 0; i < 4; i++) {
                float4 v4 = *(const float4*)(Vs + k * FS + tq * 4 + 16 * i);
                acc[i].x += p * v4.x;
                acc[i].y += p * v4.y;
                acc[i].z += p * v4.z;
                acc[i].w += p * v4.w;
            }
        }
    }
    __syncthreads();   // row_l final

    float inv = 1.f / row_l[qr2];
    float* ob = att + (size_t)(b * S_ + q0 + qr2) * DIM_ + h * HD_;
#pragma unroll
    for (int i = 0; i < 4; i++) {
        float4 o = acc[i];
        o.x *= inv; o.y *= inv; o.z *= inv; o.w *= inv;
        *(float4*)(ob + tq * 4 + 16 * i) = o;
    }
}

// ============================================================================
// launch
// ============================================================================
extern "C" void kernel_launch(void* const* d_in, const int* in_sizes, int n_in,
                              void* d_out, int out_size)
{
    const float* x    = (const float*)d_in[0];
    const float* fc   = (const float*)d_in[1];
    const float* wqkv = (const float*)d_in[2];
    const float* wo   = (const float*)d_in[3];
    float* out        = (float*)d_out;

    void* qkv_p = nullptr;
    void* att_p = nullptr;
    cudaGetSymbolAddress(&qkv_p, g_qkv);
    cudaGetSymbolAddress(&att_p, g_att);
    float* qkv = (float*)qkv_p;
    float* att = (float*)att_p;

    const int flash_smem = (4 * 64 * FS + 4 * 64 + 64 * 16) * sizeof(float);
    cudaFuncSetAttribute(flash_kernel, cudaFuncAttributeMaxDynamicSharedMemorySize,
                         flash_smem);

    // 1) qkv = x @ wqkv   (4096 x 3072 x 2048)
    sgemm_kernel<<<dim3(QKVN / BN, M_ / BM), 256>>>(x, wqkv, qkv, M_, QKVN, DIM_);

    // 2) rope in place on q and k heads
    {
        const int npair = M_ * (NH_ + NKV_) * (HD_ / 2);
        rope_kernel<<<(npair + 255) / 256, 256>>>(qkv, fc);
    }

    // 3) flash attention -> att
    flash_kernel<<<dim3(S_ / 64, NH_, B_), 256, flash_smem>>>(qkv, att);

    // 4) out = att @ wo   (4096 x 2048 x 2048)
    sgemm_kernel<<<dim3(DIM_ / BN, M_ / BM), 256>>>(att, wo, out, M_, DIM_, DIM_);
}

// round 3
// speedup vs baseline: 1.5872x; 1.5872x over previous
#include <cuda_runtime.h>
#include <cuda_bf16.h>
#include <cstdint>

// ---------------- problem constants ----------------
#define B_   2
#define S_   2048
#define DIM_ 2048
#define NH_  32
#define NKV_ 8
#define HD_  64
#define QKVN 3072            // (32 + 2*8) * 64
#define M_   (B_ * S_)       // 4096
#define KDIM 2048

// ---------------- scratch ----------------
__device__ float g_qkv[(size_t)M_ * QKVN];
__device__ float g_att[(size_t)M_ * DIM_];
__device__ __nv_bfloat16 g_x_hi[(size_t)M_ * DIM_];
__device__ __nv_bfloat16 g_x_lo[(size_t)M_ * DIM_];
__device__ __nv_bfloat16 g_wqkvT_hi[(size_t)QKVN * DIM_];
__device__ __nv_bfloat16 g_wqkvT_lo[(size_t)QKVN * DIM_];
__device__ __nv_bfloat16 g_woT_hi[(size_t)DIM_ * DIM_];
__device__ __nv_bfloat16 g_woT_lo[(size_t)DIM_ * DIM_];
__device__ __nv_bfloat16 g_att_hi[(size_t)M_ * DIM_];
__device__ __nv_bfloat16 g_att_lo[(size_t)M_ * DIM_];

// ============================================================================
// warp-MMA helpers (family-generic: sm_80+ features only)
// ============================================================================
__device__ __forceinline__ uint32_t smem_u32(const void* p) {
    uint32_t a;
    asm("{ .reg .u64 t; cvta.to.shared.u64 t, %1; cvt.u32.u64 %0, t; }"
        : "=r"(a) : "l"(p));
    return a;
}
__device__ __forceinline__ void cp_async16(uint32_t s, const void* g) {
    asm volatile("cp.async.cg.shared.global [%0], [%1], 16;" :: "r"(s), "l"(g));
}
__device__ __forceinline__ void cp_commit() {
    asm volatile("cp.async.commit_group;" ::: "memory");
}
__device__ __forceinline__ void cp_wait0() {
    asm volatile("cp.async.wait_group 0;" ::: "memory");
}
__device__ __forceinline__ void ldmatrix_x4(uint32_t& r0, uint32_t& r1,
                                            uint32_t& r2, uint32_t& r3, uint32_t a) {
    asm volatile("ldmatrix.sync.aligned.m8n8.x4.shared.b16 {%0,%1,%2,%3}, [%4];"
                 : "=r"(r0), "=r"(r1), "=r"(r2), "=r"(r3) : "r"(a));
}
__device__ __forceinline__ void mma_bf16(float* c, uint32_t a0, uint32_t a1,
                                         uint32_t a2, uint32_t a3,
                                         uint32_t b0, uint32_t b1) {
    asm volatile(
        "mma.sync.aligned.m16n8k16.row.col.f32.bf16.bf16.f32 "
        "{%0,%1,%2,%3}, {%4,%5,%6,%7}, {%8,%9}, {%0,%1,%2,%3};"
        : "+f"(c[0]), "+f"(c[1]), "+f"(c[2]), "+f"(c[3])
        : "r"(a0), "r"(a1), "r"(a2), "r"(a3), "r"(b0), "r"(b1));
}

// ============================================================================
// tc_gemm: C[M][N] = A[M][K] @ Bt[N][K]^T, 3-term bf16 split, fp32 accum.
// CTA 128x128, 8 warps (2x4), warp tile 64x32, BK=32, double-buffered cp.async.
// Smem rows padded to 80B for conflict-free ldmatrix.
// ============================================================================
#define GBM 128
#define GBN 128
#define GBK 32
#define GSTRIDE 80                         // bytes per smem row (32 bf16 + 16B pad)
#define GTILE (GBM * GSTRIDE)              // 10240 B per tile
#define GSTAGE (4 * GTILE)                 // Ah, Al, Bh, Bl
#define GSMEM_TOTAL (2 * GSTAGE)           // 81920 B

__global__ __launch_bounds__(256) void tc_gemm_kernel(
    const __nv_bfloat16* __restrict__ Ah, const __nv_bfloat16* __restrict__ Al,
    const __nv_bfloat16* __restrict__ Bh, const __nv_bfloat16* __restrict__ Bl,
    float* __restrict__ C, int N, int K)
{
    extern __shared__ char smem[];
    const uint32_t sb = smem_u32(smem);
    const int tid = threadIdx.x;
    const int wid = tid >> 5;
    const int lane = tid & 31;
    const int mb = blockIdx.y * GBM;
    const int nb = blockIdx.x * GBN;
    const int wm = (wid >> 2) * 64;        // warp m offset in tile
    const int wn = (wid & 3) * 32;         // warp n offset in tile

    // per-thread load slots: 2 chunks per tile (512 chunks / 256 threads)
    const int r0c = (tid) >> 2, s0c = tid & 3;
    const int r1c = (tid + 256) >> 2, s1c = tid & 3;

    auto load_stage = [&](int stage, int k0) {
        uint32_t base = sb + stage * GSTAGE;
        const __nv_bfloat16* gA[2] = {Ah, Al};
        const __nv_bfloat16* gB[2] = {Bh, Bl};
#pragma unroll
        for (int t = 0; t < 2; t++) {
            uint32_t sA = base + t * GTILE;
            uint32_t sB = base + (2 + t) * GTILE;
            cp_async16(sA + r0c * GSTRIDE + s0c * 16, gA[t] + (size_t)(mb + r0c) * K + k0 + s0c * 8);
            cp_async16(sA + r1c * GSTRIDE + s1c * 16, gA[t] + (size_t)(mb + r1c) * K + k0 + s1c * 8);
            cp_async16(sB + r0c * GSTRIDE + s0c * 16, gB[t] + (size_t)(nb + r0c) * K + k0 + s0c * 8);
            cp_async16(sB + r1c * GSTRIDE + s1c * 16, gB[t] + (size_t)(nb + r1c) * K + k0 + s1c * 8);
        }
        cp_commit();
    };

    float acc[4][4][4];
#pragma unroll
    for (int i = 0; i < 4; i++)
#pragma unroll
        for (int j = 0; j < 4; j++)
#pragma unroll
            for (int e = 0; e < 4; e++) acc[i][j][e] = 0.f;

    // ldmatrix lane addressing (offsets within a tile)
    const uint32_t aoff = (uint32_t)((lane & 15) * GSTRIDE + (lane >> 4) * 16);
    const uint32_t boff = (uint32_t)(((lane & 7) + ((lane >> 4) * 8)) * GSTRIDE
                                     + (((lane >> 3) & 1) * 16));

    load_stage(0, 0);
    const int niter = K / GBK;
    for (int it = 0; it < niter; it++) {
        cp_wait0();
        __syncthreads();
        if (it + 1 < niter) load_stage((it + 1) & 1, (it + 1) * GBK);

        uint32_t base = sb + (it & 1) * GSTAGE;
        uint32_t bAh = base, bAl = base + GTILE;
        uint32_t bBh = base + 2 * GTILE, bBl = base + 3 * GTILE;

#pragma unroll
        for (int ks = 0; ks < 2; ks++) {
            uint32_t kb = (uint32_t)(ks * 32);   // 16 bf16 = 32 bytes
            uint32_t ah[4][4], al[4][4];
#pragma unroll
            for (int mi = 0; mi < 4; mi++) {
                uint32_t rowb = (uint32_t)((wm + mi * 16) * GSTRIDE) + kb;
                ldmatrix_x4(ah[mi][0], ah[mi][1], ah[mi][2], ah[mi][3], bAh + rowb + aoff);
                ldmatrix_x4(al[mi][0], al[mi][1], al[mi][2], al[mi][3], bAl + rowb + aoff);
            }
            uint32_t bh[4][2], bl[4][2];
#pragma unroll
            for (int nj = 0; nj < 2; nj++) {
                uint32_t rowb = (uint32_t)((wn + nj * 16) * GSTRIDE) + kb;
                uint32_t t0, t1, t2, t3;
                ldmatrix_x4(t0, t1, t2, t3, bBh + rowb + boff);
                bh[nj * 2][0] = t0; bh[nj * 2][1] = t1;
                bh[nj * 2 + 1][0] = t2; bh[nj * 2 + 1][1] = t3;
                ldmatrix_x4(t0, t1, t2, t3, bBl + rowb + boff);
                bl[nj * 2][0] = t0; bl[nj * 2][1] = t1;
                bl[nj * 2 + 1][0] = t2; bl[nj * 2 + 1][1] = t3;
            }
#pragma unroll
            for (int mi = 0; mi < 4; mi++)
#pragma unroll
                for (int nj = 0; nj < 4; nj++) {
                    mma_bf16(acc[mi][nj], ah[mi][0], ah[mi][1], ah[mi][2], ah[mi][3],
                             bh[nj][0], bh[nj][1]);
                    mma_bf16(acc[mi][nj], ah[mi][0], ah[mi][1], ah[mi][2], ah[mi][3],
                             bl[nj][0], bl[nj][1]);
                    mma_bf16(acc[mi][nj], al[mi][0], al[mi][1], al[mi][2], al[mi][3],
                             bh[nj][0], bh[nj][1]);
                }
        }
        __syncthreads();
    }

    // epilogue
    const int g = lane >> 2, c = lane & 3;
#pragma unroll
    for (int mi = 0; mi < 4; mi++) {
#pragma unroll
        for (int nj = 0; nj < 4; nj++) {
            float* cp0 = C + (size_t)(mb + wm + mi * 16 + g) * N + nb + wn + nj * 8 + 2 * c;
            float* cp1 = cp0 + (size_t)8 * N;
            *(float2*)cp0 = make_float2(acc[mi][nj][0], acc[mi][nj][1]);
            *(float2*)cp1 = make_float2(acc[mi][nj][2], acc[mi][nj][3]);
        }
    }
}

// ============================================================================
// conversion kernels
// ============================================================================
__global__ __launch_bounds__(256) void conv_split_kernel(
    const float* __restrict__ A, __nv_bfloat16* __restrict__ H,
    __nv_bfloat16* __restrict__ L, int n4)
{
    int i = blockIdx.x * blockDim.x + threadIdx.x;
    if (i >= n4) return;
    float4 v = *(const float4*)(A + (size_t)i * 4);
    float vv[4] = {v.x, v.y, v.z, v.w};
    __nv_bfloat16 h[4], l[4];
#pragma unroll
    for (int j = 0; j < 4; j++) {
        h[j] = __float2bfloat16(vv[j]);
        l[j] = __float2bfloat16(vv[j] - __bfloat162float(h[j]));
    }
    *(uint2*)(H + (size_t)i * 4) = *(uint2*)h;
    *(uint2*)(L + (size_t)i * 4) = *(uint2*)l;
}

__global__ __launch_bounds__(256) void conv_transpose_kernel(
    const float* __restrict__ W, __nv_bfloat16* __restrict__ Th,
    __nv_bfloat16* __restrict__ Tl, int K, int N)
{
    __shared__ float t[32][33];
    const int k0 = blockIdx.y * 32, n0 = blockIdx.x * 32;
    const int tx = threadIdx.x & 31, ty = threadIdx.x >> 5;
#pragma unroll
    for (int i = 0; i < 32; i += 8)
        t[ty + i][tx] = W[(size_t)(k0 + ty + i) * N + n0 + tx];
    __syncthreads();
#pragma unroll
    for (int i = 0; i < 32; i += 8) {
        float v = t[tx][ty + i];
        __nv_bfloat16 h = __float2bfloat16(v);
        size_t o = (size_t)(n0 + ty + i) * K + k0 + tx;
        Th[o] = h;
        Tl[o] = __float2bfloat16(v - __bfloat162float(h));
    }
}

// ============================================================================
// RoPE (in place on g_qkv)
// ============================================================================
__global__ __launch_bounds__(256) void rope_kernel(float* __restrict__ qkv,
                                                   const float* __restrict__ fc)
{
    const int NPAIR = M_ * (NH_ + NKV_) * (HD_ / 2);
    int idx = blockIdx.x * blockDim.x + threadIdx.x;
    if (idx >= NPAIR) return;
    int p   = idx & 31;
    int hh  = (idx >> 5) % (NH_ + NKV_);
    int row = idx / ((NH_ + NKV_) * 32);
    int s   = row & (S_ - 1);

    float2 f = *(const float2*)(fc + (size_t)s * HD_ + p * 2);
    float* ptr = qkv + (size_t)row * QKVN + hh * HD_ + p * 2;
    float2 x = *(float2*)ptr;
    float2 o;
    o.x = x.x * f.x - x.y * f.y;
    o.y = x.y * f.x + x.x * f.y;
    *(float2*)ptr = o;
}

// ============================================================================
// Flash attention (unchanged fp32 baseline)
// ============================================================================
#define FS 68

__global__ __launch_bounds__(256) void flash_kernel(const float* __restrict__ qkv,
                                                    float* __restrict__ att)
{
    extern __shared__ float sm[];
    float* Qs       = sm;
    float* Ks       = Qs + 64 * FS;
    float* Vs       = Ks + 64 * FS;
    float* Ps       = Vs + 64 * FS;
    float* row_m    = Ps + 64 * FS;
    float* row_l    = row_m + 64;
    float* row_mnew = row_l + 64;
    float* row_sc   = row_mnew + 64;
    float* part     = row_sc + 64;

    const int tid   = threadIdx.x;
    const int qtile = blockIdx.x;
    const int h     = blockIdx.y;
    const int b     = blockIdx.z;
    const int kvh   = h >> 2;
    const int q0    = qtile * 64;

    const float* qbase = qkv + (size_t)(b * S_ + q0) * QKVN + h * HD_;
    const float* kbase = qkv + (size_t)(b * S_) * QKVN + DIM_ + kvh * HD_;
    const float* vbase = kbase + NKV_ * HD_;

#pragma unroll
    for (int i = 0; i < 4; i++) {
        int idx = tid + 256 * i;
        int r   = idx >> 4;
        int c4  = (idx & 15) << 2;
        float4 v = *(const float4*)(qbase + (size_t)r * QKVN + c4);
        *(float4*)(Qs + r * FS + c4) = v;
    }
    if (tid < 64) { row_m[tid] = -1e30f; row_l[tid] = 0.f; }

    const int qa = (tid >> 4) << 2;
    const int kb = tid & 15;
    const int qr2 = tid >> 2;
    const int tq  = tid & 3;

    float4 acc[4];
#pragma unroll
    for (int i = 0; i < 4; i++) acc[i] = make_float4(0.f, 0.f, 0.f, 0.f);

    for (int j = 0; j <= qtile; j++) {
        __syncthreads();

        const float* kt = kbase + (size_t)(j * 64) * QKVN;
        const float* vt = vbase + (size_t)(j * 64) * QKVN;
#pragma unroll
        for (int i = 0; i < 4; i++) {
            int idx = tid + 256 * i;
            int r   = idx >> 4;
            int c4  = (idx & 15) << 2;
            *(float4*)(Ks + r * FS + c4) = *(const float4*)(kt + (size_t)r * QKVN + c4);
            *(float4*)(Vs + r * FS + c4) = *(const float4*)(vt + (size_t)r * QKVN + c4);
        }
        __syncthreads();

        float s[4][4];
#pragma unroll
        for (int a = 0; a < 4; a++)
#pragma unroll
            for (int c = 0; c < 4; c++) s[a][c] = 0.f;

#pragma unroll 4
        for (int d4 = 0; d4 < 16; d4++) {
            float4 q4[4], k4[4];
#pragma unroll
            for (int a = 0; a < 4; a++)
                q4[a] = *(const float4*)(Qs + (qa + a) * FS + d4 * 4);
#pragma unroll
            for (int c = 0; c < 4; c++)
                k4[c] = *(const float4*)(Ks + (kb + 16 * c) * FS + d4 * 4);
#pragma unroll
            for (int a = 0; a < 4; a++)
#pragma unroll
                for (int c = 0; c < 4; c++)
                    s[a][c] += q4[a].x * k4[c].x + q4[a].y * k4[c].y +
                               q4[a].z * k4[c].z + q4[a].w * k4[c].w;
        }

#pragma unroll
        for (int a = 0; a < 4; a++) {
            float pm = -1e30f;
            int qi = q0 + qa + a;
#pragma unroll
            for (int c = 0; c < 4; c++) {
                int kj = j * 64 + kb + 16 * c;
                float sv = (kj <= qi) ? s[a][c] * 0.125f : -1e30f;
                s[a][c] = sv;
                pm = fmaxf(pm, sv);
            }
            part[(qa + a) * 16 + kb] = pm;
        }
        __syncthreads();

        if (kb == 0) {
#pragma unroll
            for (int a = 0; a < 4; a++) {
                int r = qa + a;
                float rm = part[r * 16];
#pragma unroll
                for (int g = 1; g < 16; g++) rm = fmaxf(rm, part[r * 16 + g]);
                float mo = row_m[r];
                float mn = fmaxf(mo, rm);
                row_mnew[r] = mn;
                row_sc[r]   = __expf(mo - mn);
                row_m[r]    = mn;
            }
        }
        __syncthreads();

#pragma unroll
        for (int a = 0; a < 4; a++) {
            int r = qa + a;
            float mn = row_mnew[r];
            float ps = 0.f;
#pragma unroll
            for (int c = 0; c < 4; c++) {
                float p = __expf(s[a][c] - mn);
                ps += p;
                Ps[r * FS + kb + 16 * c] = p;
            }
            part[r * 16 + kb] = ps;
        }
        __syncthreads();

        if (kb == 0) {
#pragma unroll
            for (int a = 0; a < 4; a++) {
                int r = qa + a;
                float sum = 0.f;
#pragma unroll
                for (int g = 0; g < 16; g++) sum += part[r * 16 + g];
                row_l[r] = row_l[r] * row_sc[r] + sum;
            }
        }

        float sc = row_sc[qr2];
#pragma unroll
        for (int i = 0; i < 4; i++) {
            acc[i].x *= sc; acc[i].y *= sc; acc[i].z *= sc; acc[i].w *= sc;
        }
#pragma unroll 8
        for (int k = 0; k < 64; k++) {
            float p = Ps[qr2 * FS + k];
#pragma unroll
            for (int i = 0; i < 4; i++) {
                float4 v4 = *(const float4*)(Vs + k * FS + tq * 4 + 16 * i);
                acc[i].x += p * v4.x;
                acc[i].y += p * v4.y;
                acc[i].z += p * v4.z;
                acc[i].w += p * v4.w;
            }
        }
    }
    __syncthreads();

    float inv = 1.f / row_l[qr2];
    float* ob = att + (size_t)(b * S_ + q0 + qr2) * DIM_ + h * HD_;
#pragma unroll
    for (int i = 0; i < 4; i++) {
        float4 o = acc[i];
        o.x *= inv; o.y *= inv; o.z *= inv; o.w *= inv;
        *(float4*)(ob + tq * 4 + 16 * i) = o;
    }
}

// ============================================================================
// launch
// ============================================================================
extern "C" void kernel_launch(void* const* d_in, const int* in_sizes, int n_in,
                              void* d_out, int out_size)
{
    const float* x    = (const float*)d_in[0];
    const float* fc   = (const float*)d_in[1];
    const float* wqkv = (const float*)d_in[2];
    const float* wo   = (const float*)d_in[3];
    float* out        = (float*)d_out;

    void *qkv_p, *att_p, *xh_p, *xl_p, *wqh_p, *wql_p, *woh_p, *wol_p, *ah_p, *al_p;
    cudaGetSymbolAddress(&qkv_p, g_qkv);
    cudaGetSymbolAddress(&att_p, g_att);
    cudaGetSymbolAddress(&xh_p, g_x_hi);
    cudaGetSymbolAddress(&xl_p, g_x_lo);
    cudaGetSymbolAddress(&wqh_p, g_wqkvT_hi);
    cudaGetSymbolAddress(&wql_p, g_wqkvT_lo);
    cudaGetSymbolAddress(&woh_p, g_woT_hi);
    cudaGetSymbolAddress(&wol_p, g_woT_lo);
    cudaGetSymbolAddress(&ah_p, g_att_hi);
    cudaGetSymbolAddress(&al_p, g_att_lo);
    float* qkv = (float*)qkv_p;
    float* att = (float*)att_p;

    const int flash_smem = (4 * 64 * FS + 4 * 64 + 64 * 16) * sizeof(float);
    cudaFuncSetAttribute(flash_kernel, cudaFuncAttributeMaxDynamicSharedMemorySize,
                         flash_smem);
    cudaFuncSetAttribute(tc_gemm_kernel, cudaFuncAttributeMaxDynamicSharedMemorySize,
                         GSMEM_TOTAL);

    // 1) split x
    {
        int n4 = M_ * DIM_ / 4;
        conv_split_kernel<<<(n4 + 255) / 256, 256>>>(
            x, (__nv_bfloat16*)xh_p, (__nv_bfloat16*)xl_p, n4);
    }
    // 2) transpose + split weights
    conv_transpose_kernel<<<dim3(QKVN / 32, KDIM / 32), 256>>>(
        wqkv, (__nv_bfloat16*)wqh_p, (__nv_bfloat16*)wql_p, KDIM, QKVN);
    conv_transpose_kernel<<<dim3(DIM_ / 32, KDIM / 32), 256>>>(
        wo, (__nv_bfloat16*)woh_p, (__nv_bfloat16*)wol_p, KDIM, DIM_);

    // 3) qkv = x @ wqkv
    tc_gemm_kernel<<<dim3(QKVN / GBN, M_ / GBM), 256, GSMEM_TOTAL>>>(
        (const __nv_bfloat16*)xh_p, (const __nv_bfloat16*)xl_p,
        (const __nv_bfloat16*)wqh_p, (const __nv_bfloat16*)wql_p,
        qkv, QKVN, KDIM);

    // 4) rope
    {
        const int npair = M_ * (NH_ + NKV_) * (HD_ / 2);
        rope_kernel<<<(npair + 255) / 256, 256>>>(qkv, fc);
    }

    // 5) flash attention
    flash_kernel<<<dim3(S_ / 64, NH_, B_), 256, flash_smem>>>(qkv, att);

    // 6) split att
    {
        int n4 = M_ * DIM_ / 4;
        conv_split_kernel<<<(n4 + 255) / 256, 256>>>(
            att, (__nv_bfloat16*)ah_p, (__nv_bfloat16*)al_p, n4);
    }

    // 7) out = att @ wo
    tc_gemm_kernel<<<dim3(DIM_ / GBN, M_ / GBM), 256, GSMEM_TOTAL>>>(
        (const __nv_bfloat16*)ah_p, (const __nv_bfloat16*)al_p,
        (const __nv_bfloat16*)woh_p, (const __nv_bfloat16*)wol_p,
        out, DIM_, KDIM);
}

// round 4
// speedup vs baseline: 3.4294x; 2.1607x over previous
#include <cuda_runtime.h>
#include <cuda_bf16.h>
#include <cstdint>

// ---------------- problem constants ----------------
#define B_   2
#define S_   2048
#define DIM_ 2048
#define NH_  32
#define NKV_ 8
#define HD_  64
#define QKVN 3072
#define M_   (B_ * S_)
#define KDIM 2048

// ---------------- scratch ----------------
__device__ float g_qkv[(size_t)M_ * QKVN];
__device__ __nv_bfloat16 g_x_hi[(size_t)M_ * DIM_];
__device__ __nv_bfloat16 g_x_lo[(size_t)M_ * DIM_];
__device__ __nv_bfloat16 g_wqkvT_hi[(size_t)QKVN * DIM_];
__device__ __nv_bfloat16 g_wqkvT_lo[(size_t)QKVN * DIM_];
__device__ __nv_bfloat16 g_woT_hi[(size_t)DIM_ * DIM_];
__device__ __nv_bfloat16 g_woT_lo[(size_t)DIM_ * DIM_];
__device__ __nv_bfloat16 g_att_hi[(size_t)M_ * DIM_];
__device__ __nv_bfloat16 g_att_lo[(size_t)M_ * DIM_];
// rope-applied, head-separated bf16 splits
__device__ __nv_bfloat16 g_q_hi[(size_t)B_ * NH_ * S_ * HD_];
__device__ __nv_bfloat16 g_q_lo[(size_t)B_ * NH_ * S_ * HD_];
__device__ __nv_bfloat16 g_k_hi[(size_t)B_ * NKV_ * S_ * HD_];
__device__ __nv_bfloat16 g_k_lo[(size_t)B_ * NKV_ * S_ * HD_];
__device__ __nv_bfloat16 g_v_hi[(size_t)B_ * NKV_ * S_ * HD_];
__device__ __nv_bfloat16 g_v_lo[(size_t)B_ * NKV_ * S_ * HD_];

// ============================================================================
// helpers (sm_80-compatible only)
// ============================================================================
__device__ __forceinline__ uint32_t smem_u32(const void* p) {
    uint32_t a;
    asm("{ .reg .u64 t; cvta.to.shared.u64 t, %1; cvt.u32.u64 %0, t; }"
        : "=r"(a) : "l"(p));
    return a;
}
__device__ __forceinline__ void cp_async16(uint32_t s, const void* g) {
    asm volatile("cp.async.cg.shared.global [%0], [%1], 16;" :: "r"(s), "l"(g));
}
__device__ __forceinline__ void cp_commit() {
    asm volatile("cp.async.commit_group;" ::: "memory");
}
__device__ __forceinline__ void cp_wait0() {
    asm volatile("cp.async.wait_group 0;" ::: "memory");
}
__device__ __forceinline__ void ldmatrix_x4(uint32_t& r0, uint32_t& r1,
                                            uint32_t& r2, uint32_t& r3, uint32_t a) {
    asm volatile("ldmatrix.sync.aligned.m8n8.x4.shared.b16 {%0,%1,%2,%3}, [%4];"
                 : "=r"(r0), "=r"(r1), "=r"(r2), "=r"(r3) : "r"(a));
}
__device__ __forceinline__ void ldmatrix_x4_trans(uint32_t& r0, uint32_t& r1,
                                                  uint32_t& r2, uint32_t& r3, uint32_t a) {
    asm volatile("ldmatrix.sync.aligned.m8n8.x4.trans.shared.b16 {%0,%1,%2,%3}, [%4];"
                 : "=r"(r0), "=r"(r1), "=r"(r2), "=r"(r3) : "r"(a));
}
__device__ __forceinline__ void mma_bf16(float* c, uint32_t a0, uint32_t a1,
                                         uint32_t a2, uint32_t a3,
                                         uint32_t b0, uint32_t b1) {
    asm volatile(
        "mma.sync.aligned.m16n8k16.row.col.f32.bf16.bf16.f32 "
        "{%0,%1,%2,%3}, {%4,%5,%6,%7}, {%8,%9}, {%0,%1,%2,%3};"
        : "+f"(c[0]), "+f"(c[1]), "+f"(c[2]), "+f"(c[3])
        : "r"(a0), "r"(a1), "r"(a2), "r"(a3), "r"(b0), "r"(b1));
}
__device__ __forceinline__ uint32_t pack_hi2(float a, float b) {
    __nv_bfloat162 t = __floats2bfloat162_rn(a, b);
    return *(uint32_t*)&t;
}
__device__ __forceinline__ uint32_t pack_lo2(float a, float b) {
    float ah = __bfloat162float(__float2bfloat16(a));
    float bh = __bfloat162float(__float2bfloat16(b));
    __nv_bfloat162 t = __floats2bfloat162_rn(a - ah, b - bh);
    return *(uint32_t*)&t;
}

// ============================================================================
// tc_gemm (unchanged from R3): C[M][N] = A @ Bt^T, 3-term bf16 split.
// ============================================================================
#define GBM 128
#define GBN 128
#define GBK 32
#define GSTRIDE 80
#define GTILE (GBM * GSTRIDE)
#define GSTAGE (4 * GTILE)
#define GSMEM_TOTAL (2 * GSTAGE)

__global__ __launch_bounds__(256) void tc_gemm_kernel(
    const __nv_bfloat16* __restrict__ Ah, const __nv_bfloat16* __restrict__ Al,
    const __nv_bfloat16* __restrict__ Bh, const __nv_bfloat16* __restrict__ Bl,
    float* __restrict__ C, int N, int K)
{
    extern __shared__ char smem[];
    const uint32_t sb = smem_u32(smem);
    const int tid = threadIdx.x;
    const int wid = tid >> 5;
    const int lane = tid & 31;
    const int mb = blockIdx.y * GBM;
    const int nb = blockIdx.x * GBN;
    const int wm = (wid >> 2) * 64;
    const int wn = (wid & 3) * 32;

    const int r0c = (tid) >> 2, s0c = tid & 3;
    const int r1c = (tid + 256) >> 2, s1c = tid & 3;

    auto load_stage = [&](int stage, int k0) {
        uint32_t base = sb + stage * GSTAGE;
        const __nv_bfloat16* gA[2] = {Ah, Al};
        const __nv_bfloat16* gB[2] = {Bh, Bl};
#pragma unroll
        for (int t = 0; t < 2; t++) {
            uint32_t sA = base + t * GTILE;
            uint32_t sB = base + (2 + t) * GTILE;
            cp_async16(sA + r0c * GSTRIDE + s0c * 16, gA[t] + (size_t)(mb + r0c) * K + k0 + s0c * 8);
            cp_async16(sA + r1c * GSTRIDE + s1c * 16, gA[t] + (size_t)(mb + r1c) * K + k0 + s1c * 8);
            cp_async16(sB + r0c * GSTRIDE + s0c * 16, gB[t] + (size_t)(nb + r0c) * K + k0 + s0c * 8);
            cp_async16(sB + r1c * GSTRIDE + s1c * 16, gB[t] + (size_t)(nb + r1c) * K + k0 + s1c * 8);
        }
        cp_commit();
    };

    float acc[4][4][4];
#pragma unroll
    for (int i = 0; i < 4; i++)
#pragma unroll
        for (int j = 0; j < 4; j++)
#pragma unroll
            for (int e = 0; e < 4; e++) acc[i][j][e] = 0.f;

    const uint32_t aoff = (uint32_t)((lane & 15) * GSTRIDE + (lane >> 4) * 16);
    const uint32_t boff = (uint32_t)(((lane & 7) + ((lane >> 4) * 8)) * GSTRIDE
                                     + (((lane >> 3) & 1) * 16));

    load_stage(0, 0);
    const int niter = K / GBK;
    for (int it = 0; it < niter; it++) {
        cp_wait0();
        __syncthreads();
        if (it + 1 < niter) load_stage((it + 1) & 1, (it + 1) * GBK);

        uint32_t base = sb + (it & 1) * GSTAGE;
        uint32_t bAh = base, bAl = base + GTILE;
        uint32_t bBh = base + 2 * GTILE, bBl = base + 3 * GTILE;

#pragma unroll
        for (int ks = 0; ks < 2; ks++) {
            uint32_t kb = (uint32_t)(ks * 32);
            uint32_t ah[4][4], al[4][4];
#pragma unroll
            for (int mi = 0; mi < 4; mi++) {
                uint32_t rowb = (uint32_t)((wm + mi * 16) * GSTRIDE) + kb;
                ldmatrix_x4(ah[mi][0], ah[mi][1], ah[mi][2], ah[mi][3], bAh + rowb + aoff);
                ldmatrix_x4(al[mi][0], al[mi][1], al[mi][2], al[mi][3], bAl + rowb + aoff);
            }
            uint32_t bh[4][2], bl[4][2];
#pragma unroll
            for (int nj = 0; nj < 2; nj++) {
                uint32_t rowb = (uint32_t)((wn + nj * 16) * GSTRIDE) + kb;
                uint32_t t0, t1, t2, t3;
                ldmatrix_x4(t0, t1, t2, t3, bBh + rowb + boff);
                bh[nj * 2][0] = t0; bh[nj * 2][1] = t1;
                bh[nj * 2 + 1][0] = t2; bh[nj * 2 + 1][1] = t3;
                ldmatrix_x4(t0, t1, t2, t3, bBl + rowb + boff);
                bl[nj * 2][0] = t0; bl[nj * 2][1] = t1;
                bl[nj * 2 + 1][0] = t2; bl[nj * 2 + 1][1] = t3;
            }
#pragma unroll
            for (int mi = 0; mi < 4; mi++)
#pragma unroll
                for (int nj = 0; nj < 4; nj++) {
                    mma_bf16(acc[mi][nj], ah[mi][0], ah[mi][1], ah[mi][2], ah[mi][3],
                             bh[nj][0], bh[nj][1]);
                    mma_bf16(acc[mi][nj], ah[mi][0], ah[mi][1], ah[mi][2], ah[mi][3],
                             bl[nj][0], bl[nj][1]);
                    mma_bf16(acc[mi][nj], al[mi][0], al[mi][1], al[mi][2], al[mi][3],
                             bh[nj][0], bh[nj][1]);
                }
        }
        __syncthreads();
    }

    const int g = lane >> 2, c = lane & 3;
#pragma unroll
    for (int mi = 0; mi < 4; mi++) {
#pragma unroll
        for (int nj = 0; nj < 4; nj++) {
            float* cp0 = C + (size_t)(mb + wm + mi * 16 + g) * N + nb + wn + nj * 8 + 2 * c;
            float* cp1 = cp0 + (size_t)8 * N;
            *(float2*)cp0 = make_float2(acc[mi][nj][0], acc[mi][nj][1]);
            *(float2*)cp1 = make_float2(acc[mi][nj][2], acc[mi][nj][3]);
        }
    }
}

// ============================================================================
// conversion kernels
// ============================================================================
__global__ __launch_bounds__(256) void conv_split_kernel(
    const float* __restrict__ A, __nv_bfloat16* __restrict__ H,
    __nv_bfloat16* __restrict__ L, int n4)
{
    int i = blockIdx.x * blockDim.x + threadIdx.x;
    if (i >= n4) return;
    float4 v = *(const float4*)(A + (size_t)i * 4);
    float vv[4] = {v.x, v.y, v.z, v.w};
    __nv_bfloat16 h[4], l[4];
#pragma unroll
    for (int j = 0; j < 4; j++) {
        h[j] = __float2bfloat16(vv[j]);
        l[j] = __float2bfloat16(vv[j] - __bfloat162float(h[j]));
    }
    *(uint2*)(H + (size_t)i * 4) = *(uint2*)h;
    *(uint2*)(L + (size_t)i * 4) = *(uint2*)l;
}

__global__ __launch_bounds__(256) void conv_transpose_kernel(
    const float* __restrict__ W, __nv_bfloat16* __restrict__ Th,
    __nv_bfloat16* __restrict__ Tl, int K, int N)
{
    __shared__ float t[32][33];
    const int k0 = blockIdx.y * 32, n0 = blockIdx.x * 32;
    const int tx = threadIdx.x & 31, ty = threadIdx.x >> 5;
#pragma unroll
    for (int i = 0; i < 32; i += 8)
        t[ty + i][tx] = W[(size_t)(k0 + ty + i) * N + n0 + tx];
    __syncthreads();
#pragma unroll
    for (int i = 0; i < 32; i += 8) {
        float v = t[tx][ty + i];
        __nv_bfloat16 h = __float2bfloat16(v);
        size_t o = (size_t)(n0 + ty + i) * K + k0 + tx;
        Th[o] = h;
        Tl[o] = __float2bfloat16(v - __bfloat162float(h));
    }
}

// ============================================================================
// fused rope + split + head-separate: g_qkv (fp32) -> Q/K/V hi/lo bf16
// one thread per 2 elements
// ============================================================================
__global__ __launch_bounds__(256) void rope_split_kernel(
    const float* __restrict__ qkv, const float* __restrict__ fc,
    __nv_bfloat16* __restrict__ Qh, __nv_bfloat16* __restrict__ Ql,
    __nv_bfloat16* __restrict__ Kh, __nv_bfloat16* __restrict__ Kl,
    __nv_bfloat16* __restrict__ Vh, __nv_bfloat16* __restrict__ Vl)
{
    const int NTOT = M_ * (QKVN / 2);
    int idx = blockIdx.x * blockDim.x + threadIdx.x;
    if (idx >= NTOT) return;
    int c2  = idx % (QKVN / 2);
    int row = idx / (QKVN / 2);
    int col = c2 * 2;
    int b = row / S_, s = row % S_;

    float2 x = *(const float2*)(qkv + (size_t)row * QKVN + col);

    __nv_bfloat16* dh;
    __nv_bfloat16* dl;
    size_t o;
    bool do_rope;
    int d;
    if (col < DIM_) {
        int h = col >> 6; d = col & 63;
        o = ((size_t)(b * NH_ + h) * S_ + s) * HD_ + d;
        dh = Qh; dl = Ql; do_rope = true;
    } else if (col < DIM_ + NKV_ * HD_) {
        int kvh = (col - DIM_) >> 6; d = col & 63;
        o = ((size_t)(b * NKV_ + kvh) * S_ + s) * HD_ + d;
        dh = Kh; dl = Kl; do_rope = true;
    } else {
        int kvh = (col - DIM_ - NKV_ * HD_) >> 6; d = col & 63;
        o = ((size_t)(b * NKV_ + kvh) * S_ + s) * HD_ + d;
        dh = Vh; dl = Vl; do_rope = false;
    }

    if (do_rope) {
        float2 f = *(const float2*)(fc + (size_t)s * HD_ + d);  // d even; pair = d/2
        float rx = x.x * f.x - x.y * f.y;
        float ry = x.y * f.x + x.x * f.y;
        x.x = rx; x.y = ry;
    }
    __nv_bfloat16 hx = __float2bfloat16(x.x);
    __nv_bfloat16 hy = __float2bfloat16(x.y);
    __nv_bfloat16 hv[2] = {hx, hy};
    __nv_bfloat16 lv[2] = {__float2bfloat16(x.x - __bfloat162float(hx)),
                           __float2bfloat16(x.y - __bfloat162float(hy))};
    *(uint32_t*)(dh + o) = *(uint32_t*)hv;
    *(uint32_t*)(dl + o) = *(uint32_t*)lv;
}

// ============================================================================
// Tensor-core flash attention, causal, GQA. 3-term split for QK^T and PV.
// CTA: 64 q-rows, 1 head. 4 warps (16 rows each). kv tiles of 64, double buffer.
// Output: bf16 hi/lo directly (feeds wo GEMM).
// ============================================================================
#define FSTR 144
#define FTILE (64 * FSTR)        // 9216 B
#define FSTAGE (4 * FTILE)       // Kh, Kl, Vh, Vl
#define FSMEM (2 * FSTAGE)       // 73728 B

__global__ __launch_bounds__(128) void flash_tc_kernel(
    const __nv_bfloat16* __restrict__ Qh, const __nv_bfloat16* __restrict__ Ql,
    const __nv_bfloat16* __restrict__ Kh, const __nv_bfloat16* __restrict__ Kl,
    const __nv_bfloat16* __restrict__ Vh, const __nv_bfloat16* __restrict__ Vl,
    __nv_bfloat16* __restrict__ Oh, __nv_bfloat16* __restrict__ Ol)
{
    extern __shared__ char smem[];
    const uint32_t sb = smem_u32(smem);
    const int tid  = threadIdx.x;
    const int wid  = tid >> 5;
    const int lane = tid & 31;
    const int qtile = blockIdx.x;
    const int h     = blockIdx.y;
    const int b     = blockIdx.z;
    const int kvh   = h >> 2;
    const int q0    = qtile * 64;
    const int wm    = wid * 16;

    const __nv_bfloat16* qhp = Qh + ((size_t)(b * NH_ + h) * S_ + q0) * HD_;
    const __nv_bfloat16* qlp = Ql + ((size_t)(b * NH_ + h) * S_ + q0) * HD_;
    const __nv_bfloat16* khp = Kh + ((size_t)(b * NKV_ + kvh) * S_) * HD_;
    const __nv_bfloat16* klp = Kl + ((size_t)(b * NKV_ + kvh) * S_) * HD_;
    const __nv_bfloat16* vhp = Vh + ((size_t)(b * NKV_ + kvh) * S_) * HD_;
    const __nv_bfloat16* vlp = Vl + ((size_t)(b * NKV_ + kvh) * S_) * HD_;

    // per-thread load slots: 4 x 16B per 64x64 tile
    const int lr[4] = {(tid) >> 3, (tid + 128) >> 3, (tid + 256) >> 3, (tid + 384) >> 3};
    const int ls = tid & 7;

    // --- stage Q into buffer 0, build register fragments ---
#pragma unroll
    for (int i = 0; i < 4; i++) {
        cp_async16(sb + lr[i] * FSTR + ls * 16, qhp + (size_t)lr[i] * HD_ + ls * 8);
        cp_async16(sb + FTILE + lr[i] * FSTR + ls * 16, qlp + (size_t)lr[i] * HD_ + ls * 8);
    }
    cp_commit();
    cp_wait0();
    __syncthreads();

    const uint32_t aoff = (uint32_t)((lane & 15) * FSTR + (lane >> 4) * 16);
    const uint32_t boff = (uint32_t)(((lane & 7) + ((lane >> 4) * 8)) * FSTR
                                     + (((lane >> 3) & 1) * 16));
    const uint32_t voff = (uint32_t)(((lane & 7) + (((lane >> 3) & 1) * 8)) * FSTR
                                     + ((lane >> 4) * 16));

    uint32_t qfh[4][4], qfl[4][4];
#pragma unroll
    for (int ks = 0; ks < 4; ks++) {
        uint32_t rowb = (uint32_t)(wm * FSTR + ks * 32);
        ldmatrix_x4(qfh[ks][0], qfh[ks][1], qfh[ks][2], qfh[ks][3], sb + rowb + aoff);
        ldmatrix_x4(qfl[ks][0], qfl[ks][1], qfl[ks][2], qfl[ks][3], sb + FTILE + rowb + aoff);
    }
    __syncthreads();

    // --- prefetch kv tile 0 ---
    auto load_kv = [&](int st, int j) {
        uint32_t base = sb + st * FSTAGE;
        size_t g0 = (size_t)(j * 64) * HD_;
#pragma unroll
        for (int i = 0; i < 4; i++) {
            uint32_t so = lr[i] * FSTR + ls * 16;
            size_t go = g0 + (size_t)lr[i] * HD_ + ls * 8;
            cp_async16(base + so, khp + go);
            cp_async16(base + FTILE + so, klp + go);
            cp_async16(base + 2 * FTILE + so, vhp + go);
            cp_async16(base + 3 * FTILE + so, vlp + go);
        }
        cp_commit();
    };
    load_kv(0, 0);

    float m0 = -1e30f, m1 = -1e30f, l0 = 0.f, l1 = 0.f;
    float o[8][4];
#pragma unroll
    for (int nj = 0; nj < 8; nj++)
#pragma unroll
        for (int e = 0; e < 4; e++) o[nj][e] = 0.f;

    const int r0 = lane >> 2;
    const int tig = lane & 3;
    const int qg0 = q0 + wm + r0;
    const int qg1 = qg0 + 8;

    for (int j = 0; j <= qtile; j++) {
        cp_wait0();
        __syncthreads();
        if (j < qtile) load_kv((j + 1) & 1, j + 1);

        uint32_t base = sb + (j & 1) * FSTAGE;
        uint32_t bKh = base, bKl = base + FTILE;
        uint32_t bVh = base + 2 * FTILE, bVl = base + 3 * FTILE;

        // ---- scores ----
        float c[8][4];
#pragma unroll
        for (int nj = 0; nj < 8; nj++)
#pragma unroll
            for (int e = 0; e < 4; e++) c[nj][e] = 0.f;

#pragma unroll
        for (int ks = 0; ks < 4; ks++) {
#pragma unroll
            for (int njp = 0; njp < 4; njp++) {
                uint32_t off = (uint32_t)(njp * 16 * FSTR + ks * 32) + boff;
                uint32_t h0, h1, h2, h3, l0r, l1r, l2r, l3r;
                ldmatrix_x4(h0, h1, h2, h3, bKh + off);
                ldmatrix_x4(l0r, l1r, l2r, l3r, bKl + off);
                mma_bf16(c[2 * njp], qfh[ks][0], qfh[ks][1], qfh[ks][2], qfh[ks][3], h0, h1);
                mma_bf16(c[2 * njp], qfh[ks][0], qfh[ks][1], qfh[ks][2], qfh[ks][3], l0r, l1r);
                mma_bf16(c[2 * njp], qfl[ks][0], qfl[ks][1], qfl[ks][2], qfl[ks][3], h0, h1);
                mma_bf16(c[2 * njp + 1], qfh[ks][0], qfh[ks][1], qfh[ks][2], qfh[ks][3], h2, h3);
                mma_bf16(c[2 * njp + 1], qfh[ks][0], qfh[ks][1], qfh[ks][2], qfh[ks][3], l2r, l3r);
                mma_bf16(c[2 * njp + 1], qfl[ks][0], qfl[ks][1], qfl[ks][2], qfl[ks][3], h2, h3);
            }
        }

        // ---- scale + mask + online softmax (registers) ----
        const bool diag = (j == qtile);
        float tm0 = -1e30f, tm1 = -1e30f;
#pragma unroll
        for (int nj = 0; nj < 8; nj++) {
            int colb = j * 64 + nj * 8 + 2 * tig;
#pragma unroll
            for (int e = 0; e < 4; e++) {
                float sv = c[nj][e] * 0.125f;
                if (diag) {
                    int colg = colb + (e & 1);
                    int rowg = (e < 2) ? qg0 : qg1;
                    if (colg > rowg) sv = -1e30f;
                }
                c[nj][e] = sv;
            }
            tm0 = fmaxf(tm0, fmaxf(c[nj][0], c[nj][1]));
            tm1 = fmaxf(tm1, fmaxf(c[nj][2], c[nj][3]));
        }
        tm0 = fmaxf(tm0, __shfl_xor_sync(0xffffffffu, tm0, 1));
        tm0 = fmaxf(tm0, __shfl_xor_sync(0xffffffffu, tm0, 2));
        tm1 = fmaxf(tm1, __shfl_xor_sync(0xffffffffu, tm1, 1));
        tm1 = fmaxf(tm1, __shfl_xor_sync(0xffffffffu, tm1, 2));

        float mn0 = fmaxf(m0, tm0), mn1 = fmaxf(m1, tm1);
        float sc0 = __expf(m0 - mn0), sc1 = __expf(m1 - mn1);
        m0 = mn0; m1 = mn1;

        float sum0 = 0.f, sum1 = 0.f;
#pragma unroll
        for (int nj = 0; nj < 8; nj++) {
            c[nj][0] = __expf(c[nj][0] - mn0);
            c[nj][1] = __expf(c[nj][1] - mn0);
            c[nj][2] = __expf(c[nj][2] - mn1);
            c[nj][3] = __expf(c[nj][3] - mn1);
            sum0 += c[nj][0] + c[nj][1];
            sum1 += c[nj][2] + c[nj][3];
        }
        sum0 += __shfl_xor_sync(0xffffffffu, sum0, 1);
        sum0 += __shfl_xor_sync(0xffffffffu, sum0, 2);
        sum1 += __shfl_xor_sync(0xffffffffu, sum1, 1);
        sum1 += __shfl_xor_sync(0xffffffffu, sum1, 2);
        l0 = l0 * sc0 + sum0;
        l1 = l1 * sc1 + sum1;

#pragma unroll
        for (int nj = 0; nj < 8; nj++) {
            o[nj][0] *= sc0; o[nj][1] *= sc0;
            o[nj][2] *= sc1; o[nj][3] *= sc1;
        }

        // ---- PV ----
#pragma unroll
        for (int ksv = 0; ksv < 4; ksv++) {
            uint32_t aph[4], apl[4];
            aph[0] = pack_hi2(c[2 * ksv][0], c[2 * ksv][1]);
            aph[1] = pack_hi2(c[2 * ksv][2], c[2 * ksv][3]);
            aph[2] = pack_hi2(c[2 * ksv + 1][0], c[2 * ksv + 1][1]);
            aph[3] = pack_hi2(c[2 * ksv + 1][2], c[2 * ksv + 1][3]);
            apl[0] = pack_lo2(c[2 * ksv][0], c[2 * ksv][1]);
            apl[1] = pack_lo2(c[2 * ksv][2], c[2 * ksv][3]);
            apl[2] = pack_lo2(c[2 * ksv + 1][0], c[2 * ksv + 1][1]);
            apl[3] = pack_lo2(c[2 * ksv + 1][2], c[2 * ksv + 1][3]);
#pragma unroll
            for (int njp = 0; njp < 4; njp++) {
                uint32_t off = (uint32_t)(ksv * 16 * FSTR + njp * 32) + voff;
                uint32_t h0, h1, h2, h3, l0r, l1r, l2r, l3r;
                ldmatrix_x4_trans(h0, h1, h2, h3, bVh + off);
                ldmatrix_x4_trans(l0r, l1r, l2r, l3r, bVl + off);
                mma_bf16(o[2 * njp], aph[0], aph[1], aph[2], aph[3], h0, h1);
                mma_bf16(o[2 * njp], aph[0], aph[1], aph[2], aph[3], l0r, l1r);
                mma_bf16(o[2 * njp], apl[0], apl[1], apl[2], apl[3], h0, h1);
                mma_bf16(o[2 * njp + 1], aph[0], aph[1], aph[2], aph[3], h2, h3);
                mma_bf16(o[2 * njp + 1], aph[0], aph[1], aph[2], aph[3], l2r, l3r);
                mma_bf16(o[2 * njp + 1], apl[0], apl[1], apl[2], apl[3], h2, h3);
            }
        }
    }

    // ---- epilogue: normalize, split, store bf16 hi/lo ----
    float inv0 = 1.f / l0, inv1 = 1.f / l1;
    size_t gr0 = (size_t)(b * S_ + q0 + wm + r0) * DIM_ + h * HD_ + 2 * tig;
    size_t gr1 = gr0 + (size_t)8 * DIM_;
#pragma unroll
    for (int nj = 0; nj < 8; nj++) {
        float v0 = o[nj][0] * inv0, v1 = o[nj][1] * inv0;
        float v2 = o[nj][2] * inv1, v3 = o[nj][3] * inv1;
        *(uint32_t*)(Oh + gr0 + nj * 8) = pack_hi2(v0, v1);
        *(uint32_t*)(Ol + gr0 + nj * 8) = pack_lo2(v0, v1);
        *(uint32_t*)(Oh + gr1 + nj * 8) = pack_hi2(v2, v3);
        *(uint32_t*)(Ol + gr1 + nj * 8) = pack_lo2(v2, v3);
    }
}

// ============================================================================
// launch
// ============================================================================
extern "C" void kernel_launch(void* const* d_in, const int* in_sizes, int n_in,
                              void* d_out, int out_size)
{
    const float* x    = (const float*)d_in[0];
    const float* fc   = (const float*)d_in[1];
    const float* wqkv = (const float*)d_in[2];
    const float* wo   = (const float*)d_in[3];
    float* out        = (float*)d_out;

    void *qkv_p, *xh_p, *xl_p, *wqh_p, *wql_p, *woh_p, *wol_p, *ah_p, *al_p;
    void *qh_p, *ql_p, *kh_p, *kl_p, *vh_p, *vl_p;
    cudaGetSymbolAddress(&qkv_p, g_qkv);
    cudaGetSymbolAddress(&xh_p, g_x_hi);
    cudaGetSymbolAddress(&xl_p, g_x_lo);
    cudaGetSymbolAddress(&wqh_p, g_wqkvT_hi);
    cudaGetSymbolAddress(&wql_p, g_wqkvT_lo);
    cudaGetSymbolAddress(&woh_p, g_woT_hi);
    cudaGetSymbolAddress(&wol_p, g_woT_lo);
    cudaGetSymbolAddress(&ah_p, g_att_hi);
    cudaGetSymbolAddress(&al_p, g_att_lo);
    cudaGetSymbolAddress(&qh_p, g_q_hi);
    cudaGetSymbolAddress(&ql_p, g_q_lo);
    cudaGetSymbolAddress(&kh_p, g_k_hi);
    cudaGetSymbolAddress(&kl_p, g_k_lo);
    cudaGetSymbolAddress(&vh_p, g_v_hi);
    cudaGetSymbolAddress(&vl_p, g_v_lo);
    float* qkv = (float*)qkv_p;

    cudaFuncSetAttribute(tc_gemm_kernel, cudaFuncAttributeMaxDynamicSharedMemorySize,
                         GSMEM_TOTAL);
    cudaFuncSetAttribute(flash_tc_kernel, cudaFuncAttributeMaxDynamicSharedMemorySize,
                         FSMEM);

    // 1) split x
    {
        int n4 = M_ * DIM_ / 4;
        conv_split_kernel<<<(n4 + 255) / 256, 256>>>(
            x, (__nv_bfloat16*)xh_p, (__nv_bfloat16*)xl_p, n4);
    }
    // 2) transpose + split weights
    conv_transpose_kernel<<<dim3(QKVN / 32, KDIM / 32), 256>>>(
        wqkv, (__nv_bfloat16*)wqh_p, (__nv_bfloat16*)wql_p, KDIM, QKVN);
    conv_transpose_kernel<<<dim3(DIM_ / 32, KDIM / 32), 256>>>(
        wo, (__nv_bfloat16*)woh_p, (__nv_bfloat16*)wol_p, KDIM, DIM_);

    // 3) qkv = x @ wqkv
    tc_gemm_kernel<<<dim3(QKVN / GBN, M_ / GBM), 256, GSMEM_TOTAL>>>(
        (const __nv_bfloat16*)xh_p, (const __nv_bfloat16*)xl_p,
        (const __nv_bfloat16*)wqh_p, (const __nv_bfloat16*)wql_p,
        qkv, QKVN, KDIM);

    // 4) rope + split + head separation
    {
        int ntot = M_ * (QKVN / 2);
        rope_split_kernel<<<(ntot + 255) / 256, 256>>>(
            qkv, fc,
            (__nv_bfloat16*)qh_p, (__nv_bfloat16*)ql_p,
            (__nv_bfloat16*)kh_p, (__nv_bfloat16*)kl_p,
            (__nv_bfloat16*)vh_p, (__nv_bfloat16*)vl_p);
    }

    // 5) tensor-core flash attention -> bf16 hi/lo att
    flash_tc_kernel<<<dim3(S_ / 64, NH_, B_), 128, FSMEM>>>(
        (const __nv_bfloat16*)qh_p, (const __nv_bfloat16*)ql_p,
        (const __nv_bfloat16*)kh_p, (const __nv_bfloat16*)kl_p,
        (const __nv_bfloat16*)vh_p, (const __nv_bfloat16*)vl_p,
        (__nv_bfloat16*)ah_p, (__nv_bfloat16*)al_p);

    // 6) out = att @ wo
    tc_gemm_kernel<<<dim3(DIM_ / GBN, M_ / GBM), 256, GSMEM_TOTAL>>>(
        (const __nv_bfloat16*)ah_p, (const __nv_bfloat16*)al_p,
        (const __nv_bfloat16*)woh_p, (const __nv_bfloat16*)wol_p,
        out, DIM_, KDIM);
}

// round 5
// speedup vs baseline: 3.4842x; 1.0160x over previous
#include <cuda_runtime.h>
#include <cuda_bf16.h>
#include <cstdint>

// ---------------- problem constants ----------------
#define B_   2
#define S_   2048
#define DIM_ 2048
#define NH_  32
#define NKV_ 8
#define HD_  64
#define QKVN 3072
#define M_   (B_ * S_)
#define KDIM 2048

// ---------------- scratch ----------------
__device__ float g_qkv[(size_t)M_ * QKVN];
__device__ __nv_bfloat16 g_x_hi[(size_t)M_ * DIM_];
__device__ __nv_bfloat16 g_x_lo[(size_t)M_ * DIM_];
__device__ __nv_bfloat16 g_wqkvT_hi[(size_t)QKVN * DIM_];
__device__ __nv_bfloat16 g_wqkvT_lo[(size_t)QKVN * DIM_];
__device__ __nv_bfloat16 g_woT_hi[(size_t)DIM_ * DIM_];
__device__ __nv_bfloat16 g_woT_lo[(size_t)DIM_ * DIM_];
__device__ __nv_bfloat16 g_att_hi[(size_t)M_ * DIM_];
__device__ __nv_bfloat16 g_att_lo[(size_t)M_ * DIM_];
__device__ __nv_bfloat16 g_q_hi[(size_t)B_ * NH_ * S_ * HD_];
__device__ __nv_bfloat16 g_q_lo[(size_t)B_ * NH_ * S_ * HD_];
__device__ __nv_bfloat16 g_k_hi[(size_t)B_ * NKV_ * S_ * HD_];
__device__ __nv_bfloat16 g_k_lo[(size_t)B_ * NKV_ * S_ * HD_];
__device__ __nv_bfloat16 g_v_hi[(size_t)B_ * NKV_ * S_ * HD_];
__device__ __nv_bfloat16 g_v_lo[(size_t)B_ * NKV_ * S_ * HD_];

// ============================================================================
// helpers (sm_80-compatible only)
// ============================================================================
__device__ __forceinline__ uint32_t smem_u32(const void* p) {
    uint32_t a;
    asm("{ .reg .u64 t; cvta.to.shared.u64 t, %1; cvt.u32.u64 %0, t; }"
        : "=r"(a) : "l"(p));
    return a;
}
__device__ __forceinline__ void cp_async16(uint32_t s, const void* g) {
    asm volatile("cp.async.cg.shared.global [%0], [%1], 16;" :: "r"(s), "l"(g));
}
__device__ __forceinline__ void cp_commit() {
    asm volatile("cp.async.commit_group;" ::: "memory");
}
__device__ __forceinline__ void cp_wait0() {
    asm volatile("cp.async.wait_group 0;" ::: "memory");
}
__device__ __forceinline__ void ldmatrix_x4(uint32_t& r0, uint32_t& r1,
                                            uint32_t& r2, uint32_t& r3, uint32_t a) {
    asm volatile("ldmatrix.sync.aligned.m8n8.x4.shared.b16 {%0,%1,%2,%3}, [%4];"
                 : "=r"(r0), "=r"(r1), "=r"(r2), "=r"(r3) : "r"(a));
}
__device__ __forceinline__ void ldmatrix_x4_trans(uint32_t& r0, uint32_t& r1,
                                                  uint32_t& r2, uint32_t& r3, uint32_t a) {
    asm volatile("ldmatrix.sync.aligned.m8n8.x4.trans.shared.b16 {%0,%1,%2,%3}, [%4];"
                 : "=r"(r0), "=r"(r1), "=r"(r2), "=r"(r3) : "r"(a));
}
__device__ __forceinline__ void mma_bf16(float* c, uint32_t a0, uint32_t a1,
                                         uint32_t a2, uint32_t a3,
                                         uint32_t b0, uint32_t b1) {
    asm volatile(
        "mma.sync.aligned.m16n8k16.row.col.f32.bf16.bf16.f32 "
        "{%0,%1,%2,%3}, {%4,%5,%6,%7}, {%8,%9}, {%0,%1,%2,%3};"
        : "+f"(c[0]), "+f"(c[1]), "+f"(c[2]), "+f"(c[3])
        : "r"(a0), "r"(a1), "r"(a2), "r"(a3), "r"(b0), "r"(b1));
}
__device__ __forceinline__ uint32_t pack_hi2(float a, float b) {
    __nv_bfloat162 t = __floats2bfloat162_rn(a, b);
    return *(uint32_t*)&t;
}
__device__ __forceinline__ uint32_t pack_lo2(float a, float b) {
    float ah = __bfloat162float(__float2bfloat16(a));
    float bh = __bfloat162float(__float2bfloat16(b));
    __nv_bfloat162 t = __floats2bfloat162_rn(a - ah, b - bh);
    return *(uint32_t*)&t;
}

// ============================================================================
// tc_gemm v2: CTA 128x128, 4 warps, warp tile 64x64. BK=32, 2-stage cp.async.
// 3-term bf16 split, fp32 accum. Higher MMA:ldmatrix ratio (96:16 per k-step).
// ============================================================================
#define GBM 128
#define GBN 128
#define GBK 32
#define GSTRIDE 80
#define GTILE (GBM * GSTRIDE)
#define GSTAGE (4 * GTILE)
#define GSMEM_TOTAL (2 * GSTAGE)

__global__ __launch_bounds__(128) void tc_gemm_kernel(
    const __nv_bfloat16* __restrict__ Ah, const __nv_bfloat16* __restrict__ Al,
    const __nv_bfloat16* __restrict__ Bh, const __nv_bfloat16* __restrict__ Bl,
    float* __restrict__ C, int N, int K)
{
    extern __shared__ char smem[];
    const uint32_t sb = smem_u32(smem);
    const int tid = threadIdx.x;
    const int wid = tid >> 5;
    const int lane = tid & 31;
    const int mb = blockIdx.y * GBM;
    const int nb = blockIdx.x * GBN;
    const int wm = (wid >> 1) * 64;
    const int wn = (wid & 1) * 64;

    auto load_stage = [&](int stage, int k0) {
        uint32_t base = sb + stage * GSTAGE;
        const __nv_bfloat16* gA[2] = {Ah, Al};
        const __nv_bfloat16* gB[2] = {Bh, Bl};
#pragma unroll
        for (int t = 0; t < 2; t++) {
            uint32_t sA = base + t * GTILE;
            uint32_t sB = base + (2 + t) * GTILE;
#pragma unroll
            for (int i = 0; i < 4; i++) {
                int slot = i * 128 + tid;
                int r = slot >> 2, sg = slot & 3;
                cp_async16(sA + r * GSTRIDE + sg * 16, gA[t] + (size_t)(mb + r) * K + k0 + sg * 8);
                cp_async16(sB + r * GSTRIDE + sg * 16, gB[t] + (size_t)(nb + r) * K + k0 + sg * 8);
            }
        }
        cp_commit();
    };

    float acc[4][8][4];
#pragma unroll
    for (int i = 0; i < 4; i++)
#pragma unroll
        for (int j = 0; j < 8; j++)
#pragma unroll
            for (int e = 0; e < 4; e++) acc[i][j][e] = 0.f;

    const uint32_t aoff = (uint32_t)((lane & 15) * GSTRIDE + (lane >> 4) * 16);
    const uint32_t boff = (uint32_t)(((lane & 7) + ((lane >> 4) * 8)) * GSTRIDE
                                     + (((lane >> 3) & 1) * 16));

    load_stage(0, 0);
    const int niter = K / GBK;
    for (int it = 0; it < niter; it++) {
        cp_wait0();
        __syncthreads();
        if (it + 1 < niter) load_stage((it + 1) & 1, (it + 1) * GBK);

        uint32_t base = sb + (it & 1) * GSTAGE;
        uint32_t bAh = base, bAl = base + GTILE;
        uint32_t bBh = base + 2 * GTILE, bBl = base + 3 * GTILE;

#pragma unroll
        for (int ks = 0; ks < 2; ks++) {
            uint32_t kb = (uint32_t)(ks * 32);
            uint32_t ah[4][4], al[4][4];
#pragma unroll
            for (int mi = 0; mi < 4; mi++) {
                uint32_t rowb = (uint32_t)((wm + mi * 16) * GSTRIDE) + kb;
                ldmatrix_x4(ah[mi][0], ah[mi][1], ah[mi][2], ah[mi][3], bAh + rowb + aoff);
                ldmatrix_x4(al[mi][0], al[mi][1], al[mi][2], al[mi][3], bAl + rowb + aoff);
            }
            uint32_t bh[8][2], bl[8][2];
#pragma unroll
            for (int nj = 0; nj < 4; nj++) {
                uint32_t rowb = (uint32_t)((wn + nj * 16) * GSTRIDE) + kb;
                uint32_t t0, t1, t2, t3;
                ldmatrix_x4(t0, t1, t2, t3, bBh + rowb + boff);
                bh[nj * 2][0] = t0; bh[nj * 2][1] = t1;
                bh[nj * 2 + 1][0] = t2; bh[nj * 2 + 1][1] = t3;
                ldmatrix_x4(t0, t1, t2, t3, bBl + rowb + boff);
                bl[nj * 2][0] = t0; bl[nj * 2][1] = t1;
                bl[nj * 2 + 1][0] = t2; bl[nj * 2 + 1][1] = t3;
            }
#pragma unroll
            for (int mi = 0; mi < 4; mi++)
#pragma unroll
                for (int nj = 0; nj < 8; nj++) {
                    mma_bf16(acc[mi][nj], ah[mi][0], ah[mi][1], ah[mi][2], ah[mi][3],
                             bh[nj][0], bh[nj][1]);
                    mma_bf16(acc[mi][nj], ah[mi][0], ah[mi][1], ah[mi][2], ah[mi][3],
                             bl[nj][0], bl[nj][1]);
                    mma_bf16(acc[mi][nj], al[mi][0], al[mi][1], al[mi][2], al[mi][3],
                             bh[nj][0], bh[nj][1]);
                }
        }
        __syncthreads();
    }

    const int g = lane >> 2, c = lane & 3;
#pragma unroll
    for (int mi = 0; mi < 4; mi++) {
#pragma unroll
        for (int nj = 0; nj < 8; nj++) {
            float* cp0 = C + (size_t)(mb + wm + mi * 16 + g) * N + nb + wn + nj * 8 + 2 * c;
            float* cp1 = cp0 + (size_t)8 * N;
            *(float2*)cp0 = make_float2(acc[mi][nj][0], acc[mi][nj][1]);
            *(float2*)cp1 = make_float2(acc[mi][nj][2], acc[mi][nj][3]);
        }
    }
}

// ============================================================================
// conversion kernels
// ============================================================================
__global__ __launch_bounds__(256) void conv_split_kernel(
    const float* __restrict__ A, __nv_bfloat16* __restrict__ H,
    __nv_bfloat16* __restrict__ L, int n4)
{
    int i = blockIdx.x * blockDim.x + threadIdx.x;
    if (i >= n4) return;
    float4 v = *(const float4*)(A + (size_t)i * 4);
    float vv[4] = {v.x, v.y, v.z, v.w};
    __nv_bfloat16 h[4], l[4];
#pragma unroll
    for (int j = 0; j < 4; j++) {
        h[j] = __float2bfloat16(vv[j]);
        l[j] = __float2bfloat16(vv[j] - __bfloat162float(h[j]));
    }
    *(uint2*)(H + (size_t)i * 4) = *(uint2*)h;
    *(uint2*)(L + (size_t)i * 4) = *(uint2*)l;
}

__global__ __launch_bounds__(256) void conv_transpose_kernel(
    const float* __restrict__ W, __nv_bfloat16* __restrict__ Th,
    __nv_bfloat16* __restrict__ Tl, int K, int N)
{
    __shared__ float t[32][33];
    const int k0 = blockIdx.y * 32, n0 = blockIdx.x * 32;
    const int tx = threadIdx.x & 31, ty = threadIdx.x >> 5;
#pragma unroll
    for (int i = 0; i < 32; i += 8)
        t[ty + i][tx] = W[(size_t)(k0 + ty + i) * N + n0 + tx];
    __syncthreads();
#pragma unroll
    for (int i = 0; i < 32; i += 8) {
        float v = t[tx][ty + i];
        __nv_bfloat16 h = __float2bfloat16(v);
        size_t o = (size_t)(n0 + ty + i) * K + k0 + tx;
        Th[o] = h;
        Tl[o] = __float2bfloat16(v - __bfloat162float(h));
    }
}

// ============================================================================
// fused rope + split + head-separate
// ============================================================================
__global__ __launch_bounds__(256) void rope_split_kernel(
    const float* __restrict__ qkv, const float* __restrict__ fc,
    __nv_bfloat16* __restrict__ Qh, __nv_bfloat16* __restrict__ Ql,
    __nv_bfloat16* __restrict__ Kh, __nv_bfloat16* __restrict__ Kl,
    __nv_bfloat16* __restrict__ Vh, __nv_bfloat16* __restrict__ Vl)
{
    const int NTOT = M_ * (QKVN / 2);
    int idx = blockIdx.x * blockDim.x + threadIdx.x;
    if (idx >= NTOT) return;
    int c2  = idx % (QKVN / 2);
    int row = idx / (QKVN / 2);
    int col = c2 * 2;
    int b = row / S_, s = row % S_;

    float2 x = *(const float2*)(qkv + (size_t)row * QKVN + col);

    __nv_bfloat16* dh;
    __nv_bfloat16* dl;
    size_t o;
    bool do_rope;
    int d;
    if (col < DIM_) {
        int h = col >> 6; d = col & 63;
        o = ((size_t)(b * NH_ + h) * S_ + s) * HD_ + d;
        dh = Qh; dl = Ql; do_rope = true;
    } else if (col < DIM_ + NKV_ * HD_) {
        int kvh = (col - DIM_) >> 6; d = col & 63;
        o = ((size_t)(b * NKV_ + kvh) * S_ + s) * HD_ + d;
        dh = Kh; dl = Kl; do_rope = true;
    } else {
        int kvh = (col - DIM_ - NKV_ * HD_) >> 6; d = col & 63;
        o = ((size_t)(b * NKV_ + kvh) * S_ + s) * HD_ + d;
        dh = Vh; dl = Vl; do_rope = false;
    }

    if (do_rope) {
        float2 f = *(const float2*)(fc + (size_t)s * HD_ + d);
        float rx = x.x * f.x - x.y * f.y;
        float ry = x.y * f.x + x.x * f.y;
        x.x = rx; x.y = ry;
    }
    __nv_bfloat16 hx = __float2bfloat16(x.x);
    __nv_bfloat16 hy = __float2bfloat16(x.y);
    __nv_bfloat16 hv[2] = {hx, hy};
    __nv_bfloat16 lv[2] = {__float2bfloat16(x.x - __bfloat162float(hx)),
                           __float2bfloat16(x.y - __bfloat162float(hy))};
    *(uint32_t*)(dh + o) = *(uint32_t*)hv;
    *(uint32_t*)(dl + o) = *(uint32_t*)lv;
}

// ============================================================================
// Tensor-core flash attention (unchanged from R4)
// ============================================================================
#define FSTR 144
#define FTILE (64 * FSTR)
#define FSTAGE (4 * FTILE)
#define FSMEM (2 * FSTAGE)

__global__ __launch_bounds__(128) void flash_tc_kernel(
    const __nv_bfloat16* __restrict__ Qh, const __nv_bfloat16* __restrict__ Ql,
    const __nv_bfloat16* __restrict__ Kh, const __nv_bfloat16* __restrict__ Kl,
    const __nv_bfloat16* __restrict__ Vh, const __nv_bfloat16* __restrict__ Vl,
    __nv_bfloat16* __restrict__ Oh, __nv_bfloat16* __restrict__ Ol)
{
    extern __shared__ char smem[];
    const uint32_t sb = smem_u32(smem);
    const int tid  = threadIdx.x;
    const int wid  = tid >> 5;
    const int lane = tid & 31;
    const int qtile = blockIdx.x;
    const int h     = blockIdx.y;
    const int b     = blockIdx.z;
    const int kvh   = h >> 2;
    const int q0    = qtile * 64;
    const int wm    = wid * 16;

    const __nv_bfloat16* qhp = Qh + ((size_t)(b * NH_ + h) * S_ + q0) * HD_;
    const __nv_bfloat16* qlp = Ql + ((size_t)(b * NH_ + h) * S_ + q0) * HD_;
    const __nv_bfloat16* khp = Kh + ((size_t)(b * NKV_ + kvh) * S_) * HD_;
    const __nv_bfloat16* klp = Kl + ((size_t)(b * NKV_ + kvh) * S_) * HD_;
    const __nv_bfloat16* vhp = Vh + ((size_t)(b * NKV_ + kvh) * S_) * HD_;
    const __nv_bfloat16* vlp = Vl + ((size_t)(b * NKV_ + kvh) * S_) * HD_;

    const int lr[4] = {(tid) >> 3, (tid + 128) >> 3, (tid + 256) >> 3, (tid + 384) >> 3};
    const int ls = tid & 7;

#pragma unroll
    for (int i = 0; i < 4; i++) {
        cp_async16(sb + lr[i] * FSTR + ls * 16, qhp + (size_t)lr[i] * HD_ + ls * 8);
        cp_async16(sb + FTILE + lr[i] * FSTR + ls * 16, qlp + (size_t)lr[i] * HD_ + ls * 8);
    }
    cp_commit();
    cp_wait0();
    __syncthreads();

    const uint32_t aoff = (uint32_t)((lane & 15) * FSTR + (lane >> 4) * 16);
    const uint32_t boff = (uint32_t)(((lane & 7) + ((lane >> 4) * 8)) * FSTR
                                     + (((lane >> 3) & 1) * 16));
    const uint32_t voff = (uint32_t)(((lane & 7) + (((lane >> 3) & 1) * 8)) * FSTR
                                     + ((lane >> 4) * 16));

    uint32_t qfh[4][4], qfl[4][4];
#pragma unroll
    for (int ks = 0; ks < 4; ks++) {
        uint32_t rowb = (uint32_t)(wm * FSTR + ks * 32);
        ldmatrix_x4(qfh[ks][0], qfh[ks][1], qfh[ks][2], qfh[ks][3], sb + rowb + aoff);
        ldmatrix_x4(qfl[ks][0], qfl[ks][1], qfl[ks][2], qfl[ks][3], sb + FTILE + rowb + aoff);
    }
    __syncthreads();

    auto load_kv = [&](int st, int j) {
        uint32_t base = sb + st * FSTAGE;
        size_t g0 = (size_t)(j * 64) * HD_;
#pragma unroll
        for (int i = 0; i < 4; i++) {
            uint32_t so = lr[i] * FSTR + ls * 16;
            size_t go = g0 + (size_t)lr[i] * HD_ + ls * 8;
            cp_async16(base + so, khp + go);
            cp_async16(base + FTILE + so, klp + go);
            cp_async16(base + 2 * FTILE + so, vhp + go);
            cp_async16(base + 3 * FTILE + so, vlp + go);
        }
        cp_commit();
    };
    load_kv(0, 0);

    float m0 = -1e30f, m1 = -1e30f, l0 = 0.f, l1 = 0.f;
    float o[8][4];
#pragma unroll
    for (int nj = 0; nj < 8; nj++)
#pragma unroll
        for (int e = 0; e < 4; e++) o[nj][e] = 0.f;

    const int r0 = lane >> 2;
    const int tig = lane & 3;
    const int qg0 = q0 + wm + r0;
    const int qg1 = qg0 + 8;

    for (int j = 0; j <= qtile; j++) {
        cp_wait0();
        __syncthreads();
        if (j < qtile) load_kv((j + 1) & 1, j + 1);

        uint32_t base = sb + (j & 1) * FSTAGE;
        uint32_t bKh = base, bKl = base + FTILE;
        uint32_t bVh = base + 2 * FTILE, bVl = base + 3 * FTILE;

        float c[8][4];
#pragma unroll
        for (int nj = 0; nj < 8; nj++)
#pragma unroll
            for (int e = 0; e < 4; e++) c[nj][e] = 0.f;

#pragma unroll
        for (int ks = 0; ks < 4; ks++) {
#pragma unroll
            for (int njp = 0; njp < 4; njp++) {
                uint32_t off = (uint32_t)(njp * 16 * FSTR + ks * 32) + boff;
                uint32_t h0, h1, h2, h3, l0r, l1r, l2r, l3r;
                ldmatrix_x4(h0, h1, h2, h3, bKh + off);
                ldmatrix_x4(l0r, l1r, l2r, l3r, bKl + off);
                mma_bf16(c[2 * njp], qfh[ks][0], qfh[ks][1], qfh[ks][2], qfh[ks][3], h0, h1);
                mma_bf16(c[2 * njp], qfh[ks][0], qfh[ks][1], qfh[ks][2], qfh[ks][3], l0r, l1r);
                mma_bf16(c[2 * njp], qfl[ks][0], qfl[ks][1], qfl[ks][2], qfl[ks][3], h0, h1);
                mma_bf16(c[2 * njp + 1], qfh[ks][0], qfh[ks][1], qfh[ks][2], qfh[ks][3], h2, h3);
                mma_bf16(c[2 * njp + 1], qfh[ks][0], qfh[ks][1], qfh[ks][2], qfh[ks][3], l2r, l3r);
                mma_bf16(c[2 * njp + 1], qfl[ks][0], qfl[ks][1], qfl[ks][2], qfl[ks][3], h2, h3);
            }
        }

        const bool diag = (j == qtile);
        float tm0 = -1e30f, tm1 = -1e30f;
#pragma unroll
        for (int nj = 0; nj < 8; nj++) {
            int colb = j * 64 + nj * 8 + 2 * tig;
#pragma unroll
            for (int e = 0; e < 4; e++) {
                float sv = c[nj][e] * 0.125f;
                if (diag) {
                    int colg = colb + (e & 1);
                    int rowg = (e < 2) ? qg0 : qg1;
                    if (colg > rowg) sv = -1e30f;
                }
                c[nj][e] = sv;
            }
            tm0 = fmaxf(tm0, fmaxf(c[nj][0], c[nj][1]));
            tm1 = fmaxf(tm1, fmaxf(c[nj][2], c[nj][3]));
        }
        tm0 = fmaxf(tm0, __shfl_xor_sync(0xffffffffu, tm0, 1));
        tm0 = fmaxf(tm0, __shfl_xor_sync(0xffffffffu, tm0, 2));
        tm1 = fmaxf(tm1, __shfl_xor_sync(0xffffffffu, tm1, 1));
        tm1 = fmaxf(tm1, __shfl_xor_sync(0xffffffffu, tm1, 2));

        float mn0 = fmaxf(m0, tm0), mn1 = fmaxf(m1, tm1);
        float sc0 = __expf(m0 - mn0), sc1 = __expf(m1 - mn1);
        m0 = mn0; m1 = mn1;

        float sum0 = 0.f, sum1 = 0.f;
#pragma unroll
        for (int nj = 0; nj < 8; nj++) {
            c[nj][0] = __expf(c[nj][0] - mn0);
            c[nj][1] = __expf(c[nj][1] - mn0);
            c[nj][2] = __expf(c[nj][2] - mn1);
            c[nj][3] = __expf(c[nj][3] - mn1);
            sum0 += c[nj][0] + c[nj][1];
            sum1 += c[nj][2] + c[nj][3];
        }
        sum0 += __shfl_xor_sync(0xffffffffu, sum0, 1);
        sum0 += __shfl_xor_sync(0xffffffffu, sum0, 2);
        sum1 += __shfl_xor_sync(0xffffffffu, sum1, 1);
        sum1 += __shfl_xor_sync(0xffffffffu, sum1, 2);
        l0 = l0 * sc0 + sum0;
        l1 = l1 * sc1 + sum1;

#pragma unroll
        for (int nj = 0; nj < 8; nj++) {
            o[nj][0] *= sc0; o[nj][1] *= sc0;
            o[nj][2] *= sc1; o[nj][3] *= sc1;
        }

#pragma unroll
        for (int ksv = 0; ksv < 4; ksv++) {
            uint32_t aph[4], apl[4];
            aph[0] = pack_hi2(c[2 * ksv][0], c[2 * ksv][1]);
            aph[1] = pack_hi2(c[2 * ksv][2], c[2 * ksv][3]);
            aph[2] = pack_hi2(c[2 * ksv + 1][0], c[2 * ksv + 1][1]);
            aph[3] = pack_hi2(c[2 * ksv + 1][2], c[2 * ksv + 1][3]);
            apl[0] = pack_lo2(c[2 * ksv][0], c[2 * ksv][1]);
            apl[1] = pack_lo2(c[2 * ksv][2], c[2 * ksv][3]);
            apl[2] = pack_lo2(c[2 * ksv + 1][0], c[2 * ksv + 1][1]);
            apl[3] = pack_lo2(c[2 * ksv + 1][2], c[2 * ksv + 1][3]);
#pragma unroll
            for (int njp = 0; njp < 4; njp++) {
                uint32_t off = (uint32_t)(ksv * 16 * FSTR + njp * 32) + voff;
                uint32_t h0, h1, h2, h3, l0r, l1r, l2r, l3r;
                ldmatrix_x4_trans(h0, h1, h2, h3, bVh + off);
                ldmatrix_x4_trans(l0r, l1r, l2r, l3r, bVl + off);
                mma_bf16(o[2 * njp], aph[0], aph[1], aph[2], aph[3], h0, h1);
                mma_bf16(o[2 * njp], aph[0], aph[1], aph[2], aph[3], l0r, l1r);
                mma_bf16(o[2 * njp], apl[0], apl[1], apl[2], apl[3], h0, h1);
                mma_bf16(o[2 * njp + 1], aph[0], aph[1], aph[2], aph[3], h2, h3);
                mma_bf16(o[2 * njp + 1], aph[0], aph[1], aph[2], aph[3], l2r, l3r);
                mma_bf16(o[2 * njp + 1], apl[0], apl[1], apl[2], apl[3], h2, h3);
            }
        }
    }

    float inv0 = 1.f / l0, inv1 = 1.f / l1;
    size_t gr0 = (size_t)(b * S_ + q0 + wm + r0) * DIM_ + h * HD_ + 2 * tig;
    size_t gr1 = gr0 + (size_t)8 * DIM_;
#pragma unroll
    for (int nj = 0; nj < 8; nj++) {
        float v0 = o[nj][0] * inv0, v1 = o[nj][1] * inv0;
        float v2 = o[nj][2] * inv1, v3 = o[nj][3] * inv1;
        *(uint32_t*)(Oh + gr0 + nj * 8) = pack_hi2(v0, v1);
        *(uint32_t*)(Ol + gr0 + nj * 8) = pack_lo2(v0, v1);
        *(uint32_t*)(Oh + gr1 + nj * 8) = pack_hi2(v2, v3);
        *(uint32_t*)(Ol + gr1 + nj * 8) = pack_lo2(v2, v3);
    }
}

// ============================================================================
// launch
// ============================================================================
extern "C" void kernel_launch(void* const* d_in, const int* in_sizes, int n_in,
                              void* d_out, int out_size)
{
    const float* x    = (const float*)d_in[0];
    const float* fc   = (const float*)d_in[1];
    const float* wqkv = (const float*)d_in[2];
    const float* wo   = (const float*)d_in[3];
    float* out        = (float*)d_out;

    void *qkv_p, *xh_p, *xl_p, *wqh_p, *wql_p, *woh_p, *wol_p, *ah_p, *al_p;
    void *qh_p, *ql_p, *kh_p, *kl_p, *vh_p, *vl_p;
    cudaGetSymbolAddress(&qkv_p, g_qkv);
    cudaGetSymbolAddress(&xh_p, g_x_hi);
    cudaGetSymbolAddress(&xl_p, g_x_lo);
    cudaGetSymbolAddress(&wqh_p, g_wqkvT_hi);
    cudaGetSymbolAddress(&wql_p, g_wqkvT_lo);
    cudaGetSymbolAddress(&woh_p, g_woT_hi);
    cudaGetSymbolAddress(&wol_p, g_woT_lo);
    cudaGetSymbolAddress(&ah_p, g_att_hi);
    cudaGetSymbolAddress(&al_p, g_att_lo);
    cudaGetSymbolAddress(&qh_p, g_q_hi);
    cudaGetSymbolAddress(&ql_p, g_q_lo);
    cudaGetSymbolAddress(&kh_p, g_k_hi);
    cudaGetSymbolAddress(&kl_p, g_k_lo);
    cudaGetSymbolAddress(&vh_p, g_v_hi);
    cudaGetSymbolAddress(&vl_p, g_v_lo);
    float* qkv = (float*)qkv_p;

    cudaFuncSetAttribute(tc_gemm_kernel, cudaFuncAttributeMaxDynamicSharedMemorySize,
                         GSMEM_TOTAL);
    cudaFuncSetAttribute(flash_tc_kernel, cudaFuncAttributeMaxDynamicSharedMemorySize,
                         FSMEM);

    {
        int n4 = M_ * DIM_ / 4;
        conv_split_kernel<<<(n4 + 255) / 256, 256>>>(
            x, (__nv_bfloat16*)xh_p, (__nv_bfloat16*)xl_p, n4);
    }
    conv_transpose_kernel<<<dim3(QKVN / 32, KDIM / 32), 256>>>(
        wqkv, (__nv_bfloat16*)wqh_p, (__nv_bfloat16*)wql_p, KDIM, QKVN);
    conv_transpose_kernel<<<dim3(DIM_ / 32, KDIM / 32), 256>>>(
        wo, (__nv_bfloat16*)woh_p, (__nv_bfloat16*)wol_p, KDIM, DIM_);

    tc_gemm_kernel<<<dim3(QKVN / GBN, M_ / GBM), 128, GSMEM_TOTAL>>>(
        (const __nv_bfloat16*)xh_p, (const __nv_bfloat16*)xl_p,
        (const __nv_bfloat16*)wqh_p, (const __nv_bfloat16*)wql_p,
        qkv, QKVN, KDIM);

    {
        int ntot = M_ * (QKVN / 2);
        rope_split_kernel<<<(ntot + 255) / 256, 256>>>(
            qkv, fc,
            (__nv_bfloat16*)qh_p, (__nv_bfloat16*)ql_p,
            (__nv_bfloat16*)kh_p, (__nv_bfloat16*)kl_p,
            (__nv_bfloat16*)vh_p, (__nv_bfloat16*)vl_p);
    }

    flash_tc_kernel<<<dim3(S_ / 64, NH_, B_), 128, FSMEM>>>(
        (const __nv_bfloat16*)qh_p, (const __nv_bfloat16*)ql_p,
        (const __nv_bfloat16*)kh_p, (const __nv_bfloat16*)kl_p,
        (const __nv_bfloat16*)vh_p, (const __nv_bfloat16*)vl_p,
        (__nv_bfloat16*)ah_p, (__nv_bfloat16*)al_p);

    tc_gemm_kernel<<<dim3(DIM_ / GBN, M_ / GBM), 128, GSMEM_TOTAL>>>(
        (const __nv_bfloat16*)ah_p, (const __nv_bfloat16*)al_p,
        (const __nv_bfloat16*)woh_p, (const __nv_bfloat16*)wol_p,
        out, DIM_, KDIM);
}

// round 6
// speedup vs baseline: 3.5598x; 1.0217x over previous
#include <cuda_runtime.h>
#include <cuda_bf16.h>
#include <cstdint>

// ---------------- problem constants ----------------
#define B_   2
#define S_   2048
#define DIM_ 2048
#define NH_  32
#define NKV_ 8
#define HD_  64
#define QKVN 3072
#define M_   (B_ * S_)
#define KDIM 2048

// ---------------- scratch ----------------
__device__ __nv_bfloat16 g_x_hi[(size_t)M_ * DIM_];
__device__ __nv_bfloat16 g_x_lo[(size_t)M_ * DIM_];
__device__ __nv_bfloat16 g_wqkvT_hi[(size_t)QKVN * DIM_];
__device__ __nv_bfloat16 g_wqkvT_lo[(size_t)QKVN * DIM_];
__device__ __nv_bfloat16 g_woT_hi[(size_t)DIM_ * DIM_];
__device__ __nv_bfloat16 g_woT_lo[(size_t)DIM_ * DIM_];
__device__ __nv_bfloat16 g_att_hi[(size_t)M_ * DIM_];
__device__ __nv_bfloat16 g_att_lo[(size_t)M_ * DIM_];
__device__ __nv_bfloat16 g_q_hi[(size_t)B_ * NH_ * S_ * HD_];
__device__ __nv_bfloat16 g_q_lo[(size_t)B_ * NH_ * S_ * HD_];
__device__ __nv_bfloat16 g_k_hi[(size_t)B_ * NKV_ * S_ * HD_];
__device__ __nv_bfloat16 g_k_lo[(size_t)B_ * NKV_ * S_ * HD_];
__device__ __nv_bfloat16 g_v_hi[(size_t)B_ * NKV_ * S_ * HD_];
__device__ __nv_bfloat16 g_v_lo[(size_t)B_ * NKV_ * S_ * HD_];

// ============================================================================
// helpers (sm_80-compatible only)
// ============================================================================
__device__ __forceinline__ uint32_t smem_u32(const void* p) {
    uint32_t a;
    asm("{ .reg .u64 t; cvta.to.shared.u64 t, %1; cvt.u32.u64 %0, t; }"
        : "=r"(a) : "l"(p));
    return a;
}
__device__ __forceinline__ void cp_async16(uint32_t s, const void* g) {
    asm volatile("cp.async.cg.shared.global [%0], [%1], 16;" :: "r"(s), "l"(g));
}
__device__ __forceinline__ void cp_commit() {
    asm volatile("cp.async.commit_group;" ::: "memory");
}
__device__ __forceinline__ void cp_wait0() {
    asm volatile("cp.async.wait_group 0;" ::: "memory");
}
__device__ __forceinline__ void ldmatrix_x4(uint32_t& r0, uint32_t& r1,
                                            uint32_t& r2, uint32_t& r3, uint32_t a) {
    asm volatile("ldmatrix.sync.aligned.m8n8.x4.shared.b16 {%0,%1,%2,%3}, [%4];"
                 : "=r"(r0), "=r"(r1), "=r"(r2), "=r"(r3) : "r"(a));
}
__device__ __forceinline__ void ldmatrix_x4_trans(uint32_t& r0, uint32_t& r1,
                                                  uint32_t& r2, uint32_t& r3, uint32_t a) {
    asm volatile("ldmatrix.sync.aligned.m8n8.x4.trans.shared.b16 {%0,%1,%2,%3}, [%4];"
                 : "=r"(r0), "=r"(r1), "=r"(r2), "=r"(r3) : "r"(a));
}
__device__ __forceinline__ void mma_bf16(float* c, uint32_t a0, uint32_t a1,
                                         uint32_t a2, uint32_t a3,
                                         uint32_t b0, uint32_t b1) {
    asm volatile(
        "mma.sync.aligned.m16n8k16.row.col.f32.bf16.bf16.f32 "
        "{%0,%1,%2,%3}, {%4,%5,%6,%7}, {%8,%9}, {%0,%1,%2,%3};"
        : "+f"(c[0]), "+f"(c[1]), "+f"(c[2]), "+f"(c[3])
        : "r"(a0), "r"(a1), "r"(a2), "r"(a3), "r"(b0), "r"(b1));
}
__device__ __forceinline__ uint32_t pack_hi2(float a, float b) {
    __nv_bfloat162 t = __floats2bfloat162_rn(a, b);
    return *(uint32_t*)&t;
}
__device__ __forceinline__ uint32_t pack_lo2(float a, float b) {
    float ah = __bfloat162float(__float2bfloat16(a));
    float bh = __bfloat162float(__float2bfloat16(b));
    __nv_bfloat162 t = __floats2bfloat162_rn(a - ah, b - bh);
    return *(uint32_t*)&t;
}

// ============================================================================
// tc_gemm: CTA 128x128, 4 warps, warp tile 64x64, BK=32, 2-stage cp.async.
// 3-term bf16 split, TERM-MAJOR MMA order (acc reuse distance 32).
// MODE 0: plain fp32 C.  MODE 1: fused rope + hi/lo split + head-separated
//         Q/K/V stores (qkv projection epilogue).
// ============================================================================
#define GBM 128
#define GBN 128
#define GBK 32
#define GSTRIDE 80
#define GTILE (GBM * GSTRIDE)
#define GSTAGE (4 * GTILE)
#define GSMEM_TOTAL (2 * GSTAGE)

template <int MODE>
__global__ __launch_bounds__(128) void tc_gemm_kernel(
    const __nv_bfloat16* __restrict__ Ah, const __nv_bfloat16* __restrict__ Al,
    const __nv_bfloat16* __restrict__ Bh, const __nv_bfloat16* __restrict__ Bl,
    float* __restrict__ C,
    const float* __restrict__ fc,
    __nv_bfloat16* __restrict__ Qh, __nv_bfloat16* __restrict__ Ql,
    __nv_bfloat16* __restrict__ Kh, __nv_bfloat16* __restrict__ Kl,
    __nv_bfloat16* __restrict__ Vh, __nv_bfloat16* __restrict__ Vl,
    int N, int K)
{
    extern __shared__ char smem[];
    const uint32_t sb = smem_u32(smem);
    const int tid = threadIdx.x;
    const int wid = tid >> 5;
    const int lane = tid & 31;
    const int mb = blockIdx.y * GBM;
    const int nb = blockIdx.x * GBN;
    const int wm = (wid >> 1) * 64;
    const int wn = (wid & 1) * 64;

    auto load_stage = [&](int stage, int k0) {
        uint32_t base = sb + stage * GSTAGE;
        const __nv_bfloat16* gA[2] = {Ah, Al};
        const __nv_bfloat16* gB[2] = {Bh, Bl};
#pragma unroll
        for (int t = 0; t < 2; t++) {
            uint32_t sA = base + t * GTILE;
            uint32_t sB = base + (2 + t) * GTILE;
#pragma unroll
            for (int i = 0; i < 4; i++) {
                int slot = i * 128 + tid;
                int r = slot >> 2, sg = slot & 3;
                cp_async16(sA + r * GSTRIDE + sg * 16, gA[t] + (size_t)(mb + r) * K + k0 + sg * 8);
                cp_async16(sB + r * GSTRIDE + sg * 16, gB[t] + (size_t)(nb + r) * K + k0 + sg * 8);
            }
        }
        cp_commit();
    };

    float acc[4][8][4];
#pragma unroll
    for (int i = 0; i < 4; i++)
#pragma unroll
        for (int j = 0; j < 8; j++)
#pragma unroll
            for (int e = 0; e < 4; e++) acc[i][j][e] = 0.f;

    const uint32_t aoff = (uint32_t)((lane & 15) * GSTRIDE + (lane >> 4) * 16);
    const uint32_t boff = (uint32_t)(((lane & 7) + ((lane >> 4) * 8)) * GSTRIDE
                                     + (((lane >> 3) & 1) * 16));

    load_stage(0, 0);
    const int niter = K / GBK;
    for (int it = 0; it < niter; it++) {
        cp_wait0();
        __syncthreads();
        if (it + 1 < niter) load_stage((it + 1) & 1, (it + 1) * GBK);

        uint32_t base = sb + (it & 1) * GSTAGE;
        uint32_t bAh = base, bAl = base + GTILE;
        uint32_t bBh = base + 2 * GTILE, bBl = base + 3 * GTILE;

#pragma unroll
        for (int ks = 0; ks < 2; ks++) {
            uint32_t kb = (uint32_t)(ks * 32);
            uint32_t ah[4][4], al[4][4];
#pragma unroll
            for (int mi = 0; mi < 4; mi++) {
                uint32_t rowb = (uint32_t)((wm + mi * 16) * GSTRIDE) + kb;
                ldmatrix_x4(ah[mi][0], ah[mi][1], ah[mi][2], ah[mi][3], bAh + rowb + aoff);
                ldmatrix_x4(al[mi][0], al[mi][1], al[mi][2], al[mi][3], bAl + rowb + aoff);
            }
            uint32_t bh[8][2], bl[8][2];
#pragma unroll
            for (int nj = 0; nj < 4; nj++) {
                uint32_t rowb = (uint32_t)((wn + nj * 16) * GSTRIDE) + kb;
                uint32_t t0, t1, t2, t3;
                ldmatrix_x4(t0, t1, t2, t3, bBh + rowb + boff);
                bh[nj * 2][0] = t0; bh[nj * 2][1] = t1;
                bh[nj * 2 + 1][0] = t2; bh[nj * 2 + 1][1] = t3;
                ldmatrix_x4(t0, t1, t2, t3, bBl + rowb + boff);
                bl[nj * 2][0] = t0; bl[nj * 2][1] = t1;
                bl[nj * 2 + 1][0] = t2; bl[nj * 2 + 1][1] = t3;
            }
            // term-major: all 32 accumulators per term -> no RAW chains
#pragma unroll
            for (int mi = 0; mi < 4; mi++)
#pragma unroll
                for (int nj = 0; nj < 8; nj++)
                    mma_bf16(acc[mi][nj], ah[mi][0], ah[mi][1], ah[mi][2], ah[mi][3],
                             bh[nj][0], bh[nj][1]);
#pragma unroll
            for (int mi = 0; mi < 4; mi++)
#pragma unroll
                for (int nj = 0; nj < 8; nj++)
                    mma_bf16(acc[mi][nj], ah[mi][0], ah[mi][1], ah[mi][2], ah[mi][3],
                             bl[nj][0], bl[nj][1]);
#pragma unroll
            for (int mi = 0; mi < 4; mi++)
#pragma unroll
                for (int nj = 0; nj < 8; nj++)
                    mma_bf16(acc[mi][nj], al[mi][0], al[mi][1], al[mi][2], al[mi][3],
                             bh[nj][0], bh[nj][1]);
        }
        __syncthreads();
    }

    const int g = lane >> 2, c = lane & 3;
#pragma unroll
    for (int mi = 0; mi < 4; mi++) {
#pragma unroll
        for (int nj = 0; nj < 8; nj++) {
            const int col = nb + wn + nj * 8 + 2 * c;
#pragma unroll
            for (int rr = 0; rr < 2; rr++) {
                const int row = mb + wm + mi * 16 + g + rr * 8;
                float v0 = acc[mi][nj][rr * 2 + 0];
                float v1 = acc[mi][nj][rr * 2 + 1];
                if (MODE == 0) {
                    *(float2*)(C + (size_t)row * N + col) = make_float2(v0, v1);
                } else {
                    const int b = row >> 11, s = row & (S_ - 1);
                    const int d = col & 63;
                    if (col < DIM_ + NKV_ * HD_) {
                        // rope (Q or K)
                        float2 f = *(const float2*)(fc + (size_t)s * HD_ + d);
                        float rx = v0 * f.x - v1 * f.y;
                        float ry = v1 * f.x + v0 * f.y;
                        v0 = rx; v1 = ry;
                    }
                    uint32_t hi = pack_hi2(v0, v1);
                    uint32_t lo = pack_lo2(v0, v1);
                    size_t o;
                    __nv_bfloat16 *dh, *dl;
                    if (col < DIM_) {
                        int h = col >> 6;
                        o = ((size_t)(b * NH_ + h) * S_ + s) * HD_ + d;
                        dh = Qh; dl = Ql;
                    } else if (col < DIM_ + NKV_ * HD_) {
                        int kvh = (col - DIM_) >> 6;
                        o = ((size_t)(b * NKV_ + kvh) * S_ + s) * HD_ + d;
                        dh = Kh; dl = Kl;
                    } else {
                        int kvh = (col - DIM_ - NKV_ * HD_) >> 6;
                        o = ((size_t)(b * NKV_ + kvh) * S_ + s) * HD_ + d;
                        dh = Vh; dl = Vl;
                    }
                    *(uint32_t*)(dh + o) = hi;
                    *(uint32_t*)(dl + o) = lo;
                }
            }
        }
    }
}

// ============================================================================
// conversion kernels
// ============================================================================
__global__ __launch_bounds__(256) void conv_split_kernel(
    const float* __restrict__ A, __nv_bfloat16* __restrict__ H,
    __nv_bfloat16* __restrict__ L, int n4)
{
    int i = blockIdx.x * blockDim.x + threadIdx.x;
    if (i >= n4) return;
    float4 v = *(const float4*)(A + (size_t)i * 4);
    float vv[4] = {v.x, v.y, v.z, v.w};
    __nv_bfloat16 h[4], l[4];
#pragma unroll
    for (int j = 0; j < 4; j++) {
        h[j] = __float2bfloat16(vv[j]);
        l[j] = __float2bfloat16(vv[j] - __bfloat162float(h[j]));
    }
    *(uint2*)(H + (size_t)i * 4) = *(uint2*)h;
    *(uint2*)(L + (size_t)i * 4) = *(uint2*)l;
}

__global__ __launch_bounds__(256) void conv_transpose_kernel(
    const float* __restrict__ W, __nv_bfloat16* __restrict__ Th,
    __nv_bfloat16* __restrict__ Tl, int K, int N)
{
    __shared__ float t[32][33];
    const int k0 = blockIdx.y * 32, n0 = blockIdx.x * 32;
    const int tx = threadIdx.x & 31, ty = threadIdx.x >> 5;
#pragma unroll
    for (int i = 0; i < 32; i += 8)
        t[ty + i][tx] = W[(size_t)(k0 + ty + i) * N + n0 + tx];
    __syncthreads();
#pragma unroll
    for (int i = 0; i < 32; i += 8) {
        float v = t[tx][ty + i];
        __nv_bfloat16 h = __float2bfloat16(v);
        size_t o = (size_t)(n0 + ty + i) * K + k0 + tx;
        Th[o] = h;
        Tl[o] = __float2bfloat16(v - __bfloat162float(h));
    }
}

// ============================================================================
// Tensor-core flash attention, term-major MMA ordering.
// ============================================================================
#define FSTR 144
#define FTILE (64 * FSTR)
#define FSTAGE (4 * FTILE)
#define FSMEM (2 * FSTAGE)

__global__ __launch_bounds__(128) void flash_tc_kernel(
    const __nv_bfloat16* __restrict__ Qh, const __nv_bfloat16* __restrict__ Ql,
    const __nv_bfloat16* __restrict__ Kh, const __nv_bfloat16* __restrict__ Kl,
    const __nv_bfloat16* __restrict__ Vh, const __nv_bfloat16* __restrict__ Vl,
    __nv_bfloat16* __restrict__ Oh, __nv_bfloat16* __restrict__ Ol)
{
    extern __shared__ char smem[];
    const uint32_t sb = smem_u32(smem);
    const int tid  = threadIdx.x;
    const int wid  = tid >> 5;
    const int lane = tid & 31;
    const int qtile = blockIdx.x;
    const int h     = blockIdx.y;
    const int b     = blockIdx.z;
    const int kvh   = h >> 2;
    const int q0    = qtile * 64;
    const int wm    = wid * 16;

    const __nv_bfloat16* qhp = Qh + ((size_t)(b * NH_ + h) * S_ + q0) * HD_;
    const __nv_bfloat16* qlp = Ql + ((size_t)(b * NH_ + h) * S_ + q0) * HD_;
    const __nv_bfloat16* khp = Kh + ((size_t)(b * NKV_ + kvh) * S_) * HD_;
    const __nv_bfloat16* klp = Kl + ((size_t)(b * NKV_ + kvh) * S_) * HD_;
    const __nv_bfloat16* vhp = Vh + ((size_t)(b * NKV_ + kvh) * S_) * HD_;
    const __nv_bfloat16* vlp = Vl + ((size_t)(b * NKV_ + kvh) * S_) * HD_;

    const int lr[4] = {(tid) >> 3, (tid + 128) >> 3, (tid + 256) >> 3, (tid + 384) >> 3};
    const int ls = tid & 7;

#pragma unroll
    for (int i = 0; i < 4; i++) {
        cp_async16(sb + lr[i] * FSTR + ls * 16, qhp + (size_t)lr[i] * HD_ + ls * 8);
        cp_async16(sb + FTILE + lr[i] * FSTR + ls * 16, qlp + (size_t)lr[i] * HD_ + ls * 8);
    }
    cp_commit();
    cp_wait0();
    __syncthreads();

    const uint32_t aoff = (uint32_t)((lane & 15) * FSTR + (lane >> 4) * 16);
    const uint32_t boff = (uint32_t)(((lane & 7) + ((lane >> 4) * 8)) * FSTR
                                     + (((lane >> 3) & 1) * 16));
    const uint32_t voff = (uint32_t)(((lane & 7) + (((lane >> 3) & 1) * 8)) * FSTR
                                     + ((lane >> 4) * 16));

    uint32_t qfh[4][4], qfl[4][4];
#pragma unroll
    for (int ks = 0; ks < 4; ks++) {
        uint32_t rowb = (uint32_t)(wm * FSTR + ks * 32);
        ldmatrix_x4(qfh[ks][0], qfh[ks][1], qfh[ks][2], qfh[ks][3], sb + rowb + aoff);
        ldmatrix_x4(qfl[ks][0], qfl[ks][1], qfl[ks][2], qfl[ks][3], sb + FTILE + rowb + aoff);
    }
    __syncthreads();

    auto load_kv = [&](int st, int j) {
        uint32_t base = sb + st * FSTAGE;
        size_t g0 = (size_t)(j * 64) * HD_;
#pragma unroll
        for (int i = 0; i < 4; i++) {
            uint32_t so = lr[i] * FSTR + ls * 16;
            size_t go = g0 + (size_t)lr[i] * HD_ + ls * 8;
            cp_async16(base + so, khp + go);
            cp_async16(base + FTILE + so, klp + go);
            cp_async16(base + 2 * FTILE + so, vhp + go);
            cp_async16(base + 3 * FTILE + so, vlp + go);
        }
        cp_commit();
    };
    load_kv(0, 0);

    float m0 = -1e30f, m1 = -1e30f, l0 = 0.f, l1 = 0.f;
    float o[8][4];
#pragma unroll
    for (int nj = 0; nj < 8; nj++)
#pragma unroll
        for (int e = 0; e < 4; e++) o[nj][e] = 0.f;

    const int r0 = lane >> 2;
    const int tig = lane & 3;
    const int qg0 = q0 + wm + r0;
    const int qg1 = qg0 + 8;

    for (int j = 0; j <= qtile; j++) {
        cp_wait0();
        __syncthreads();
        if (j < qtile) load_kv((j + 1) & 1, j + 1);

        uint32_t base = sb + (j & 1) * FSTAGE;
        uint32_t bKh = base, bKl = base + FTILE;
        uint32_t bVh = base + 2 * FTILE, bVl = base + 3 * FTILE;

        float c[8][4];
#pragma unroll
        for (int nj = 0; nj < 8; nj++)
#pragma unroll
            for (int e = 0; e < 4; e++) c[nj][e] = 0.f;

#pragma unroll
        for (int ks = 0; ks < 4; ks++) {
            uint32_t kf[4][4], lf[4][4];
#pragma unroll
            for (int njp = 0; njp < 4; njp++) {
                uint32_t off = (uint32_t)(njp * 16 * FSTR + ks * 32) + boff;
                ldmatrix_x4(kf[njp][0], kf[njp][1], kf[njp][2], kf[njp][3], bKh + off);
                ldmatrix_x4(lf[njp][0], lf[njp][1], lf[njp][2], lf[njp][3], bKl + off);
            }
            // term-major sweeps (acc reuse distance 8)
#pragma unroll
            for (int njp = 0; njp < 4; njp++) {
                mma_bf16(c[2 * njp],     qfh[ks][0], qfh[ks][1], qfh[ks][2], qfh[ks][3], kf[njp][0], kf[njp][1]);
                mma_bf16(c[2 * njp + 1], qfh[ks][0], qfh[ks][1], qfh[ks][2], qfh[ks][3], kf[njp][2], kf[njp][3]);
            }
#pragma unroll
            for (int njp = 0; njp < 4; njp++) {
                mma_bf16(c[2 * njp],     qfh[ks][0], qfh[ks][1], qfh[ks][2], qfh[ks][3], lf[njp][0], lf[njp][1]);
                mma_bf16(c[2 * njp + 1], qfh[ks][0], qfh[ks][1], qfh[ks][2], qfh[ks][3], lf[njp][2], lf[njp][3]);
            }
#pragma unroll
            for (int njp = 0; njp < 4; njp++) {
                mma_bf16(c[2 * njp],     qfl[ks][0], qfl[ks][1], qfl[ks][2], qfl[ks][3], kf[njp][0], kf[njp][1]);
                mma_bf16(c[2 * njp + 1], qfl[ks][0], qfl[ks][1], qfl[ks][2], qfl[ks][3], kf[njp][2], kf[njp][3]);
            }
        }

        const bool diag = (j == qtile);
        float tm0 = -1e30f, tm1 = -1e30f;
#pragma unroll
        for (int nj = 0; nj < 8; nj++) {
            int colb = j * 64 + nj * 8 + 2 * tig;
#pragma unroll
            for (int e = 0; e < 4; e++) {
                float sv = c[nj][e] * 0.125f;
                if (diag) {
                    int colg = colb + (e & 1);
                    int rowg = (e < 2) ? qg0 : qg1;
                    if (colg > rowg) sv = -1e30f;
                }
                c[nj][e] = sv;
            }
            tm0 = fmaxf(tm0, fmaxf(c[nj][0], c[nj][1]));
            tm1 = fmaxf(tm1, fmaxf(c[nj][2], c[nj][3]));
        }
        tm0 = fmaxf(tm0, __shfl_xor_sync(0xffffffffu, tm0, 1));
        tm0 = fmaxf(tm0, __shfl_xor_sync(0xffffffffu, tm0, 2));
        tm1 = fmaxf(tm1, __shfl_xor_sync(0xffffffffu, tm1, 1));
        tm1 = fmaxf(tm1, __shfl_xor_sync(0xffffffffu, tm1, 2));

        float mn0 = fmaxf(m0, tm0), mn1 = fmaxf(m1, tm1);
        float sc0 = __expf(m0 - mn0), sc1 = __expf(m1 - mn1);
        m0 = mn0; m1 = mn1;

        float sum0 = 0.f, sum1 = 0.f;
#pragma unroll
        for (int nj = 0; nj < 8; nj++) {
            c[nj][0] = __expf(c[nj][0] - mn0);
            c[nj][1] = __expf(c[nj][1] - mn0);
            c[nj][2] = __expf(c[nj][2] - mn1);
            c[nj][3] = __expf(c[nj][3] - mn1);
            sum0 += c[nj][0] + c[nj][1];
            sum1 += c[nj][2] + c[nj][3];
        }
        sum0 += __shfl_xor_sync(0xffffffffu, sum0, 1);
        sum0 += __shfl_xor_sync(0xffffffffu, sum0, 2);
        sum1 += __shfl_xor_sync(0xffffffffu, sum1, 1);
        sum1 += __shfl_xor_sync(0xffffffffu, sum1, 2);
        l0 = l0 * sc0 + sum0;
        l1 = l1 * sc1 + sum1;

#pragma unroll
        for (int nj = 0; nj < 8; nj++) {
            o[nj][0] *= sc0; o[nj][1] *= sc0;
            o[nj][2] *= sc1; o[nj][3] *= sc1;
        }

#pragma unroll
        for (int ksv = 0; ksv < 4; ksv++) {
            uint32_t aph[4], apl[4];
            aph[0] = pack_hi2(c[2 * ksv][0], c[2 * ksv][1]);
            aph[1] = pack_hi2(c[2 * ksv][2], c[2 * ksv][3]);
            aph[2] = pack_hi2(c[2 * ksv + 1][0], c[2 * ksv + 1][1]);
            aph[3] = pack_hi2(c[2 * ksv + 1][2], c[2 * ksv + 1][3]);
            apl[0] = pack_lo2(c[2 * ksv][0], c[2 * ksv][1]);
            apl[1] = pack_lo2(c[2 * ksv][2], c[2 * ksv][3]);
            apl[2] = pack_lo2(c[2 * ksv + 1][0], c[2 * ksv + 1][1]);
            apl[3] = pack_lo2(c[2 * ksv + 1][2], c[2 * ksv + 1][3]);

            uint32_t vh[4][4], vl[4][4];
#pragma unroll
            for (int njp = 0; njp < 4; njp++) {
                uint32_t off = (uint32_t)(ksv * 16 * FSTR + njp * 32) + voff;
                ldmatrix_x4_trans(vh[njp][0], vh[njp][1], vh[njp][2], vh[njp][3], bVh + off);
                ldmatrix_x4_trans(vl[njp][0], vl[njp][1], vl[njp][2], vl[njp][3], bVl + off);
            }
            // term-major sweeps
#pragma unroll
            for (int njp = 0; njp < 4; njp++) {
                mma_bf16(o[2 * njp],     aph[0], aph[1], aph[2], aph[3], vh[njp][0], vh[njp][1]);
                mma_bf16(o[2 * njp + 1], aph[0], aph[1], aph[2], aph[3], vh[njp][2], vh[njp][3]);
            }
#pragma unroll
            for (int njp = 0; njp < 4; njp++) {
                mma_bf16(o[2 * njp],     aph[0], aph[1], aph[2], aph[3], vl[njp][0], vl[njp][1]);
                mma_bf16(o[2 * njp + 1], aph[0], aph[1], aph[2], aph[3], vl[njp][2], vl[njp][3]);
            }
#pragma unroll
            for (int njp = 0; njp < 4; njp++) {
                mma_bf16(o[2 * njp],     apl[0], apl[1], apl[2], apl[3], vh[njp][0], vh[njp][1]);
                mma_bf16(o[2 * njp + 1], apl[0], apl[1], apl[2], apl[3], vh[njp][2], vh[njp][3]);
            }
        }
    }

    float inv0 = 1.f / l0, inv1 = 1.f / l1;
    size_t gr0 = (size_t)(b * S_ + q0 + wm + r0) * DIM_ + h * HD_ + 2 * tig;
    size_t gr1 = gr0 + (size_t)8 * DIM_;
#pragma unroll
    for (int nj = 0; nj < 8; nj++) {
        float v0 = o[nj][0] * inv0, v1 = o[nj][1] * inv0;
        float v2 = o[nj][2] * inv1, v3 = o[nj][3] * inv1;
        *(uint32_t*)(Oh + gr0 + nj * 8) = pack_hi2(v0, v1);
        *(uint32_t*)(Ol + gr0 + nj * 8) = pack_lo2(v0, v1);
        *(uint32_t*)(Oh + gr1 + nj * 8) = pack_hi2(v2, v3);
        *(uint32_t*)(Ol + gr1 + nj * 8) = pack_lo2(v2, v3);
    }
}

// ============================================================================
// launch
// ============================================================================
extern "C" void kernel_launch(void* const* d_in, const int* in_sizes, int n_in,
                              void* d_out, int out_size)
{
    const float* x    = (const float*)d_in[0];
    const float* fc   = (const float*)d_in[1];
    const float* wqkv = (const float*)d_in[2];
    const float* wo   = (const float*)d_in[3];
    float* out        = (float*)d_out;

    void *xh_p, *xl_p, *wqh_p, *wql_p, *woh_p, *wol_p, *ah_p, *al_p;
    void *qh_p, *ql_p, *kh_p, *kl_p, *vh_p, *vl_p;
    cudaGetSymbolAddress(&xh_p, g_x_hi);
    cudaGetSymbolAddress(&xl_p, g_x_lo);
    cudaGetSymbolAddress(&wqh_p, g_wqkvT_hi);
    cudaGetSymbolAddress(&wql_p, g_wqkvT_lo);
    cudaGetSymbolAddress(&woh_p, g_woT_hi);
    cudaGetSymbolAddress(&wol_p, g_woT_lo);
    cudaGetSymbolAddress(&ah_p, g_att_hi);
    cudaGetSymbolAddress(&al_p, g_att_lo);
    cudaGetSymbolAddress(&qh_p, g_q_hi);
    cudaGetSymbolAddress(&ql_p, g_q_lo);
    cudaGetSymbolAddress(&kh_p, g_k_hi);
    cudaGetSymbolAddress(&kl_p, g_k_lo);
    cudaGetSymbolAddress(&vh_p, g_v_hi);
    cudaGetSymbolAddress(&vl_p, g_v_lo);

    cudaFuncSetAttribute(tc_gemm_kernel<0>, cudaFuncAttributeMaxDynamicSharedMemorySize,
                         GSMEM_TOTAL);
    cudaFuncSetAttribute(tc_gemm_kernel<1>, cudaFuncAttributeMaxDynamicSharedMemorySize,
                         GSMEM_TOTAL);
    cudaFuncSetAttribute(flash_tc_kernel, cudaFuncAttributeMaxDynamicSharedMemorySize,
                         FSMEM);

    // 1) split x
    {
        int n4 = M_ * DIM_ / 4;
        conv_split_kernel<<<(n4 + 255) / 256, 256>>>(
            x, (__nv_bfloat16*)xh_p, (__nv_bfloat16*)xl_p, n4);
    }
    // 2) transpose + split weights
    conv_transpose_kernel<<<dim3(QKVN / 32, KDIM / 32), 256>>>(
        wqkv, (__nv_bfloat16*)wqh_p, (__nv_bfloat16*)wql_p, KDIM, QKVN);
    conv_transpose_kernel<<<dim3(DIM_ / 32, KDIM / 32), 256>>>(
        wo, (__nv_bfloat16*)woh_p, (__nv_bfloat16*)wol_p, KDIM, DIM_);

    // 3) qkv projection + fused rope/split/head-separation epilogue
    tc_gemm_kernel<1><<<dim3(QKVN / GBN, M_ / GBM), 128, GSMEM_TOTAL>>>(
        (const __nv_bfloat16*)xh_p, (const __nv_bfloat16*)xl_p,
        (const __nv_bfloat16*)wqh_p, (const __nv_bfloat16*)wql_p,
        nullptr, fc,
        (__nv_bfloat16*)qh_p, (__nv_bfloat16*)ql_p,
        (__nv_bfloat16*)kh_p, (__nv_bfloat16*)kl_p,
        (__nv_bfloat16*)vh_p, (__nv_bfloat16*)vl_p,
        QKVN, KDIM);

    // 4) tensor-core flash attention -> bf16 hi/lo att
    flash_tc_kernel<<<dim3(S_ / 64, NH_, B_), 128, FSMEM>>>(
        (const __nv_bfloat16*)qh_p, (const __nv_bfloat16*)ql_p,
        (const __nv_bfloat16*)kh_p, (const __nv_bfloat16*)kl_p,
        (const __nv_bfloat16*)vh_p, (const __nv_bfloat16*)vl_p,
        (__nv_bfloat16*)ah_p, (__nv_bfloat16*)al_p);

    // 5) out = att @ wo
    tc_gemm_kernel<0><<<dim3(DIM_ / GBN, M_ / GBM), 128, GSMEM_TOTAL>>>(
        (const __nv_bfloat16*)ah_p, (const __nv_bfloat16*)al_p,
        (const __nv_bfloat16*)woh_p, (const __nv_bfloat16*)wol_p,
        out, nullptr,
        nullptr, nullptr, nullptr, nullptr, nullptr, nullptr,
        DIM_, KDIM);
}

// round 7
// speedup vs baseline: 4.7375x; 1.3308x over previous
#include <cuda_runtime.h>
#include <cuda_fp16.h>
#include <cstdint>

// ---------------- problem constants ----------------
#define B_   2
#define S_   2048
#define DIM_ 2048
#define NH_  32
#define NKV_ 8
#define HD_  64
#define QKVN 3072
#define M_   (B_ * S_)
#define KDIM 2048

// ---------------- scratch (fp16) ----------------
__device__ __half g_x_hi[(size_t)M_ * DIM_];
__device__ __half g_x_lo[(size_t)M_ * DIM_];
__device__ __half g_wqkvT_hi[(size_t)QKVN * DIM_];
__device__ __half g_wqkvT_lo[(size_t)QKVN * DIM_];
__device__ __half g_woT_hi[(size_t)DIM_ * DIM_];
__device__ __half g_att_hi[(size_t)M_ * DIM_];
__device__ __half g_q_hi[(size_t)B_ * NH_ * S_ * HD_];
__device__ __half g_q_lo[(size_t)B_ * NH_ * S_ * HD_];
__device__ __half g_k_hi[(size_t)B_ * NKV_ * S_ * HD_];
__device__ __half g_k_lo[(size_t)B_ * NKV_ * S_ * HD_];
__device__ __half g_v_hi[(size_t)B_ * NKV_ * S_ * HD_];

// ============================================================================
// helpers (sm_80-compatible only)
// ============================================================================
__device__ __forceinline__ uint32_t smem_u32(const void* p) {
    uint32_t a;
    asm("{ .reg .u64 t; cvta.to.shared.u64 t, %1; cvt.u32.u64 %0, t; }"
        : "=r"(a) : "l"(p));
    return a;
}
__device__ __forceinline__ void cp_async16(uint32_t s, const void* g) {
    asm volatile("cp.async.cg.shared.global [%0], [%1], 16;" :: "r"(s), "l"(g));
}
__device__ __forceinline__ void cp_commit() {
    asm volatile("cp.async.commit_group;" ::: "memory");
}
__device__ __forceinline__ void cp_wait0() {
    asm volatile("cp.async.wait_group 0;" ::: "memory");
}
__device__ __forceinline__ void ldmatrix_x4(uint32_t& r0, uint32_t& r1,
                                            uint32_t& r2, uint32_t& r3, uint32_t a) {
    asm volatile("ldmatrix.sync.aligned.m8n8.x4.shared.b16 {%0,%1,%2,%3}, [%4];"
                 : "=r"(r0), "=r"(r1), "=r"(r2), "=r"(r3) : "r"(a));
}
__device__ __forceinline__ void ldmatrix_x4_trans(uint32_t& r0, uint32_t& r1,
                                                  uint32_t& r2, uint32_t& r3, uint32_t a) {
    asm volatile("ldmatrix.sync.aligned.m8n8.x4.trans.shared.b16 {%0,%1,%2,%3}, [%4];"
                 : "=r"(r0), "=r"(r1), "=r"(r2), "=r"(r3) : "r"(a));
}
__device__ __forceinline__ void mma_fp16(float* c, uint32_t a0, uint32_t a1,
                                         uint32_t a2, uint32_t a3,
                                         uint32_t b0, uint32_t b1) {
    asm volatile(
        "mma.sync.aligned.m16n8k16.row.col.f32.f16.f16.f32 "
        "{%0,%1,%2,%3}, {%4,%5,%6,%7}, {%8,%9}, {%0,%1,%2,%3};"
        : "+f"(c[0]), "+f"(c[1]), "+f"(c[2]), "+f"(c[3])
        : "r"(a0), "r"(a1), "r"(a2), "r"(a3), "r"(b0), "r"(b1));
}
__device__ __forceinline__ uint32_t pack_h2(float a, float b) {
    __half2 t = __floats2half2_rn(a, b);
    return *(uint32_t*)&t;
}
__device__ __forceinline__ uint32_t pack_h2_lo(float a, float b) {
    float ah = __half2float(__float2half_rn(a));
    float bh = __half2float(__float2half_rn(b));
    __half2 t = __floats2half2_rn(a - ah, b - bh);
    return *(uint32_t*)&t;
}

// ============================================================================
// tc_gemm3: 3-term fp16 split GEMM. CTA 128x128, 4 warps (64x64 tiles), BK=32.
// MODE 0: fp32 C.  MODE 1: fused rope + Q/K hi/lo + V hi epilogue.
// ============================================================================
#define GBM 128
#define GBN 128
#define GBK 32
#define GSTRIDE 80
#define GTILE (GBM * GSTRIDE)
#define GSTAGE (4 * GTILE)
#define GSMEM_TOTAL (2 * GSTAGE)

template <int MODE>
__global__ __launch_bounds__(128) void tc_gemm3_kernel(
    const __half* __restrict__ Ah, const __half* __restrict__ Al,
    const __half* __restrict__ Bh, const __half* __restrict__ Bl,
    float* __restrict__ C,
    const float* __restrict__ fc,
    __half* __restrict__ Qh, __half* __restrict__ Ql,
    __half* __restrict__ Kh, __half* __restrict__ Kl,
    __half* __restrict__ Vh,
    int N, int K)
{
    extern __shared__ char smem[];
    const uint32_t sb = smem_u32(smem);
    const int tid = threadIdx.x;
    const int wid = tid >> 5;
    const int lane = tid & 31;
    const int mb = blockIdx.y * GBM;
    const int nb = blockIdx.x * GBN;
    const int wm = (wid >> 1) * 64;
    const int wn = (wid & 1) * 64;

    auto load_stage = [&](int stage, int k0) {
        uint32_t base = sb + stage * GSTAGE;
        const __half* gA[2] = {Ah, Al};
        const __half* gB[2] = {Bh, Bl};
#pragma unroll
        for (int t = 0; t < 2; t++) {
            uint32_t sA = base + t * GTILE;
            uint32_t sB = base + (2 + t) * GTILE;
#pragma unroll
            for (int i = 0; i < 4; i++) {
                int slot = i * 128 + tid;
                int r = slot >> 2, sg = slot & 3;
                cp_async16(sA + r * GSTRIDE + sg * 16, gA[t] + (size_t)(mb + r) * K + k0 + sg * 8);
                cp_async16(sB + r * GSTRIDE + sg * 16, gB[t] + (size_t)(nb + r) * K + k0 + sg * 8);
            }
        }
        cp_commit();
    };

    float acc[4][8][4];
#pragma unroll
    for (int i = 0; i < 4; i++)
#pragma unroll
        for (int j = 0; j < 8; j++)
#pragma unroll
            for (int e = 0; e < 4; e++) acc[i][j][e] = 0.f;

    const uint32_t aoff = (uint32_t)((lane & 15) * GSTRIDE + (lane >> 4) * 16);
    const uint32_t boff = (uint32_t)(((lane & 7) + ((lane >> 4) * 8)) * GSTRIDE
                                     + (((lane >> 3) & 1) * 16));

    load_stage(0, 0);
    const int niter = K / GBK;
    for (int it = 0; it < niter; it++) {
        cp_wait0();
        __syncthreads();
        if (it + 1 < niter) load_stage((it + 1) & 1, (it + 1) * GBK);

        uint32_t base = sb + (it & 1) * GSTAGE;
        uint32_t bAh = base, bAl = base + GTILE;
        uint32_t bBh = base + 2 * GTILE, bBl = base + 3 * GTILE;

#pragma unroll
        for (int ks = 0; ks < 2; ks++) {
            uint32_t kb = (uint32_t)(ks * 32);
            uint32_t ah[4][4], al[4][4];
#pragma unroll
            for (int mi = 0; mi < 4; mi++) {
                uint32_t rowb = (uint32_t)((wm + mi * 16) * GSTRIDE) + kb;
                ldmatrix_x4(ah[mi][0], ah[mi][1], ah[mi][2], ah[mi][3], bAh + rowb + aoff);
                ldmatrix_x4(al[mi][0], al[mi][1], al[mi][2], al[mi][3], bAl + rowb + aoff);
            }
            uint32_t bh[8][2], bl[8][2];
#pragma unroll
            for (int nj = 0; nj < 4; nj++) {
                uint32_t rowb = (uint32_t)((wn + nj * 16) * GSTRIDE) + kb;
                uint32_t t0, t1, t2, t3;
                ldmatrix_x4(t0, t1, t2, t3, bBh + rowb + boff);
                bh[nj * 2][0] = t0; bh[nj * 2][1] = t1;
                bh[nj * 2 + 1][0] = t2; bh[nj * 2 + 1][1] = t3;
                ldmatrix_x4(t0, t1, t2, t3, bBl + rowb + boff);
                bl[nj * 2][0] = t0; bl[nj * 2][1] = t1;
                bl[nj * 2 + 1][0] = t2; bl[nj * 2 + 1][1] = t3;
            }
#pragma unroll
            for (int mi = 0; mi < 4; mi++)
#pragma unroll
                for (int nj = 0; nj < 8; nj++) {
                    mma_fp16(acc[mi][nj], ah[mi][0], ah[mi][1], ah[mi][2], ah[mi][3],
                             bh[nj][0], bh[nj][1]);
                    mma_fp16(acc[mi][nj], ah[mi][0], ah[mi][1], ah[mi][2], ah[mi][3],
                             bl[nj][0], bl[nj][1]);
                    mma_fp16(acc[mi][nj], al[mi][0], al[mi][1], al[mi][2], al[mi][3],
                             bh[nj][0], bh[nj][1]);
                }
        }
        __syncthreads();
    }

    const int g = lane >> 2, c = lane & 3;
#pragma unroll
    for (int mi = 0; mi < 4; mi++) {
#pragma unroll
        for (int nj = 0; nj < 8; nj++) {
            const int col = nb + wn + nj * 8 + 2 * c;
#pragma unroll
            for (int rr = 0; rr < 2; rr++) {
                const int row = mb + wm + mi * 16 + g + rr * 8;
                float v0 = acc[mi][nj][rr * 2 + 0];
                float v1 = acc[mi][nj][rr * 2 + 1];
                if (MODE == 0) {
                    *(float2*)(C + (size_t)row * N + col) = make_float2(v0, v1);
                } else {
                    const int b = row >> 11, s = row & (S_ - 1);
                    const int d = col & 63;
                    if (col < DIM_ + NKV_ * HD_) {
                        float2 f = *(const float2*)(fc + (size_t)s * HD_ + d);
                        float rx = v0 * f.x - v1 * f.y;
                        float ry = v1 * f.x + v0 * f.y;
                        v0 = rx; v1 = ry;
                    }
                    if (col < DIM_) {
                        int h = col >> 6;
                        size_t o = ((size_t)(b * NH_ + h) * S_ + s) * HD_ + d;
                        *(uint32_t*)(Qh + o) = pack_h2(v0, v1);
                        *(uint32_t*)(Ql + o) = pack_h2_lo(v0, v1);
                    } else if (col < DIM_ + NKV_ * HD_) {
                        int kvh = (col - DIM_) >> 6;
                        size_t o = ((size_t)(b * NKV_ + kvh) * S_ + s) * HD_ + d;
                        *(uint32_t*)(Kh + o) = pack_h2(v0, v1);
                        *(uint32_t*)(Kl + o) = pack_h2_lo(v0, v1);
                    } else {
                        int kvh = (col - DIM_ - NKV_ * HD_) >> 6;
                        size_t o = ((size_t)(b * NKV_ + kvh) * S_ + s) * HD_ + d;
                        *(uint32_t*)(Vh + o) = pack_h2(v0, v1);
                    }
                }
            }
        }
    }
}

// ============================================================================
// tc_gemm1: single-term fp16 GEMM (out = att @ woT^T). CTA 128x128, 4 warps.
// ============================================================================
#define G1STAGE (2 * GTILE)
#define G1SMEM (2 * G1STAGE)

__global__ __launch_bounds__(128) void tc_gemm1_kernel(
    const __half* __restrict__ A, const __half* __restrict__ B,
    float* __restrict__ C, int N, int K)
{
    extern __shared__ char smem[];
    const uint32_t sb = smem_u32(smem);
    const int tid = threadIdx.x;
    const int wid = tid >> 5;
    const int lane = tid & 31;
    const int mb = blockIdx.y * GBM;
    const int nb = blockIdx.x * GBN;
    const int wm = (wid >> 1) * 64;
    const int wn = (wid & 1) * 64;

    auto load_stage = [&](int stage, int k0) {
        uint32_t base = sb + stage * G1STAGE;
        uint32_t sA = base, sB = base + GTILE;
#pragma unroll
        for (int i = 0; i < 4; i++) {
            int slot = i * 128 + tid;
            int r = slot >> 2, sg = slot & 3;
            cp_async16(sA + r * GSTRIDE + sg * 16, A + (size_t)(mb + r) * K + k0 + sg * 8);
            cp_async16(sB + r * GSTRIDE + sg * 16, B + (size_t)(nb + r) * K + k0 + sg * 8);
        }
        cp_commit();
    };

    float acc[4][8][4];
#pragma unroll
    for (int i = 0; i < 4; i++)
#pragma unroll
        for (int j = 0; j < 8; j++)
#pragma unroll
            for (int e = 0; e < 4; e++) acc[i][j][e] = 0.f;

    const uint32_t aoff = (uint32_t)((lane & 15) * GSTRIDE + (lane >> 4) * 16);
    const uint32_t boff = (uint32_t)(((lane & 7) + ((lane >> 4) * 8)) * GSTRIDE
                                     + (((lane >> 3) & 1) * 16));

    load_stage(0, 0);
    const int niter = K / GBK;
    for (int it = 0; it < niter; it++) {
        cp_wait0();
        __syncthreads();
        if (it + 1 < niter) load_stage((it + 1) & 1, (it + 1) * GBK);

        uint32_t base = sb + (it & 1) * G1STAGE;
        uint32_t bA = base, bB = base + GTILE;

#pragma unroll
        for (int ks = 0; ks < 2; ks++) {
            uint32_t kb = (uint32_t)(ks * 32);
            uint32_t af[4][4];
#pragma unroll
            for (int mi = 0; mi < 4; mi++) {
                uint32_t rowb = (uint32_t)((wm + mi * 16) * GSTRIDE) + kb;
                ldmatrix_x4(af[mi][0], af[mi][1], af[mi][2], af[mi][3], bA + rowb + aoff);
            }
            uint32_t bf[8][2];
#pragma unroll
            for (int nj = 0; nj < 4; nj++) {
                uint32_t rowb = (uint32_t)((wn + nj * 16) * GSTRIDE) + kb;
                uint32_t t0, t1, t2, t3;
                ldmatrix_x4(t0, t1, t2, t3, bB + rowb + boff);
                bf[nj * 2][0] = t0; bf[nj * 2][1] = t1;
                bf[nj * 2 + 1][0] = t2; bf[nj * 2 + 1][1] = t3;
            }
#pragma unroll
            for (int mi = 0; mi < 4; mi++)
#pragma unroll
                for (int nj = 0; nj < 8; nj++)
                    mma_fp16(acc[mi][nj], af[mi][0], af[mi][1], af[mi][2], af[mi][3],
                             bf[nj][0], bf[nj][1]);
        }
        __syncthreads();
    }

    const int g = lane >> 2, c = lane & 3;
#pragma unroll
    for (int mi = 0; mi < 4; mi++) {
#pragma unroll
        for (int nj = 0; nj < 8; nj++) {
            float* cp0 = C + (size_t)(mb + wm + mi * 16 + g) * N + nb + wn + nj * 8 + 2 * c;
            float* cp1 = cp0 + (size_t)8 * N;
            *(float2*)cp0 = make_float2(acc[mi][nj][0], acc[mi][nj][1]);
            *(float2*)cp1 = make_float2(acc[mi][nj][2], acc[mi][nj][3]);
        }
    }
}

// ============================================================================
// conversion kernels (fp16)
// ============================================================================
__global__ __launch_bounds__(256) void conv_split_kernel(
    const float* __restrict__ A, __half* __restrict__ H,
    __half* __restrict__ L, int n4)
{
    int i = blockIdx.x * blockDim.x + threadIdx.x;
    if (i >= n4) return;
    float4 v = *(const float4*)(A + (size_t)i * 4);
    float vv[4] = {v.x, v.y, v.z, v.w};
    __half h[4], l[4];
#pragma unroll
    for (int j = 0; j < 4; j++) {
        h[j] = __float2half_rn(vv[j]);
        l[j] = __float2half_rn(vv[j] - __half2float(h[j]));
    }
    *(uint2*)(H + (size_t)i * 4) = *(uint2*)h;
    *(uint2*)(L + (size_t)i * 4) = *(uint2*)l;
}

// W [K][N] fp32 -> Wt hi (and optionally lo) [N][K] fp16
template <int SPLIT>
__global__ __launch_bounds__(256) void conv_transpose_kernel(
    const float* __restrict__ W, __half* __restrict__ Th,
    __half* __restrict__ Tl, int K, int N)
{
    __shared__ float t[32][33];
    const int k0 = blockIdx.y * 32, n0 = blockIdx.x * 32;
    const int tx = threadIdx.x & 31, ty = threadIdx.x >> 5;
#pragma unroll
    for (int i = 0; i < 32; i += 8)
        t[ty + i][tx] = W[(size_t)(k0 + ty + i) * N + n0 + tx];
    __syncthreads();
#pragma unroll
    for (int i = 0; i < 32; i += 8) {
        float v = t[tx][ty + i];
        __half h = __float2half_rn(v);
        size_t o = (size_t)(n0 + ty + i) * K + k0 + tx;
        Th[o] = h;
        if (SPLIT) Tl[o] = __float2half_rn(v - __half2float(h));
    }
}

// ============================================================================
// Flash attention: QK^T 3-term fp16, PV 1-term fp16, att out fp16.
// ============================================================================
#define FSTR 144
#define FTILE (64 * FSTR)
#define FSTAGE (3 * FTILE)       // Kh, Kl, Vh
#define FSMEM (2 * FSTAGE)

__global__ __launch_bounds__(128) void flash_tc_kernel(
    const __half* __restrict__ Qh, const __half* __restrict__ Ql,
    const __half* __restrict__ Kh, const __half* __restrict__ Kl,
    const __half* __restrict__ Vh,
    __half* __restrict__ Oh)
{
    extern __shared__ char smem[];
    const uint32_t sb = smem_u32(smem);
    const int tid  = threadIdx.x;
    const int wid  = tid >> 5;
    const int lane = tid & 31;
    const int qtile = blockIdx.x;
    const int h     = blockIdx.y;
    const int b     = blockIdx.z;
    const int kvh   = h >> 2;
    const int q0    = qtile * 64;
    const int wm    = wid * 16;

    const __half* qhp = Qh + ((size_t)(b * NH_ + h) * S_ + q0) * HD_;
    const __half* qlp = Ql + ((size_t)(b * NH_ + h) * S_ + q0) * HD_;
    const __half* khp = Kh + ((size_t)(b * NKV_ + kvh) * S_) * HD_;
    const __half* klp = Kl + ((size_t)(b * NKV_ + kvh) * S_) * HD_;
    const __half* vhp = Vh + ((size_t)(b * NKV_ + kvh) * S_) * HD_;

    const int lr[4] = {(tid) >> 3, (tid + 128) >> 3, (tid + 256) >> 3, (tid + 384) >> 3};
    const int ls = tid & 7;

    // stage Q hi/lo, build fragments
#pragma unroll
    for (int i = 0; i < 4; i++) {
        cp_async16(sb + lr[i] * FSTR + ls * 16, qhp + (size_t)lr[i] * HD_ + ls * 8);
        cp_async16(sb + FTILE + lr[i] * FSTR + ls * 16, qlp + (size_t)lr[i] * HD_ + ls * 8);
    }
    cp_commit();
    cp_wait0();
    __syncthreads();

    const uint32_t aoff = (uint32_t)((lane & 15) * FSTR + (lane >> 4) * 16);
    const uint32_t boff = (uint32_t)(((lane & 7) + ((lane >> 4) * 8)) * FSTR
                                     + (((lane >> 3) & 1) * 16));
    const uint32_t voff = (uint32_t)(((lane & 7) + (((lane >> 3) & 1) * 8)) * FSTR
                                     + ((lane >> 4) * 16));

    uint32_t qfh[4][4], qfl[4][4];
#pragma unroll
    for (int ks = 0; ks < 4; ks++) {
        uint32_t rowb = (uint32_t)(wm * FSTR + ks * 32);
        ldmatrix_x4(qfh[ks][0], qfh[ks][1], qfh[ks][2], qfh[ks][3], sb + rowb + aoff);
        ldmatrix_x4(qfl[ks][0], qfl[ks][1], qfl[ks][2], qfl[ks][3], sb + FTILE + rowb + aoff);
    }
    __syncthreads();

    auto load_kv = [&](int st, int j) {
        uint32_t base = sb + st * FSTAGE;
        size_t g0 = (size_t)(j * 64) * HD_;
#pragma unroll
        for (int i = 0; i < 4; i++) {
            uint32_t so = lr[i] * FSTR + ls * 16;
            size_t go = g0 + (size_t)lr[i] * HD_ + ls * 8;
            cp_async16(base + so, khp + go);
            cp_async16(base + FTILE + so, klp + go);
            cp_async16(base + 2 * FTILE + so, vhp + go);
        }
        cp_commit();
    };
    load_kv(0, 0);

    float m0 = -1e30f, m1 = -1e30f, l0 = 0.f, l1 = 0.f;
    float o[8][4];
#pragma unroll
    for (int nj = 0; nj < 8; nj++)
#pragma unroll
        for (int e = 0; e < 4; e++) o[nj][e] = 0.f;

    const int r0 = lane >> 2;
    const int tig = lane & 3;
    const int qg0 = q0 + wm + r0;
    const int qg1 = qg0 + 8;

    for (int j = 0; j <= qtile; j++) {
        cp_wait0();
        __syncthreads();
        if (j < qtile) load_kv((j + 1) & 1, j + 1);

        uint32_t base = sb + (j & 1) * FSTAGE;
        uint32_t bKh = base, bKl = base + FTILE;
        uint32_t bVh = base + 2 * FTILE;

        float c[8][4];
#pragma unroll
        for (int nj = 0; nj < 8; nj++)
#pragma unroll
            for (int e = 0; e < 4; e++) c[nj][e] = 0.f;

#pragma unroll
        for (int ks = 0; ks < 4; ks++) {
            uint32_t kf[4][4], lf[4][4];
#pragma unroll
            for (int njp = 0; njp < 4; njp++) {
                uint32_t off = (uint32_t)(njp * 16 * FSTR + ks * 32) + boff;
                ldmatrix_x4(kf[njp][0], kf[njp][1], kf[njp][2], kf[njp][3], bKh + off);
                ldmatrix_x4(lf[njp][0], lf[njp][1], lf[njp][2], lf[njp][3], bKl + off);
            }
#pragma unroll
            for (int njp = 0; njp < 4; njp++) {
                mma_fp16(c[2 * njp],     qfh[ks][0], qfh[ks][1], qfh[ks][2], qfh[ks][3], kf[njp][0], kf[njp][1]);
                mma_fp16(c[2 * njp + 1], qfh[ks][0], qfh[ks][1], qfh[ks][2], qfh[ks][3], kf[njp][2], kf[njp][3]);
                mma_fp16(c[2 * njp],     qfh[ks][0], qfh[ks][1], qfh[ks][2], qfh[ks][3], lf[njp][0], lf[njp][1]);
                mma_fp16(c[2 * njp + 1], qfh[ks][0], qfh[ks][1], qfh[ks][2], qfh[ks][3], lf[njp][2], lf[njp][3]);
                mma_fp16(c[2 * njp],     qfl[ks][0], qfl[ks][1], qfl[ks][2], qfl[ks][3], kf[njp][0], kf[njp][1]);
                mma_fp16(c[2 * njp + 1], qfl[ks][0], qfl[ks][1], qfl[ks][2], qfl[ks][3], kf[njp][2], kf[njp][3]);
            }
        }

        const bool diag = (j == qtile);
        float tm0 = -1e30f, tm1 = -1e30f;
#pragma unroll
        for (int nj = 0; nj < 8; nj++) {
            int colb = j * 64 + nj * 8 + 2 * tig;
#pragma unroll
            for (int e = 0; e < 4; e++) {
                float sv = c[nj][e] * 0.125f;
                if (diag) {
                    int colg = colb + (e & 1);
                    int rowg = (e < 2) ? qg0 : qg1;
                    if (colg > rowg) sv = -1e30f;
                }
                c[nj][e] = sv;
            }
            tm0 = fmaxf(tm0, fmaxf(c[nj][0], c[nj][1]));
            tm1 = fmaxf(tm1, fmaxf(c[nj][2], c[nj][3]));
        }
        tm0 = fmaxf(tm0, __shfl_xor_sync(0xffffffffu, tm0, 1));
        tm0 = fmaxf(tm0, __shfl_xor_sync(0xffffffffu, tm0, 2));
        tm1 = fmaxf(tm1, __shfl_xor_sync(0xffffffffu, tm1, 1));
        tm1 = fmaxf(tm1, __shfl_xor_sync(0xffffffffu, tm1, 2));

        float mn0 = fmaxf(m0, tm0), mn1 = fmaxf(m1, tm1);
        float sc0 = __expf(m0 - mn0), sc1 = __expf(m1 - mn1);
        m0 = mn0; m1 = mn1;

        float sum0 = 0.f, sum1 = 0.f;
#pragma unroll
        for (int nj = 0; nj < 8; nj++) {
            c[nj][0] = __expf(c[nj][0] - mn0);
            c[nj][1] = __expf(c[nj][1] - mn0);
            c[nj][2] = __expf(c[nj][2] - mn1);
            c[nj][3] = __expf(c[nj][3] - mn1);
            sum0 += c[nj][0] + c[nj][1];
            sum1 += c[nj][2] + c[nj][3];
        }
        sum0 += __shfl_xor_sync(0xffffffffu, sum0, 1);
        sum0 += __shfl_xor_sync(0xffffffffu, sum0, 2);
        sum1 += __shfl_xor_sync(0xffffffffu, sum1, 1);
        sum1 += __shfl_xor_sync(0xffffffffu, sum1, 2);
        l0 = l0 * sc0 + sum0;
        l1 = l1 * sc1 + sum1;

#pragma unroll
        for (int nj = 0; nj < 8; nj++) {
            o[nj][0] *= sc0; o[nj][1] *= sc0;
            o[nj][2] *= sc1; o[nj][3] *= sc1;
        }

        // ---- PV: single-term fp16 ----
#pragma unroll
        for (int ksv = 0; ksv < 4; ksv++) {
            uint32_t ap[4];
            ap[0] = pack_h2(c[2 * ksv][0], c[2 * ksv][1]);
            ap[1] = pack_h2(c[2 * ksv][2], c[2 * ksv][3]);
            ap[2] = pack_h2(c[2 * ksv + 1][0], c[2 * ksv + 1][1]);
            ap[3] = pack_h2(c[2 * ksv + 1][2], c[2 * ksv + 1][3]);
#pragma unroll
            for (int njp = 0; njp < 4; njp++) {
                uint32_t off = (uint32_t)(ksv * 16 * FSTR + njp * 32) + voff;
                uint32_t v0, v1, v2, v3;
                ldmatrix_x4_trans(v0, v1, v2, v3, bVh + off);
                mma_fp16(o[2 * njp],     ap[0], ap[1], ap[2], ap[3], v0, v1);
                mma_fp16(o[2 * njp + 1], ap[0], ap[1], ap[2], ap[3], v2, v3);
            }
        }
    }

    float inv0 = 1.f / l0, inv1 = 1.f / l1;
    size_t gr0 = (size_t)(b * S_ + q0 + wm + r0) * DIM_ + h * HD_ + 2 * tig;
    size_t gr1 = gr0 + (size_t)8 * DIM_;
#pragma unroll
    for (int nj = 0; nj < 8; nj++) {
        *(uint32_t*)(Oh + gr0 + nj * 8) = pack_h2(o[nj][0] * inv0, o[nj][1] * inv0);
        *(uint32_t*)(Oh + gr1 + nj * 8) = pack_h2(o[nj][2] * inv1, o[nj][3] * inv1);
    }
}

// ============================================================================
// launch
// ============================================================================
extern "C" void kernel_launch(void* const* d_in, const int* in_sizes, int n_in,
                              void* d_out, int out_size)
{
    const float* x    = (const float*)d_in[0];
    const float* fc   = (const float*)d_in[1];
    const float* wqkv = (const float*)d_in[2];
    const float* wo   = (const float*)d_in[3];
    float* out        = (float*)d_out;

    void *xh_p, *xl_p, *wqh_p, *wql_p, *woh_p, *ah_p;
    void *qh_p, *ql_p, *kh_p, *kl_p, *vh_p;
    cudaGetSymbolAddress(&xh_p, g_x_hi);
    cudaGetSymbolAddress(&xl_p, g_x_lo);
    cudaGetSymbolAddress(&wqh_p, g_wqkvT_hi);
    cudaGetSymbolAddress(&wql_p, g_wqkvT_lo);
    cudaGetSymbolAddress(&woh_p, g_woT_hi);
    cudaGetSymbolAddress(&ah_p, g_att_hi);
    cudaGetSymbolAddress(&qh_p, g_q_hi);
    cudaGetSymbolAddress(&ql_p, g_q_lo);
    cudaGetSymbolAddress(&kh_p, g_k_hi);
    cudaGetSymbolAddress(&kl_p, g_k_lo);
    cudaGetSymbolAddress(&vh_p, g_v_hi);

    cudaFuncSetAttribute(tc_gemm3_kernel<0>, cudaFuncAttributeMaxDynamicSharedMemorySize,
                         GSMEM_TOTAL);
    cudaFuncSetAttribute(tc_gemm3_kernel<1>, cudaFuncAttributeMaxDynamicSharedMemorySize,
                         GSMEM_TOTAL);
    cudaFuncSetAttribute(tc_gemm1_kernel, cudaFuncAttributeMaxDynamicSharedMemorySize,
                         G1SMEM);
    cudaFuncSetAttribute(flash_tc_kernel, cudaFuncAttributeMaxDynamicSharedMemorySize,
                         FSMEM);

    // 1) split x -> fp16 hi/lo
    {
        int n4 = M_ * DIM_ / 4;
        conv_split_kernel<<<(n4 + 255) / 256, 256>>>(
            x, (__half*)xh_p, (__half*)xl_p, n4);
    }
    // 2) transpose + split weights
    conv_transpose_kernel<1><<<dim3(QKVN / 32, KDIM / 32), 256>>>(
        wqkv, (__half*)wqh_p, (__half*)wql_p, KDIM, QKVN);
    conv_transpose_kernel<0><<<dim3(DIM_ / 32, KDIM / 32), 256>>>(
        wo, (__half*)woh_p, nullptr, KDIM, DIM_);

    // 3) qkv projection (3-term) + fused rope/split epilogue
    tc_gemm3_kernel<1><<<dim3(QKVN / GBN, M_ / GBM), 128, GSMEM_TOTAL>>>(
        (const __half*)xh_p, (const __half*)xl_p,
        (const __half*)wqh_p, (const __half*)wql_p,
        nullptr, fc,
        (__half*)qh_p, (__half*)ql_p,
        (__half*)kh_p, (__half*)kl_p,
        (__half*)vh_p,
        QKVN, KDIM);

    // 4) flash attention (QK 3-term, PV 1-term) -> att fp16
    flash_tc_kernel<<<dim3(S_ / 64, NH_, B_), 128, FSMEM>>>(
        (const __half*)qh_p, (const __half*)ql_p,
        (const __half*)kh_p, (const __half*)kl_p,
        (const __half*)vh_p,
        (__half*)ah_p);

    // 5) out = att @ wo (1-term fp16)
    tc_gemm1_kernel<<<dim3(DIM_ / GBN, M_ / GBM), 128, G1SMEM>>>(
        (const __half*)ah_p, (const __half*)woh_p, out, DIM_, KDIM);
}

// round 9
// speedup vs baseline: 5.8638x; 1.2377x over previous
#include <cuda_runtime.h>
#include <cuda_fp16.h>
#include <cstdint>

// ---------------- problem constants ----------------
#define B_   2
#define S_   2048
#define DIM_ 2048
#define NH_  32
#define NKV_ 8
#define HD_  64
#define QKVN 3072
#define M_   (B_ * S_)
#define KDIM 2048

// ---------------- scratch (fp16) ----------------
__device__ __half g_x_hi[(size_t)M_ * DIM_];
__device__ __half g_x_lo[(size_t)M_ * DIM_];
__device__ __half g_wqkvT_hi[(size_t)QKVN * DIM_];
__device__ __half g_woT_hi[(size_t)DIM_ * DIM_];
__device__ __half g_att_hi[(size_t)M_ * DIM_];
__device__ __half g_q_hi[(size_t)B_ * NH_ * S_ * HD_];
__device__ __half g_q_lo[(size_t)B_ * NH_ * S_ * HD_];
__device__ __half g_k_hi[(size_t)B_ * NKV_ * S_ * HD_];
__device__ __half g_k_lo[(size_t)B_ * NKV_ * S_ * HD_];
__device__ __half g_v_hi[(size_t)B_ * NKV_ * S_ * HD_];

// ============================================================================
// helpers (sm_80-compatible only)
// ============================================================================
__device__ __forceinline__ uint32_t smem_u32(const void* p) {
    uint32_t a;
    asm("{ .reg .u64 t; cvta.to.shared.u64 t, %1; cvt.u32.u64 %0, t; }"
        : "=r"(a) : "l"(p));
    return a;
}
__device__ __forceinline__ void cp_async16(uint32_t s, const void* g) {
    asm volatile("cp.async.cg.shared.global [%0], [%1], 16;" :: "r"(s), "l"(g));
}
__device__ __forceinline__ void cp_commit() {
    asm volatile("cp.async.commit_group;" ::: "memory");
}
__device__ __forceinline__ void cp_wait0() {
    asm volatile("cp.async.wait_group 0;" ::: "memory");
}
__device__ __forceinline__ void ldmatrix_x4(uint32_t& r0, uint32_t& r1,
                                            uint32_t& r2, uint32_t& r3, uint32_t a) {
    asm volatile("ldmatrix.sync.aligned.m8n8.x4.shared.b16 {%0,%1,%2,%3}, [%4];"
                 : "=r"(r0), "=r"(r1), "=r"(r2), "=r"(r3) : "r"(a));
}
__device__ __forceinline__ void ldmatrix_x4_trans(uint32_t& r0, uint32_t& r1,
                                                  uint32_t& r2, uint32_t& r3, uint32_t a) {
    asm volatile("ldmatrix.sync.aligned.m8n8.x4.trans.shared.b16 {%0,%1,%2,%3}, [%4];"
                 : "=r"(r0), "=r"(r1), "=r"(r2), "=r"(r3) : "r"(a));
}
__device__ __forceinline__ void mma_fp16(float* c, uint32_t a0, uint32_t a1,
                                         uint32_t a2, uint32_t a3,
                                         uint32_t b0, uint32_t b1) {
    asm volatile(
        "mma.sync.aligned.m16n8k16.row.col.f32.f16.f16.f32 "
        "{%0,%1,%2,%3}, {%4,%5,%6,%7}, {%8,%9}, {%0,%1,%2,%3};"
        : "+f"(c[0]), "+f"(c[1]), "+f"(c[2]), "+f"(c[3])
        : "r"(a0), "r"(a1), "r"(a2), "r"(a3), "r"(b0), "r"(b1));
}
__device__ __forceinline__ uint32_t pack_h2(float a, float b) {
    __half2 t = __floats2half2_rn(a, b);
    return *(uint32_t*)&t;
}
__device__ __forceinline__ uint32_t pack_h2_lo(float a, float b) {
    float ah = __half2float(__float2half_rn(a));
    float bh = __half2float(__float2half_rn(b));
    __half2 t = __floats2half2_rn(a - ah, b - bh);
    return *(uint32_t*)&t;
}

// ============================================================================
// tc_gemm2: 2-term fp16 GEMM: C = (Ah+Al) @ Bh^T. CTA 128x128, 4 warps
// (64x64 warp tiles), BK=32, 2-stage cp.async (3 tiles/stage).
// Fused epilogue: rope + Q/K hi/lo + V hi (qkv projection).
// ============================================================================
#define GBM 128
#define GBN 128
#define GBK 32
#define GSTRIDE 80
#define GTILE (GBM * GSTRIDE)
#define G2STAGE (3 * GTILE)
#define G2SMEM (2 * G2STAGE)

__global__ __launch_bounds__(128) void tc_gemm2_kernel(
    const __half* __restrict__ Ah, const __half* __restrict__ Al,
    const __half* __restrict__ Bh,
    const float* __restrict__ fc,
    __half* __restrict__ Qh, __half* __restrict__ Ql,
    __half* __restrict__ Kh, __half* __restrict__ Kl,
    __half* __restrict__ Vh,
    int N, int K)
{
    extern __shared__ char smem[];
    const uint32_t sb = smem_u32(smem);
    const int tid = threadIdx.x;
    const int wid = tid >> 5;
    const int lane = tid & 31;
    const int mb = blockIdx.y * GBM;
    const int nb = blockIdx.x * GBN;
    const int wm = (wid >> 1) * 64;
    const int wn = (wid & 1) * 64;

    auto load_stage = [&](int stage, int k0) {
        uint32_t base = sb + stage * G2STAGE;
        uint32_t sAh = base, sAl = base + GTILE, sB = base + 2 * GTILE;
#pragma unroll
        for (int i = 0; i < 4; i++) {
            int slot = i * 128 + tid;
            int r = slot >> 2, sg = slot & 3;
            cp_async16(sAh + r * GSTRIDE + sg * 16, Ah + (size_t)(mb + r) * K + k0 + sg * 8);
            cp_async16(sAl + r * GSTRIDE + sg * 16, Al + (size_t)(mb + r) * K + k0 + sg * 8);
            cp_async16(sB + r * GSTRIDE + sg * 16, Bh + (size_t)(nb + r) * K + k0 + sg * 8);
        }
        cp_commit();
    };

    float acc[4][8][4];
#pragma unroll
    for (int i = 0; i < 4; i++)
#pragma unroll
        for (int j = 0; j < 8; j++)
#pragma unroll
            for (int e = 0; e < 4; e++) acc[i][j][e] = 0.f;

    const uint32_t aoff = (uint32_t)((lane & 15) * GSTRIDE + (lane >> 4) * 16);
    const uint32_t boff = (uint32_t)(((lane & 7) + ((lane >> 4) * 8)) * GSTRIDE
                                     + (((lane >> 3) & 1) * 16));

    load_stage(0, 0);
    const int niter = K / GBK;
    for (int it = 0; it < niter; it++) {
        cp_wait0();
        __syncthreads();
        if (it + 1 < niter) load_stage((it + 1) & 1, (it + 1) * GBK);

        uint32_t base = sb + (it & 1) * G2STAGE;
        uint32_t bAh = base, bAl = base + GTILE, bB = base + 2 * GTILE;

#pragma unroll
        for (int ks = 0; ks < 2; ks++) {
            uint32_t kb = (uint32_t)(ks * 32);
            uint32_t ah[4][4], al[4][4];
#pragma unroll
            for (int mi = 0; mi < 4; mi++) {
                uint32_t rowb = (uint32_t)((wm + mi * 16) * GSTRIDE) + kb;
                ldmatrix_x4(ah[mi][0], ah[mi][1], ah[mi][2], ah[mi][3], bAh + rowb + aoff);
                ldmatrix_x4(al[mi][0], al[mi][1], al[mi][2], al[mi][3], bAl + rowb + aoff);
            }
            uint32_t bf[8][2];
#pragma unroll
            for (int nj = 0; nj < 4; nj++) {
                uint32_t rowb = (uint32_t)((wn + nj * 16) * GSTRIDE) + kb;
                uint32_t t0, t1, t2, t3;
                ldmatrix_x4(t0, t1, t2, t3, bB + rowb + boff);
                bf[nj * 2][0] = t0; bf[nj * 2][1] = t1;
                bf[nj * 2 + 1][0] = t2; bf[nj * 2 + 1][1] = t3;
            }
#pragma unroll
            for (int mi = 0; mi < 4; mi++)
#pragma unroll
                for (int nj = 0; nj < 8; nj++) {
                    mma_fp16(acc[mi][nj], ah[mi][0], ah[mi][1], ah[mi][2], ah[mi][3],
                             bf[nj][0], bf[nj][1]);
                    mma_fp16(acc[mi][nj], al[mi][0], al[mi][1], al[mi][2], al[mi][3],
                             bf[nj][0], bf[nj][1]);
                }
        }
        __syncthreads();
    }

    const int g = lane >> 2, c = lane & 3;
#pragma unroll
    for (int mi = 0; mi < 4; mi++) {
#pragma unroll
        for (int nj = 0; nj < 8; nj++) {
            const int col = nb + wn + nj * 8 + 2 * c;
#pragma unroll
            for (int rr = 0; rr < 2; rr++) {
                const int row = mb + wm + mi * 16 + g + rr * 8;
                float v0 = acc[mi][nj][rr * 2 + 0];
                float v1 = acc[mi][nj][rr * 2 + 1];
                const int b = row >> 11, s = row & (S_ - 1);
                const int d = col & 63;
                if (col < DIM_ + NKV_ * HD_) {
                    float2 f = *(const float2*)(fc + (size_t)s * HD_ + d);
                    float rx = v0 * f.x - v1 * f.y;
                    float ry = v1 * f.x + v0 * f.y;
                    v0 = rx; v1 = ry;
                }
                if (col < DIM_) {
                    int h = col >> 6;
                    size_t o = ((size_t)(b * NH_ + h) * S_ + s) * HD_ + d;
                    *(uint32_t*)(Qh + o) = pack_h2(v0, v1);
                    *(uint32_t*)(Ql + o) = pack_h2_lo(v0, v1);
                } else if (col < DIM_ + NKV_ * HD_) {
                    int kvh = (col - DIM_) >> 6;
                    size_t o = ((size_t)(b * NKV_ + kvh) * S_ + s) * HD_ + d;
                    *(uint32_t*)(Kh + o) = pack_h2(v0, v1);
                    *(uint32_t*)(Kl + o) = pack_h2_lo(v0, v1);
                } else {
                    int kvh = (col - DIM_ - NKV_ * HD_) >> 6;
                    size_t o = ((size_t)(b * NKV_ + kvh) * S_ + s) * HD_ + d;
                    *(uint32_t*)(Vh + o) = pack_h2(v0, v1);
                }
            }
        }
    }
}

// ============================================================================
// tc_gemm1: single-term fp16 GEMM (out = att @ woT^T). CTA 128x128, 4 warps.
// ============================================================================
#define G1STAGE (2 * GTILE)
#define G1SMEM (2 * G1STAGE)

__global__ __launch_bounds__(128) void tc_gemm1_kernel(
    const __half* __restrict__ A, const __half* __restrict__ B,
    float* __restrict__ C, int N, int K)
{
    extern __shared__ char smem[];
    const uint32_t sb = smem_u32(smem);
    const int tid = threadIdx.x;
    const int wid = tid >> 5;
    const int lane = tid & 31;
    const int mb = blockIdx.y * GBM;
    const int nb = blockIdx.x * GBN;
    const int wm = (wid >> 1) * 64;
    const int wn = (wid & 1) * 64;

    auto load_stage = [&](int stage, int k0) {
        uint32_t base = sb + stage * G1STAGE;
        uint32_t sA = base, sB = base + GTILE;
#pragma unroll
        for (int i = 0; i < 4; i++) {
            int slot = i * 128 + tid;
            int r = slot >> 2, sg = slot & 3;
            cp_async16(sA + r * GSTRIDE + sg * 16, A + (size_t)(mb + r) * K + k0 + sg * 8);
            cp_async16(sB + r * GSTRIDE + sg * 16, B + (size_t)(nb + r) * K + k0 + sg * 8);
        }
        cp_commit();
    };

    float acc[4][8][4];
#pragma unroll
    for (int i = 0; i < 4; i++)
#pragma unroll
        for (int j = 0; j < 8; j++)
#pragma unroll
            for (int e = 0; e < 4; e++) acc[i][j][e] = 0.f;

    const uint32_t aoff = (uint32_t)((lane & 15) * GSTRIDE + (lane >> 4) * 16);
    const uint32_t boff = (uint32_t)(((lane & 7) + ((lane >> 4) * 8)) * GSTRIDE
                                     + (((lane >> 3) & 1) * 16));

    load_stage(0, 0);
    const int niter = K / GBK;
    for (int it = 0; it < niter; it++) {
        cp_wait0();
        __syncthreads();
        if (it + 1 < niter) load_stage((it + 1) & 1, (it + 1) * GBK);

        uint32_t base = sb + (it & 1) * G1STAGE;
        uint32_t bA = base, bB = base + GTILE;

#pragma unroll
        for (int ks = 0; ks < 2; ks++) {
            uint32_t kb = (uint32_t)(ks * 32);
            uint32_t af[4][4];
#pragma unroll
            for (int mi = 0; mi < 4; mi++) {
                uint32_t rowb = (uint32_t)((wm + mi * 16) * GSTRIDE) + kb;
                ldmatrix_x4(af[mi][0], af[mi][1], af[mi][2], af[mi][3], bA + rowb + aoff);
            }
            uint32_t bf[8][2];
#pragma unroll
            for (int nj = 0; nj < 4; nj++) {
                uint32_t rowb = (uint32_t)((wn + nj * 16) * GSTRIDE) + kb;
                uint32_t t0, t1, t2, t3;
                ldmatrix_x4(t0, t1, t2, t3, bB + rowb + boff);
                bf[nj * 2][0] = t0; bf[nj * 2][1] = t1;
                bf[nj * 2 + 1][0] = t2; bf[nj * 2 + 1][1] = t3;
            }
#pragma unroll
            for (int mi = 0; mi < 4; mi++)
#pragma unroll
                for (int nj = 0; nj < 8; nj++)
                    mma_fp16(acc[mi][nj], af[mi][0], af[mi][1], af[mi][2], af[mi][3],
                             bf[nj][0], bf[nj][1]);
        }
        __syncthreads();
    }

    const int g = lane >> 2, c = lane & 3;
#pragma unroll
    for (int mi = 0; mi < 4; mi++) {
#pragma unroll
        for (int nj = 0; nj < 8; nj++) {
            float* cp0 = C + (size_t)(mb + wm + mi * 16 + g) * N + nb + wn + nj * 8 + 2 * c;
            float* cp1 = cp0 + (size_t)8 * N;
            *(float2*)cp0 = make_float2(acc[mi][nj][0], acc[mi][nj][1]);
            *(float2*)cp1 = make_float2(acc[mi][nj][2], acc[mi][nj][3]);
        }
    }
}

// ============================================================================
// conversion kernels (fp16)
// ============================================================================
__global__ __launch_bounds__(256) void conv_split_kernel(
    const float* __restrict__ A, __half* __restrict__ H,
    __half* __restrict__ L, int n4)
{
    int i = blockIdx.x * blockDim.x + threadIdx.x;
    if (i >= n4) return;
    float4 v = *(const float4*)(A + (size_t)i * 4);
    float vv[4] = {v.x, v.y, v.z, v.w};
    __half h[4], l[4];
#pragma unroll
    for (int j = 0; j < 4; j++) {
        h[j] = __float2half_rn(vv[j]);
        l[j] = __float2half_rn(vv[j] - __half2float(h[j]));
    }
    *(uint2*)(H + (size_t)i * 4) = *(uint2*)h;
    *(uint2*)(L + (size_t)i * 4) = *(uint2*)l;
}

// W [K][N] fp32 -> Wt hi [N][K] fp16
__global__ __launch_bounds__(256) void conv_transpose_kernel(
    const float* __restrict__ W, __half* __restrict__ Th, int K, int N)
{
    __shared__ float t[32][33];
    const int k0 = blockIdx.y * 32, n0 = blockIdx.x * 32;
    const int tx = threadIdx.x & 31, ty = threadIdx.x >> 5;
#pragma unroll
    for (int i = 0; i < 32; i += 8)
        t[ty + i][tx] = W[(size_t)(k0 + ty + i) * N + n0 + tx];
    __syncthreads();
#pragma unroll
    for (int i = 0; i < 32; i += 8) {
        float v = t[tx][ty + i];
        Th[(size_t)(n0 + ty + i) * K + k0 + tx] = __float2half_rn(v);
    }
}

// ============================================================================
// Flash attention: QK^T 3-term fp16, PV 1-term fp16, att out fp16.
// ============================================================================
#define FSTR 144
#define FTILE (64 * FSTR)
#define FSTAGE (3 * FTILE)       // Kh, Kl, Vh
#define FSMEM (2 * FSTAGE)

__global__ __launch_bounds__(128) void flash_tc_kernel(
    const __half* __restrict__ Qh, const __half* __restrict__ Ql,
    const __half* __restrict__ Kh, const __half* __restrict__ Kl,
    const __half* __restrict__ Vh,
    __half* __restrict__ Oh)
{
    extern __shared__ char smem[];
    const uint32_t sb = smem_u32(smem);
    const int tid  = threadIdx.x;
    const int wid  = tid >> 5;
    const int lane = tid & 31;
    const int qtile = blockIdx.x;
    const int h     = blockIdx.y;
    const int b     = blockIdx.z;
    const int kvh   = h >> 2;
    const int q0    = qtile * 64;
    const int wm    = wid * 16;

    const __half* qhp = Qh + ((size_t)(b * NH_ + h) * S_ + q0) * HD_;
    const __half* qlp = Ql + ((size_t)(b * NH_ + h) * S_ + q0) * HD_;
    const __half* khp = Kh + ((size_t)(b * NKV_ + kvh) * S_) * HD_;
    const __half* klp = Kl + ((size_t)(b * NKV_ + kvh) * S_) * HD_;
    const __half* vhp = Vh + ((size_t)(b * NKV_ + kvh) * S_) * HD_;

    const int lr[4] = {(tid) >> 3, (tid + 128) >> 3, (tid + 256) >> 3, (tid + 384) >> 3};
    const int ls = tid & 7;

#pragma unroll
    for (int i = 0; i < 4; i++) {
        cp_async16(sb + lr[i] * FSTR + ls * 16, qhp + (size_t)lr[i] * HD_ + ls * 8);
        cp_async16(sb + FTILE + lr[i] * FSTR + ls * 16, qlp + (size_t)lr[i] * HD_ + ls * 8);
    }
    cp_commit();
    cp_wait0();
    __syncthreads();

    const uint32_t aoff = (uint32_t)((lane & 15) * FSTR + (lane >> 4) * 16);
    const uint32_t boff = (uint32_t)(((lane & 7) + ((lane >> 4) * 8)) * FSTR
                                     + (((lane >> 3) & 1) * 16));
    const uint32_t voff = (uint32_t)(((lane & 7) + (((lane >> 3) & 1) * 8)) * FSTR
                                     + ((lane >> 4) * 16));

    uint32_t qfh[4][4], qfl[4][4];
#pragma unroll
    for (int ks = 0; ks < 4; ks++) {
        uint32_t rowb = (uint32_t)(wm * FSTR + ks * 32);
        ldmatrix_x4(qfh[ks][0], qfh[ks][1], qfh[ks][2], qfh[ks][3], sb + rowb + aoff);
        ldmatrix_x4(qfl[ks][0], qfl[ks][1], qfl[ks][2], qfl[ks][3], sb + FTILE + rowb + aoff);
    }
    __syncthreads();

    auto load_kv = [&](int st, int j) {
        uint32_t base = sb + st * FSTAGE;
        size_t g0 = (size_t)(j * 64) * HD_;
#pragma unroll
        for (int i = 0; i < 4; i++) {
            uint32_t so = lr[i] * FSTR + ls * 16;
            size_t go = g0 + (size_t)lr[i] * HD_ + ls * 8;
            cp_async16(base + so, khp + go);
            cp_async16(base + FTILE + so, klp + go);
            cp_async16(base + 2 * FTILE + so, vhp + go);
        }
        cp_commit();
    };
    load_kv(0, 0);

    float m0 = -1e30f, m1 = -1e30f, l0 = 0.f, l1 = 0.f;
    float o[8][4];
#pragma unroll
    for (int nj = 0; nj < 8; nj++)
#pragma unroll
        for (int e = 0; e < 4; e++) o[nj][e] = 0.f;

    const int r0 = lane >> 2;
    const int tig = lane & 3;
    const int qg0 = q0 + wm + r0;
    const int qg1 = qg0 + 8;

    for (int j = 0; j <= qtile; j++) {
        cp_wait0();
        __syncthreads();
        if (j < qtile) load_kv((j + 1) & 1, j + 1);

        uint32_t base = sb + (j & 1) * FSTAGE;
        uint32_t bKh = base, bKl = base + FTILE;
        uint32_t bVh = base + 2 * FTILE;

        float c[8][4];
#pragma unroll
        for (int nj = 0; nj < 8; nj++)
#pragma unroll
            for (int e = 0; e < 4; e++) c[nj][e] = 0.f;

#pragma unroll
        for (int ks = 0; ks < 4; ks++) {
            uint32_t kf[4][4], lf[4][4];
#pragma unroll
            for (int njp = 0; njp < 4; njp++) {
                uint32_t off = (uint32_t)(njp * 16 * FSTR + ks * 32) + boff;
                ldmatrix_x4(kf[njp][0], kf[njp][1], kf[njp][2], kf[njp][3], bKh + off);
                ldmatrix_x4(lf[njp][0], lf[njp][1], lf[njp][2], lf[njp][3], bKl + off);
            }
#pragma unroll
            for (int njp = 0; njp < 4; njp++) {
                mma_fp16(c[2 * njp],     qfh[ks][0], qfh[ks][1], qfh[ks][2], qfh[ks][3], kf[njp][0], kf[njp][1]);
                mma_fp16(c[2 * njp + 1], qfh[ks][0], qfh[ks][1], qfh[ks][2], qfh[ks][3], kf[njp][2], kf[njp][3]);
                mma_fp16(c[2 * njp],     qfh[ks][0], qfh[ks][1], qfh[ks][2], qfh[ks][3], lf[njp][0], lf[njp][1]);
                mma_fp16(c[2 * njp + 1], qfh[ks][0], qfh[ks][1], qfh[ks][2], qfh[ks][3], lf[njp][2], lf[njp][3]);
                mma_fp16(c[2 * njp],     qfl[ks][0], qfl[ks][1], qfl[ks][2], qfl[ks][3], kf[njp][0], kf[njp][1]);
                mma_fp16(c[2 * njp + 1], qfl[ks][0], qfl[ks][1], qfl[ks][2], qfl[ks][3], kf[njp][2], kf[njp][3]);
            }
        }

        const bool diag = (j == qtile);
        float tm0 = -1e30f, tm1 = -1e30f;
#pragma unroll
        for (int nj = 0; nj < 8; nj++) {
            int colb = j * 64 + nj * 8 + 2 * tig;
#pragma unroll
            for (int e = 0; e < 4; e++) {
                float sv = c[nj][e] * 0.125f;
                if (diag) {
                    int colg = colb + (e & 1);
                    int rowg = (e < 2) ? qg0 : qg1;
                    if (colg > rowg) sv = -1e30f;
                }
                c[nj][e] = sv;
            }
            tm0 = fmaxf(tm0, fmaxf(c[nj][0], c[nj][1]));
            tm1 = fmaxf(tm1, fmaxf(c[nj][2], c[nj][3]));
        }
        tm0 = fmaxf(tm0, __shfl_xor_sync(0xffffffffu, tm0, 1));
        tm0 = fmaxf(tm0, __shfl_xor_sync(0xffffffffu, tm0, 2));
        tm1 = fmaxf(tm1, __shfl_xor_sync(0xffffffffu, tm1, 1));
        tm1 = fmaxf(tm1, __shfl_xor_sync(0xffffffffu, tm1, 2));

        float mn0 = fmaxf(m0, tm0), mn1 = fmaxf(m1, tm1);
        float sc0 = __expf(m0 - mn0), sc1 = __expf(m1 - mn1);
        m0 = mn0; m1 = mn1;

        float sum0 = 0.f, sum1 = 0.f;
#pragma unroll
        for (int nj = 0; nj < 8; nj++) {
            c[nj][0] = __expf(c[nj][0] - mn0);
            c[nj][1] = __expf(c[nj][1] - mn0);
            c[nj][2] = __expf(c[nj][2] - mn1);
            c[nj][3] = __expf(c[nj][3] - mn1);
            sum0 += c[nj][0] + c[nj][1];
            sum1 += c[nj][2] + c[nj][3];
        }
        sum0 += __shfl_xor_sync(0xffffffffu, sum0, 1);
        sum0 += __shfl_xor_sync(0xffffffffu, sum0, 2);
        sum1 += __shfl_xor_sync(0xffffffffu, sum1, 1);
        sum1 += __shfl_xor_sync(0xffffffffu, sum1, 2);
        l0 = l0 * sc0 + sum0;
        l1 = l1 * sc1 + sum1;

#pragma unroll
        for (int nj = 0; nj < 8; nj++) {
            o[nj][0] *= sc0; o[nj][1] *= sc0;
            o[nj][2] *= sc1; o[nj][3] *= sc1;
        }

#pragma unroll
        for (int ksv = 0; ksv < 4; ksv++) {
            uint32_t ap[4];
            ap[0] = pack_h2(c[2 * ksv][0], c[2 * ksv][1]);
            ap[1] = pack_h2(c[2 * ksv][2], c[2 * ksv][3]);
            ap[2] = pack_h2(c[2 * ksv + 1][0], c[2 * ksv + 1][1]);
            ap[3] = pack_h2(c[2 * ksv + 1][2], c[2 * ksv + 1][3]);
#pragma unroll
            for (int njp = 0; njp < 4; njp++) {
                uint32_t off = (uint32_t)(ksv * 16 * FSTR + njp * 32) + voff;
                uint32_t v0, v1, v2, v3;
                ldmatrix_x4_trans(v0, v1, v2, v3, bVh + off);
                mma_fp16(o[2 * njp],     ap[0], ap[1], ap[2], ap[3], v0, v1);
                mma_fp16(o[2 * njp + 1], ap[0], ap[1], ap[2], ap[3], v2, v3);
            }
        }
    }

    float inv0 = 1.f / l0, inv1 = 1.f / l1;
    size_t gr0 = (size_t)(b * S_ + q0 + wm + r0) * DIM_ + h * HD_ + 2 * tig;
    size_t gr1 = gr0 + (size_t)8 * DIM_;
#pragma unroll
    for (int nj = 0; nj < 8; nj++) {
        *(uint32_t*)(Oh + gr0 + nj * 8) = pack_h2(o[nj][0] * inv0, o[nj][1] * inv0);
        *(uint32_t*)(Oh + gr1 + nj * 8) = pack_h2(o[nj][2] * inv1, o[nj][3] * inv1);
    }
}

// ============================================================================
// launch
// ============================================================================
extern "C" void kernel_launch(void* const* d_in, const int* in_sizes, int n_in,
                              void* d_out, int out_size)
{
    const float* x    = (const float*)d_in[0];
    const float* fc   = (const float*)d_in[1];
    const float* wqkv = (const float*)d_in[2];
    const float* wo   = (const float*)d_in[3];
    float* out        = (float*)d_out;

    void *xh_p, *xl_p, *wqh_p, *woh_p, *ah_p;
    void *qh_p, *ql_p, *kh_p, *kl_p, *vh_p;
    cudaGetSymbolAddress(&xh_p, g_x_hi);
    cudaGetSymbolAddress(&xl_p, g_x_lo);
    cudaGetSymbolAddress(&wqh_p, g_wqkvT_hi);
    cudaGetSymbolAddress(&woh_p, g_woT_hi);
    cudaGetSymbolAddress(&ah_p, g_att_hi);
    cudaGetSymbolAddress(&qh_p, g_q_hi);
    cudaGetSymbolAddress(&ql_p, g_q_lo);
    cudaGetSymbolAddress(&kh_p, g_k_hi);
    cudaGetSymbolAddress(&kl_p, g_k_lo);
    cudaGetSymbolAddress(&vh_p, g_v_hi);

    cudaFuncSetAttribute(tc_gemm2_kernel, cudaFuncAttributeMaxDynamicSharedMemorySize,
                         G2SMEM);
    cudaFuncSetAttribute(tc_gemm1_kernel, cudaFuncAttributeMaxDynamicSharedMemorySize,
                         G1SMEM);
    cudaFuncSetAttribute(flash_tc_kernel, cudaFuncAttributeMaxDynamicSharedMemorySize,
                         FSMEM);

    // 1) split x -> fp16 hi/lo
    {
        int n4 = M_ * DIM_ / 4;
        conv_split_kernel<<<(n4 + 255) / 256, 256>>>(
            x, (__half*)xh_p, (__half*)xl_p, n4);
    }
    // 2) transpose weights (hi only)
    conv_transpose_kernel<<<dim3(QKVN / 32, KDIM / 32), 256>>>(
        wqkv, (__half*)wqh_p, KDIM, QKVN);
    conv_transpose_kernel<<<dim3(DIM_ / 32, KDIM / 32), 256>>>(
        wo, (__half*)woh_p, KDIM, DIM_);

    // 3) qkv projection (2-term: (xh+xl)·wh) + fused rope/split epilogue
    tc_gemm2_kernel<<<dim3(QKVN / GBN, M_ / GBM), 128, G2SMEM>>>(
        (const __half*)xh_p, (const __half*)xl_p,
        (const __half*)wqh_p, fc,
        (__half*)qh_p, (__half*)ql_p,
        (__half*)kh_p, (__half*)kl_p,
        (__half*)vh_p,
        QKVN, KDIM);

    // 4) flash attention (QK 3-term, PV 1-term) -> att fp16
    flash_tc_kernel<<<dim3(S_ / 64, NH_, B_), 128, FSMEM>>>(
        (const __half*)qh_p, (const __half*)ql_p,
        (const __half*)kh_p, (const __half*)kl_p,
        (const __half*)vh_p,
        (__half*)ah_p);

    // 5) out = att @ wo (1-term fp16)
    tc_gemm1_kernel<<<dim3(DIM_ / GBN, M_ / GBM), 128, G1SMEM>>>(
        (const __half*)ah_p, (const __half*)woh_p, out, DIM_, KDIM);
}

// round 10
// speedup vs baseline: 6.6714x; 1.1377x over previous
#include <cuda_runtime.h>
#include <cuda_fp16.h>
#include <cstdint>

// ---------------- problem constants ----------------
#define B_   2
#define S_   2048
#define DIM_ 2048
#define NH_  32
#define NKV_ 8
#define HD_  64
#define QKVN 3072
#define M_   (B_ * S_)
#define KDIM 2048

// ---------------- scratch (fp16) ----------------
__device__ __half g_x_hi[(size_t)M_ * DIM_];
__device__ __half g_x_lo[(size_t)M_ * DIM_];
__device__ __half g_wqkvT_hi[(size_t)QKVN * DIM_];
__device__ __half g_woT_hi[(size_t)DIM_ * DIM_];
__device__ __half g_att_hi[(size_t)M_ * DIM_];
__device__ __half g_q_hi[(size_t)B_ * NH_ * S_ * HD_];
__device__ __half g_k_hi[(size_t)B_ * NKV_ * S_ * HD_];
__device__ __half g_v_hi[(size_t)B_ * NKV_ * S_ * HD_];

// ============================================================================
// helpers (sm_80-compatible only)
// ============================================================================
__device__ __forceinline__ uint32_t smem_u32(const void* p) {
    uint32_t a;
    asm("{ .reg .u64 t; cvta.to.shared.u64 t, %1; cvt.u32.u64 %0, t; }"
        : "=r"(a) : "l"(p));
    return a;
}
__device__ __forceinline__ void cp_async16(uint32_t s, const void* g) {
    asm volatile("cp.async.cg.shared.global [%0], [%1], 16;" :: "r"(s), "l"(g));
}
__device__ __forceinline__ void cp_commit() {
    asm volatile("cp.async.commit_group;" ::: "memory");
}
__device__ __forceinline__ void cp_wait0() {
    asm volatile("cp.async.wait_group 0;" ::: "memory");
}
__device__ __forceinline__ void ldmatrix_x4(uint32_t& r0, uint32_t& r1,
                                            uint32_t& r2, uint32_t& r3, uint32_t a) {
    asm volatile("ldmatrix.sync.aligned.m8n8.x4.shared.b16 {%0,%1,%2,%3}, [%4];"
                 : "=r"(r0), "=r"(r1), "=r"(r2), "=r"(r3) : "r"(a));
}
__device__ __forceinline__ void ldmatrix_x4_trans(uint32_t& r0, uint32_t& r1,
                                                  uint32_t& r2, uint32_t& r3, uint32_t a) {
    asm volatile("ldmatrix.sync.aligned.m8n8.x4.trans.shared.b16 {%0,%1,%2,%3}, [%4];"
                 : "=r"(r0), "=r"(r1), "=r"(r2), "=r"(r3) : "r"(a));
}
__device__ __forceinline__ void mma_fp16(float* c, uint32_t a0, uint32_t a1,
                                         uint32_t a2, uint32_t a3,
                                         uint32_t b0, uint32_t b1) {
    asm volatile(
        "mma.sync.aligned.m16n8k16.row.col.f32.f16.f16.f32 "
        "{%0,%1,%2,%3}, {%4,%5,%6,%7}, {%8,%9}, {%0,%1,%2,%3};"
        : "+f"(c[0]), "+f"(c[1]), "+f"(c[2]), "+f"(c[3])
        : "r"(a0), "r"(a1), "r"(a2), "r"(a3), "r"(b0), "r"(b1));
}
__device__ __forceinline__ uint32_t pack_h2(float a, float b) {
    __half2 t = __floats2half2_rn(a, b);
    return *(uint32_t*)&t;
}

// ============================================================================
// tc_gemm2: 2-term fp16 GEMM: C = (Ah+Al) @ Bh^T. CTA 128x128, 4 warps
// (64x64 warp tiles), BK=32, 2-stage cp.async (3 tiles/stage).
// Fused epilogue: rope + Q/K/V fp16 stores (hi only).
// ============================================================================
#define GBM 128
#define GBN 128
#define GBK 32
#define GSTRIDE 80
#define GTILE (GBM * GSTRIDE)
#define G2STAGE (3 * GTILE)
#define G2SMEM (2 * G2STAGE)

__global__ __launch_bounds__(128) void tc_gemm2_kernel(
    const __half* __restrict__ Ah, const __half* __restrict__ Al,
    const __half* __restrict__ Bh,
    const float* __restrict__ fc,
    __half* __restrict__ Qh,
    __half* __restrict__ Kh,
    __half* __restrict__ Vh,
    int N, int K)
{
    extern __shared__ char smem[];
    const uint32_t sb = smem_u32(smem);
    const int tid = threadIdx.x;
    const int wid = tid >> 5;
    const int lane = tid & 31;
    const int mb = blockIdx.y * GBM;
    const int nb = blockIdx.x * GBN;
    const int wm = (wid >> 1) * 64;
    const int wn = (wid & 1) * 64;

    auto load_stage = [&](int stage, int k0) {
        uint32_t base = sb + stage * G2STAGE;
        uint32_t sAh = base, sAl = base + GTILE, sB = base + 2 * GTILE;
#pragma unroll
        for (int i = 0; i < 4; i++) {
            int slot = i * 128 + tid;
            int r = slot >> 2, sg = slot & 3;
            cp_async16(sAh + r * GSTRIDE + sg * 16, Ah + (size_t)(mb + r) * K + k0 + sg * 8);
            cp_async16(sAl + r * GSTRIDE + sg * 16, Al + (size_t)(mb + r) * K + k0 + sg * 8);
            cp_async16(sB + r * GSTRIDE + sg * 16, Bh + (size_t)(nb + r) * K + k0 + sg * 8);
        }
        cp_commit();
    };

    float acc[4][8][4];
#pragma unroll
    for (int i = 0; i < 4; i++)
#pragma unroll
        for (int j = 0; j < 8; j++)
#pragma unroll
            for (int e = 0; e < 4; e++) acc[i][j][e] = 0.f;

    const uint32_t aoff = (uint32_t)((lane & 15) * GSTRIDE + (lane >> 4) * 16);
    const uint32_t boff = (uint32_t)(((lane & 7) + ((lane >> 4) * 8)) * GSTRIDE
                                     + (((lane >> 3) & 1) * 16));

    load_stage(0, 0);
    const int niter = K / GBK;
    for (int it = 0; it < niter; it++) {
        cp_wait0();
        __syncthreads();
        if (it + 1 < niter) load_stage((it + 1) & 1, (it + 1) * GBK);

        uint32_t base = sb + (it & 1) * G2STAGE;
        uint32_t bAh = base, bAl = base + GTILE, bB = base + 2 * GTILE;

#pragma unroll
        for (int ks = 0; ks < 2; ks++) {
            uint32_t kb = (uint32_t)(ks * 32);
            uint32_t ah[4][4], al[4][4];
#pragma unroll
            for (int mi = 0; mi < 4; mi++) {
                uint32_t rowb = (uint32_t)((wm + mi * 16) * GSTRIDE) + kb;
                ldmatrix_x4(ah[mi][0], ah[mi][1], ah[mi][2], ah[mi][3], bAh + rowb + aoff);
                ldmatrix_x4(al[mi][0], al[mi][1], al[mi][2], al[mi][3], bAl + rowb + aoff);
            }
            uint32_t bf[8][2];
#pragma unroll
            for (int nj = 0; nj < 4; nj++) {
                uint32_t rowb = (uint32_t)((wn + nj * 16) * GSTRIDE) + kb;
                uint32_t t0, t1, t2, t3;
                ldmatrix_x4(t0, t1, t2, t3, bB + rowb + boff);
                bf[nj * 2][0] = t0; bf[nj * 2][1] = t1;
                bf[nj * 2 + 1][0] = t2; bf[nj * 2 + 1][1] = t3;
            }
#pragma unroll
            for (int mi = 0; mi < 4; mi++)
#pragma unroll
                for (int nj = 0; nj < 8; nj++) {
                    mma_fp16(acc[mi][nj], ah[mi][0], ah[mi][1], ah[mi][2], ah[mi][3],
                             bf[nj][0], bf[nj][1]);
                    mma_fp16(acc[mi][nj], al[mi][0], al[mi][1], al[mi][2], al[mi][3],
                             bf[nj][0], bf[nj][1]);
                }
        }
        __syncthreads();
    }

    const int g = lane >> 2, c = lane & 3;
#pragma unroll
    for (int mi = 0; mi < 4; mi++) {
#pragma unroll
        for (int nj = 0; nj < 8; nj++) {
            const int col = nb + wn + nj * 8 + 2 * c;
#pragma unroll
            for (int rr = 0; rr < 2; rr++) {
                const int row = mb + wm + mi * 16 + g + rr * 8;
                float v0 = acc[mi][nj][rr * 2 + 0];
                float v1 = acc[mi][nj][rr * 2 + 1];
                const int b = row >> 11, s = row & (S_ - 1);
                const int d = col & 63;
                if (col < DIM_ + NKV_ * HD_) {
                    float2 f = *(const float2*)(fc + (size_t)s * HD_ + d);
                    float rx = v0 * f.x - v1 * f.y;
                    float ry = v1 * f.x + v0 * f.y;
                    v0 = rx; v1 = ry;
                }
                if (col < DIM_) {
                    int h = col >> 6;
                    size_t o = ((size_t)(b * NH_ + h) * S_ + s) * HD_ + d;
                    *(uint32_t*)(Qh + o) = pack_h2(v0, v1);
                } else if (col < DIM_ + NKV_ * HD_) {
                    int kvh = (col - DIM_) >> 6;
                    size_t o = ((size_t)(b * NKV_ + kvh) * S_ + s) * HD_ + d;
                    *(uint32_t*)(Kh + o) = pack_h2(v0, v1);
                } else {
                    int kvh = (col - DIM_ - NKV_ * HD_) >> 6;
                    size_t o = ((size_t)(b * NKV_ + kvh) * S_ + s) * HD_ + d;
                    *(uint32_t*)(Vh + o) = pack_h2(v0, v1);
                }
            }
        }
    }
}

// ============================================================================
// tc_gemm1: single-term fp16 GEMM (out = att @ woT^T). CTA 128x128, 4 warps.
// ============================================================================
#define G1STAGE (2 * GTILE)
#define G1SMEM (2 * G1STAGE)

__global__ __launch_bounds__(128) void tc_gemm1_kernel(
    const __half* __restrict__ A, const __half* __restrict__ B,
    float* __restrict__ C, int N, int K)
{
    extern __shared__ char smem[];
    const uint32_t sb = smem_u32(smem);
    const int tid = threadIdx.x;
    const int wid = tid >> 5;
    const int lane = tid & 31;
    const int mb = blockIdx.y * GBM;
    const int nb = blockIdx.x * GBN;
    const int wm = (wid >> 1) * 64;
    const int wn = (wid & 1) * 64;

    auto load_stage = [&](int stage, int k0) {
        uint32_t base = sb + stage * G1STAGE;
        uint32_t sA = base, sB = base + GTILE;
#pragma unroll
        for (int i = 0; i < 4; i++) {
            int slot = i * 128 + tid;
            int r = slot >> 2, sg = slot & 3;
            cp_async16(sA + r * GSTRIDE + sg * 16, A + (size_t)(mb + r) * K + k0 + sg * 8);
            cp_async16(sB + r * GSTRIDE + sg * 16, B + (size_t)(nb + r) * K + k0 + sg * 8);
        }
        cp_commit();
    };

    float acc[4][8][4];
#pragma unroll
    for (int i = 0; i < 4; i++)
#pragma unroll
        for (int j = 0; j < 8; j++)
#pragma unroll
            for (int e = 0; e < 4; e++) acc[i][j][e] = 0.f;

    const uint32_t aoff = (uint32_t)((lane & 15) * GSTRIDE + (lane >> 4) * 16);
    const uint32_t boff = (uint32_t)(((lane & 7) + ((lane >> 4) * 8)) * GSTRIDE
                                     + (((lane >> 3) & 1) * 16));

    load_stage(0, 0);
    const int niter = K / GBK;
    for (int it = 0; it < niter; it++) {
        cp_wait0();
        __syncthreads();
        if (it + 1 < niter) load_stage((it + 1) & 1, (it + 1) * GBK);

        uint32_t base = sb + (it & 1) * G1STAGE;
        uint32_t bA = base, bB = base + GTILE;

#pragma unroll
        for (int ks = 0; ks < 2; ks++) {
            uint32_t kb = (uint32_t)(ks * 32);
            uint32_t af[4][4];
#pragma unroll
            for (int mi = 0; mi < 4; mi++) {
                uint32_t rowb = (uint32_t)((wm + mi * 16) * GSTRIDE) + kb;
                ldmatrix_x4(af[mi][0], af[mi][1], af[mi][2], af[mi][3], bA + rowb + aoff);
            }
            uint32_t bf[8][2];
#pragma unroll
            for (int nj = 0; nj < 4; nj++) {
                uint32_t rowb = (uint32_t)((wn + nj * 16) * GSTRIDE) + kb;
                uint32_t t0, t1, t2, t3;
                ldmatrix_x4(t0, t1, t2, t3, bB + rowb + boff);
                bf[nj * 2][0] = t0; bf[nj * 2][1] = t1;
                bf[nj * 2 + 1][0] = t2; bf[nj * 2 + 1][1] = t3;
            }
#pragma unroll
            for (int mi = 0; mi < 4; mi++)
#pragma unroll
                for (int nj = 0; nj < 8; nj++)
                    mma_fp16(acc[mi][nj], af[mi][0], af[mi][1], af[mi][2], af[mi][3],
                             bf[nj][0], bf[nj][1]);
        }
        __syncthreads();
    }

    const int g = lane >> 2, c = lane & 3;
#pragma unroll
    for (int mi = 0; mi < 4; mi++) {
#pragma unroll
        for (int nj = 0; nj < 8; nj++) {
            float* cp0 = C + (size_t)(mb + wm + mi * 16 + g) * N + nb + wn + nj * 8 + 2 * c;
            float* cp1 = cp0 + (size_t)8 * N;
            *(float2*)cp0 = make_float2(acc[mi][nj][0], acc[mi][nj][1]);
            *(float2*)cp1 = make_float2(acc[mi][nj][2], acc[mi][nj][3]);
        }
    }
}

// ============================================================================
// conversion kernels (fp16)
// ============================================================================
__global__ __launch_bounds__(256) void conv_split_kernel(
    const float* __restrict__ A, __half* __restrict__ H,
    __half* __restrict__ L, int n4)
{
    int i = blockIdx.x * blockDim.x + threadIdx.x;
    if (i >= n4) return;
    float4 v = *(const float4*)(A + (size_t)i * 4);
    float vv[4] = {v.x, v.y, v.z, v.w};
    __half h[4], l[4];
#pragma unroll
    for (int j = 0; j < 4; j++) {
        h[j] = __float2half_rn(vv[j]);
        l[j] = __float2half_rn(vv[j] - __half2float(h[j]));
    }
    *(uint2*)(H + (size_t)i * 4) = *(uint2*)h;
    *(uint2*)(L + (size_t)i * 4) = *(uint2*)l;
}

// W [K][N] fp32 -> Wt hi [N][K] fp16
__global__ __launch_bounds__(256) void conv_transpose_kernel(
    const float* __restrict__ W, __half* __restrict__ Th, int K, int N)
{
    __shared__ float t[32][33];
    const int k0 = blockIdx.y * 32, n0 = blockIdx.x * 32;
    const int tx = threadIdx.x & 31, ty = threadIdx.x >> 5;
#pragma unroll
    for (int i = 0; i < 32; i += 8)
        t[ty + i][tx] = W[(size_t)(k0 + ty + i) * N + n0 + tx];
    __syncthreads();
#pragma unroll
    for (int i = 0; i < 32; i += 8) {
        float v = t[tx][ty + i];
        Th[(size_t)(n0 + ty + i) * K + k0 + tx] = __float2half_rn(v);
    }
}

// ============================================================================
// Flash attention: QK^T 1-term fp16, PV 1-term fp16, att out fp16.
// CTA: 64 q-rows x 1 head, 4 warps. kv tiles of 64, double buffer (Kh+Vh).
// ============================================================================
#define FSTR 144
#define FTILE (64 * FSTR)
#define FSTAGE (2 * FTILE)       // Kh, Vh
#define FSMEM (2 * FSTAGE)

__global__ __launch_bounds__(128) void flash_tc_kernel(
    const __half* __restrict__ Qh,
    const __half* __restrict__ Kh,
    const __half* __restrict__ Vh,
    __half* __restrict__ Oh)
{
    extern __shared__ char smem[];
    const uint32_t sb = smem_u32(smem);
    const int tid  = threadIdx.x;
    const int wid  = tid >> 5;
    const int lane = tid & 31;
    const int qtile = blockIdx.x;
    const int h     = blockIdx.y;
    const int b     = blockIdx.z;
    const int kvh   = h >> 2;
    const int q0    = qtile * 64;
    const int wm    = wid * 16;

    const __half* qhp = Qh + ((size_t)(b * NH_ + h) * S_ + q0) * HD_;
    const __half* khp = Kh + ((size_t)(b * NKV_ + kvh) * S_) * HD_;
    const __half* vhp = Vh + ((size_t)(b * NKV_ + kvh) * S_) * HD_;

    const int lr[4] = {(tid) >> 3, (tid + 128) >> 3, (tid + 256) >> 3, (tid + 384) >> 3};
    const int ls = tid & 7;

    // stage Q, build fragments
#pragma unroll
    for (int i = 0; i < 4; i++)
        cp_async16(sb + lr[i] * FSTR + ls * 16, qhp + (size_t)lr[i] * HD_ + ls * 8);
    cp_commit();
    cp_wait0();
    __syncthreads();

    const uint32_t aoff = (uint32_t)((lane & 15) * FSTR + (lane >> 4) * 16);
    const uint32_t boff = (uint32_t)(((lane & 7) + ((lane >> 4) * 8)) * FSTR
                                     + (((lane >> 3) & 1) * 16));
    const uint32_t voff = (uint32_t)(((lane & 7) + (((lane >> 3) & 1) * 8)) * FSTR
                                     + ((lane >> 4) * 16));

    uint32_t qf[4][4];
#pragma unroll
    for (int ks = 0; ks < 4; ks++) {
        uint32_t rowb = (uint32_t)(wm * FSTR + ks * 32);
        ldmatrix_x4(qf[ks][0], qf[ks][1], qf[ks][2], qf[ks][3], sb + rowb + aoff);
    }
    __syncthreads();

    auto load_kv = [&](int st, int j) {
        uint32_t base = sb + st * FSTAGE;
        size_t g0 = (size_t)(j * 64) * HD_;
#pragma unroll
        for (int i = 0; i < 4; i++) {
            uint32_t so = lr[i] * FSTR + ls * 16;
            size_t go = g0 + (size_t)lr[i] * HD_ + ls * 8;
            cp_async16(base + so, khp + go);
            cp_async16(base + FTILE + so, vhp + go);
        }
        cp_commit();
    };
    load_kv(0, 0);

    float m0 = -1e30f, m1 = -1e30f, l0 = 0.f, l1 = 0.f;
    float o[8][4];
#pragma unroll
    for (int nj = 0; nj < 8; nj++)
#pragma unroll
        for (int e = 0; e < 4; e++) o[nj][e] = 0.f;

    const int r0 = lane >> 2;
    const int tig = lane & 3;
    const int qg0 = q0 + wm + r0;
    const int qg1 = qg0 + 8;

    for (int j = 0; j <= qtile; j++) {
        cp_wait0();
        __syncthreads();
        if (j < qtile) load_kv((j + 1) & 1, j + 1);

        uint32_t base = sb + (j & 1) * FSTAGE;
        uint32_t bKh = base;
        uint32_t bVh = base + FTILE;

        float c[8][4];
#pragma unroll
        for (int nj = 0; nj < 8; nj++)
#pragma unroll
            for (int e = 0; e < 4; e++) c[nj][e] = 0.f;

#pragma unroll
        for (int ks = 0; ks < 4; ks++) {
            uint32_t kf[4][4];
#pragma unroll
            for (int njp = 0; njp < 4; njp++) {
                uint32_t off = (uint32_t)(njp * 16 * FSTR + ks * 32) + boff;
                ldmatrix_x4(kf[njp][0], kf[njp][1], kf[njp][2], kf[njp][3], bKh + off);
            }
#pragma unroll
            for (int njp = 0; njp < 4; njp++) {
                mma_fp16(c[2 * njp],     qf[ks][0], qf[ks][1], qf[ks][2], qf[ks][3], kf[njp][0], kf[njp][1]);
                mma_fp16(c[2 * njp + 1], qf[ks][0], qf[ks][1], qf[ks][2], qf[ks][3], kf[njp][2], kf[njp][3]);
            }
        }

        const bool diag = (j == qtile);
        float tm0 = -1e30f, tm1 = -1e30f;
#pragma unroll
        for (int nj = 0; nj < 8; nj++) {
            int colb = j * 64 + nj * 8 + 2 * tig;
#pragma unroll
            for (int e = 0; e < 4; e++) {
                float sv = c[nj][e] * 0.125f;
                if (diag) {
                    int colg = colb + (e & 1);
                    int rowg = (e < 2) ? qg0 : qg1;
                    if (colg > rowg) sv = -1e30f;
                }
                c[nj][e] = sv;
            }
            tm0 = fmaxf(tm0, fmaxf(c[nj][0], c[nj][1]));
            tm1 = fmaxf(tm1, fmaxf(c[nj][2], c[nj][3]));
        }
        tm0 = fmaxf(tm0, __shfl_xor_sync(0xffffffffu, tm0, 1));
        tm0 = fmaxf(tm0, __shfl_xor_sync(0xffffffffu, tm0, 2));
        tm1 = fmaxf(tm1, __shfl_xor_sync(0xffffffffu, tm1, 1));
        tm1 = fmaxf(tm1, __shfl_xor_sync(0xffffffffu, tm1, 2));

        float mn0 = fmaxf(m0, tm0), mn1 = fmaxf(m1, tm1);
        float sc0 = __expf(m0 - mn0), sc1 = __expf(m1 - mn1);
        m0 = mn0; m1 = mn1;

        float sum0 = 0.f, sum1 = 0.f;
#pragma unroll
        for (int nj = 0; nj < 8; nj++) {
            c[nj][0] = __expf(c[nj][0] - mn0);
            c[nj][1] = __expf(c[nj][1] - mn0);
            c[nj][2] = __expf(c[nj][2] - mn1);
            c[nj][3] = __expf(c[nj][3] - mn1);
            sum0 += c[nj][0] + c[nj][1];
            sum1 += c[nj][2] + c[nj][3];
        }
        sum0 += __shfl_xor_sync(0xffffffffu, sum0, 1);
        sum0 += __shfl_xor_sync(0xffffffffu, sum0, 2);
        sum1 += __shfl_xor_sync(0xffffffffu, sum1, 1);
        sum1 += __shfl_xor_sync(0xffffffffu, sum1, 2);
        l0 = l0 * sc0 + sum0;
        l1 = l1 * sc1 + sum1;

#pragma unroll
        for (int nj = 0; nj < 8; nj++) {
            o[nj][0] *= sc0; o[nj][1] *= sc0;
            o[nj][2] *= sc1; o[nj][3] *= sc1;
        }

#pragma unroll
        for (int ksv = 0; ksv < 4; ksv++) {
            uint32_t ap[4];
            ap[0] = pack_h2(c[2 * ksv][0], c[2 * ksv][1]);
            ap[1] = pack_h2(c[2 * ksv][2], c[2 * ksv][3]);
            ap[2] = pack_h2(c[2 * ksv + 1][0], c[2 * ksv + 1][1]);
            ap[3] = pack_h2(c[2 * ksv + 1][2], c[2 * ksv + 1][3]);
#pragma unroll
            for (int njp = 0; njp < 4; njp++) {
                uint32_t off = (uint32_t)(ksv * 16 * FSTR + njp * 32) + voff;
                uint32_t v0, v1, v2, v3;
                ldmatrix_x4_trans(v0, v1, v2, v3, bVh + off);
                mma_fp16(o[2 * njp],     ap[0], ap[1], ap[2], ap[3], v0, v1);
                mma_fp16(o[2 * njp + 1], ap[0], ap[1], ap[2], ap[3], v2, v3);
            }
        }
    }

    float inv0 = 1.f / l0, inv1 = 1.f / l1;
    size_t gr0 = (size_t)(b * S_ + q0 + wm + r0) * DIM_ + h * HD_ + 2 * tig;
    size_t gr1 = gr0 + (size_t)8 * DIM_;
#pragma unroll
    for (int nj = 0; nj < 8; nj++) {
        *(uint32_t*)(Oh + gr0 + nj * 8) = pack_h2(o[nj][0] * inv0, o[nj][1] * inv0);
        *(uint32_t*)(Oh + gr1 + nj * 8) = pack_h2(o[nj][2] * inv1, o[nj][3] * inv1);
    }
}

// ============================================================================
// launch
// ============================================================================
extern "C" void kernel_launch(void* const* d_in, const int* in_sizes, int n_in,
                              void* d_out, int out_size)
{
    const float* x    = (const float*)d_in[0];
    const float* fc   = (const float*)d_in[1];
    const float* wqkv = (const float*)d_in[2];
    const float* wo   = (const float*)d_in[3];
    float* out        = (float*)d_out;

    void *xh_p, *xl_p, *wqh_p, *woh_p, *ah_p;
    void *qh_p, *kh_p, *vh_p;
    cudaGetSymbolAddress(&xh_p, g_x_hi);
    cudaGetSymbolAddress(&xl_p, g_x_lo);
    cudaGetSymbolAddress(&wqh_p, g_wqkvT_hi);
    cudaGetSymbolAddress(&woh_p, g_woT_hi);
    cudaGetSymbolAddress(&ah_p, g_att_hi);
    cudaGetSymbolAddress(&qh_p, g_q_hi);
    cudaGetSymbolAddress(&kh_p, g_k_hi);
    cudaGetSymbolAddress(&vh_p, g_v_hi);

    cudaFuncSetAttribute(tc_gemm2_kernel, cudaFuncAttributeMaxDynamicSharedMemorySize,
                         G2SMEM);
    cudaFuncSetAttribute(tc_gemm1_kernel, cudaFuncAttributeMaxDynamicSharedMemorySize,
                         G1SMEM);
    cudaFuncSetAttribute(flash_tc_kernel, cudaFuncAttributeMaxDynamicSharedMemorySize,
                         FSMEM);

    // 1) split x -> fp16 hi/lo
    {
        int n4 = M_ * DIM_ / 4;
        conv_split_kernel<<<(n4 + 255) / 256, 256>>>(
            x, (__half*)xh_p, (__half*)xl_p, n4);
    }
    // 2) transpose weights (hi only)
    conv_transpose_kernel<<<dim3(QKVN / 32, KDIM / 32), 256>>>(
        wqkv, (__half*)wqh_p, KDIM, QKVN);
    conv_transpose_kernel<<<dim3(DIM_ / 32, KDIM / 32), 256>>>(
        wo, (__half*)woh_p, KDIM, DIM_);

    // 3) qkv projection (2-term) + fused rope epilogue -> Q/K/V fp16
    tc_gemm2_kernel<<<dim3(QKVN / GBN, M_ / GBM), 128, G2SMEM>>>(
        (const __half*)xh_p, (const __half*)xl_p,
        (const __half*)wqh_p, fc,
        (__half*)qh_p, (__half*)kh_p, (__half*)vh_p,
        QKVN, KDIM);

    // 4) flash attention (QK 1-term, PV 1-term) -> att fp16
    flash_tc_kernel<<<dim3(S_ / 64, NH_, B_), 128, FSMEM>>>(
        (const __half*)qh_p, (const __half*)kh_p, (const __half*)vh_p,
        (__half*)ah_p);

    // 5) out = att @ wo (1-term fp16)
    tc_gemm1_kernel<<<dim3(DIM_ / GBN, M_ / GBM), 128, G1SMEM>>>(
        (const __half*)ah_p, (const __half*)woh_p, out, DIM_, KDIM);
}

// round 11
// speedup vs baseline: 6.7433x; 1.0108x over previous
#include <cuda_runtime.h>
#include <cuda_fp16.h>
#include <cstdint>

// ---------------- problem constants ----------------
#define B_   2
#define S_   2048
#define DIM_ 2048
#define NH_  32
#define NKV_ 8
#define HD_  64
#define QKVN 3072
#define M_   (B_ * S_)
#define KDIM 2048

// ---------------- scratch (fp16) ----------------
__device__ __half g_x_hi[(size_t)M_ * DIM_];
__device__ __half g_x_lo[(size_t)M_ * DIM_];
__device__ __half g_wqkvT_hi[(size_t)QKVN * DIM_];
__device__ __half g_woT_hi[(size_t)DIM_ * DIM_];
__device__ __half g_att_hi[(size_t)M_ * DIM_];
__device__ __half g_q_hi[(size_t)B_ * NH_ * S_ * HD_];
__device__ __half g_k_hi[(size_t)B_ * NKV_ * S_ * HD_];
__device__ __half g_v_hi[(size_t)B_ * NKV_ * S_ * HD_];

// ============================================================================
// helpers (sm_80-compatible only)
// ============================================================================
__device__ __forceinline__ uint32_t smem_u32(const void* p) {
    uint32_t a;
    asm("{ .reg .u64 t; cvta.to.shared.u64 t, %1; cvt.u32.u64 %0, t; }"
        : "=r"(a) : "l"(p));
    return a;
}
__device__ __forceinline__ void cp_async16(uint32_t s, const void* g) {
    asm volatile("cp.async.cg.shared.global [%0], [%1], 16;" :: "r"(s), "l"(g));
}
__device__ __forceinline__ void cp_commit() {
    asm volatile("cp.async.commit_group;" ::: "memory");
}
__device__ __forceinline__ void cp_wait0() {
    asm volatile("cp.async.wait_group 0;" ::: "memory");
}
__device__ __forceinline__ void ldmatrix_x4(uint32_t& r0, uint32_t& r1,
                                            uint32_t& r2, uint32_t& r3, uint32_t a) {
    asm volatile("ldmatrix.sync.aligned.m8n8.x4.shared.b16 {%0,%1,%2,%3}, [%4];"
                 : "=r"(r0), "=r"(r1), "=r"(r2), "=r"(r3) : "r"(a));
}
__device__ __forceinline__ void ldmatrix_x4_trans(uint32_t& r0, uint32_t& r1,
                                                  uint32_t& r2, uint32_t& r3, uint32_t a) {
    asm volatile("ldmatrix.sync.aligned.m8n8.x4.trans.shared.b16 {%0,%1,%2,%3}, [%4];"
                 : "=r"(r0), "=r"(r1), "=r"(r2), "=r"(r3) : "r"(a));
}
__device__ __forceinline__ void mma_fp16(float* c, uint32_t a0, uint32_t a1,
                                         uint32_t a2, uint32_t a3,
                                         uint32_t b0, uint32_t b1) {
    asm volatile(
        "mma.sync.aligned.m16n8k16.row.col.f32.f16.f16.f32 "
        "{%0,%1,%2,%3}, {%4,%5,%6,%7}, {%8,%9}, {%0,%1,%2,%3};"
        : "+f"(c[0]), "+f"(c[1]), "+f"(c[2]), "+f"(c[3])
        : "r"(a0), "r"(a1), "r"(a2), "r"(a3), "r"(b0), "r"(b1));
}
__device__ __forceinline__ uint32_t pack_h2(float a, float b) {
    __half2 t = __floats2half2_rn(a, b);
    return *(uint32_t*)&t;
}

// ============================================================================
// tc_gemm2: 2-term fp16 GEMM: C = (Ah+Al) @ Bh^T. CTA 128x128, 4 warps
// (64x64 warp tiles), BK=32, 2-stage cp.async (3 tiles/stage).
// Fused epilogue: rope + Q/K/V fp16 stores.
// ============================================================================
#define GBM 128
#define GBN 128
#define GBK 32
#define GSTRIDE 80
#define GTILE (GBM * GSTRIDE)
#define G2STAGE (3 * GTILE)
#define G2SMEM (2 * G2STAGE)

__global__ __launch_bounds__(128) void tc_gemm2_kernel(
    const __half* __restrict__ Ah, const __half* __restrict__ Al,
    const __half* __restrict__ Bh,
    const float* __restrict__ fc,
    __half* __restrict__ Qh,
    __half* __restrict__ Kh,
    __half* __restrict__ Vh,
    int N, int K)
{
    extern __shared__ char smem[];
    const uint32_t sb = smem_u32(smem);
    const int tid = threadIdx.x;
    const int wid = tid >> 5;
    const int lane = tid & 31;
    const int mb = blockIdx.y * GBM;
    const int nb = blockIdx.x * GBN;
    const int wm = (wid >> 1) * 64;
    const int wn = (wid & 1) * 64;

    auto load_stage = [&](int stage, int k0) {
        uint32_t base = sb + stage * G2STAGE;
        uint32_t sAh = base, sAl = base + GTILE, sB = base + 2 * GTILE;
#pragma unroll
        for (int i = 0; i < 4; i++) {
            int slot = i * 128 + tid;
            int r = slot >> 2, sg = slot & 3;
            cp_async16(sAh + r * GSTRIDE + sg * 16, Ah + (size_t)(mb + r) * K + k0 + sg * 8);
            cp_async16(sAl + r * GSTRIDE + sg * 16, Al + (size_t)(mb + r) * K + k0 + sg * 8);
            cp_async16(sB + r * GSTRIDE + sg * 16, Bh + (size_t)(nb + r) * K + k0 + sg * 8);
        }
        cp_commit();
    };

    float acc[4][8][4];
#pragma unroll
    for (int i = 0; i < 4; i++)
#pragma unroll
        for (int j = 0; j < 8; j++)
#pragma unroll
            for (int e = 0; e < 4; e++) acc[i][j][e] = 0.f;

    const uint32_t aoff = (uint32_t)((lane & 15) * GSTRIDE + (lane >> 4) * 16);
    const uint32_t boff = (uint32_t)(((lane & 7) + ((lane >> 4) * 8)) * GSTRIDE
                                     + (((lane >> 3) & 1) * 16));

    load_stage(0, 0);
    const int niter = K / GBK;
    for (int it = 0; it < niter; it++) {
        cp_wait0();
        __syncthreads();
        if (it + 1 < niter) load_stage((it + 1) & 1, (it + 1) * GBK);

        uint32_t base = sb + (it & 1) * G2STAGE;
        uint32_t bAh = base, bAl = base + GTILE, bB = base + 2 * GTILE;

#pragma unroll
        for (int ks = 0; ks < 2; ks++) {
            uint32_t kb = (uint32_t)(ks * 32);
            uint32_t ah[4][4], al[4][4];
#pragma unroll
            for (int mi = 0; mi < 4; mi++) {
                uint32_t rowb = (uint32_t)((wm + mi * 16) * GSTRIDE) + kb;
                ldmatrix_x4(ah[mi][0], ah[mi][1], ah[mi][2], ah[mi][3], bAh + rowb + aoff);
                ldmatrix_x4(al[mi][0], al[mi][1], al[mi][2], al[mi][3], bAl + rowb + aoff);
            }
            uint32_t bf[8][2];
#pragma unroll
            for (int nj = 0; nj < 4; nj++) {
                uint32_t rowb = (uint32_t)((wn + nj * 16) * GSTRIDE) + kb;
                uint32_t t0, t1, t2, t3;
                ldmatrix_x4(t0, t1, t2, t3, bB + rowb + boff);
                bf[nj * 2][0] = t0; bf[nj * 2][1] = t1;
                bf[nj * 2 + 1][0] = t2; bf[nj * 2 + 1][1] = t3;
            }
#pragma unroll
            for (int mi = 0; mi < 4; mi++)
#pragma unroll
                for (int nj = 0; nj < 8; nj++) {
                    mma_fp16(acc[mi][nj], ah[mi][0], ah[mi][1], ah[mi][2], ah[mi][3],
                             bf[nj][0], bf[nj][1]);
                    mma_fp16(acc[mi][nj], al[mi][0], al[mi][1], al[mi][2], al[mi][3],
                             bf[nj][0], bf[nj][1]);
                }
        }
        __syncthreads();
    }

    const int g = lane >> 2, c = lane & 3;
#pragma unroll
    for (int mi = 0; mi < 4; mi++) {
#pragma unroll
        for (int nj = 0; nj < 8; nj++) {
            const int col = nb + wn + nj * 8 + 2 * c;
#pragma unroll
            for (int rr = 0; rr < 2; rr++) {
                const int row = mb + wm + mi * 16 + g + rr * 8;
                float v0 = acc[mi][nj][rr * 2 + 0];
                float v1 = acc[mi][nj][rr * 2 + 1];
                const int b = row >> 11, s = row & (S_ - 1);
                const int d = col & 63;
                if (col < DIM_ + NKV_ * HD_) {
                    float2 f = *(const float2*)(fc + (size_t)s * HD_ + d);
                    float rx = v0 * f.x - v1 * f.y;
                    float ry = v1 * f.x + v0 * f.y;
                    v0 = rx; v1 = ry;
                }
                if (col < DIM_) {
                    int h = col >> 6;
                    size_t o = ((size_t)(b * NH_ + h) * S_ + s) * HD_ + d;
                    *(uint32_t*)(Qh + o) = pack_h2(v0, v1);
                } else if (col < DIM_ + NKV_ * HD_) {
                    int kvh = (col - DIM_) >> 6;
                    size_t o = ((size_t)(b * NKV_ + kvh) * S_ + s) * HD_ + d;
                    *(uint32_t*)(Kh + o) = pack_h2(v0, v1);
                } else {
                    int kvh = (col - DIM_ - NKV_ * HD_) >> 6;
                    size_t o = ((size_t)(b * NKV_ + kvh) * S_ + s) * HD_ + d;
                    *(uint32_t*)(Vh + o) = pack_h2(v0, v1);
                }
            }
        }
    }
}

// ============================================================================
// tc_gemm1: single-term fp16 GEMM (out = att @ woT^T). CTA 128x128, 4 warps.
// ============================================================================
#define G1STAGE (2 * GTILE)
#define G1SMEM (2 * G1STAGE)

__global__ __launch_bounds__(128) void tc_gemm1_kernel(
    const __half* __restrict__ A, const __half* __restrict__ B,
    float* __restrict__ C, int N, int K)
{
    extern __shared__ char smem[];
    const uint32_t sb = smem_u32(smem);
    const int tid = threadIdx.x;
    const int wid = tid >> 5;
    const int lane = tid & 31;
    const int mb = blockIdx.y * GBM;
    const int nb = blockIdx.x * GBN;
    const int wm = (wid >> 1) * 64;
    const int wn = (wid & 1) * 64;

    auto load_stage = [&](int stage, int k0) {
        uint32_t base = sb + stage * G1STAGE;
        uint32_t sA = base, sB = base + GTILE;
#pragma unroll
        for (int i = 0; i < 4; i++) {
            int slot = i * 128 + tid;
            int r = slot >> 2, sg = slot & 3;
            cp_async16(sA + r * GSTRIDE + sg * 16, A + (size_t)(mb + r) * K + k0 + sg * 8);
            cp_async16(sB + r * GSTRIDE + sg * 16, B + (size_t)(nb + r) * K + k0 + sg * 8);
        }
        cp_commit();
    };

    float acc[4][8][4];
#pragma unroll
    for (int i = 0; i < 4; i++)
#pragma unroll
        for (int j = 0; j < 8; j++)
#pragma unroll
            for (int e = 0; e < 4; e++) acc[i][j][e] = 0.f;

    const uint32_t aoff = (uint32_t)((lane & 15) * GSTRIDE + (lane >> 4) * 16);
    const uint32_t boff = (uint32_t)(((lane & 7) + ((lane >> 4) * 8)) * GSTRIDE
                                     + (((lane >> 3) & 1) * 16));

    load_stage(0, 0);
    const int niter = K / GBK;
    for (int it = 0; it < niter; it++) {
        cp_wait0();
        __syncthreads();
        if (it + 1 < niter) load_stage((it + 1) & 1, (it + 1) * GBK);

        uint32_t base = sb + (it & 1) * G1STAGE;
        uint32_t bA = base, bB = base + GTILE;

#pragma unroll
        for (int ks = 0; ks < 2; ks++) {
            uint32_t kb = (uint32_t)(ks * 32);
            uint32_t af[4][4];
#pragma unroll
            for (int mi = 0; mi < 4; mi++) {
                uint32_t rowb = (uint32_t)((wm + mi * 16) * GSTRIDE) + kb;
                ldmatrix_x4(af[mi][0], af[mi][1], af[mi][2], af[mi][3], bA + rowb + aoff);
            }
            uint32_t bf[8][2];
#pragma unroll
            for (int nj = 0; nj < 4; nj++) {
                uint32_t rowb = (uint32_t)((wn + nj * 16) * GSTRIDE) + kb;
                uint32_t t0, t1, t2, t3;
                ldmatrix_x4(t0, t1, t2, t3, bB + rowb + boff);
                bf[nj * 2][0] = t0; bf[nj * 2][1] = t1;
                bf[nj * 2 + 1][0] = t2; bf[nj * 2 + 1][1] = t3;
            }
#pragma unroll
            for (int mi = 0; mi < 4; mi++)
#pragma unroll
                for (int nj = 0; nj < 8; nj++)
                    mma_fp16(acc[mi][nj], af[mi][0], af[mi][1], af[mi][2], af[mi][3],
                             bf[nj][0], bf[nj][1]);
        }
        __syncthreads();
    }

    const int g = lane >> 2, c = lane & 3;
#pragma unroll
    for (int mi = 0; mi < 4; mi++) {
#pragma unroll
        for (int nj = 0; nj < 8; nj++) {
            float* cp0 = C + (size_t)(mb + wm + mi * 16 + g) * N + nb + wn + nj * 8 + 2 * c;
            float* cp1 = cp0 + (size_t)8 * N;
            *(float2*)cp0 = make_float2(acc[mi][nj][0], acc[mi][nj][1]);
            *(float2*)cp1 = make_float2(acc[mi][nj][2], acc[mi][nj][3]);
        }
    }
}

// ============================================================================
// Fused conversion kernel: one launch does all three jobs.
//   Job A (blocks [0, NB_A)):          x fp32 -> x_hi/x_lo fp16 split
//   Job B (blocks [NB_A, NB_A+NB_B)):  wqkv [K][N] fp32 -> wqkvT_hi [N][K] fp16
//   Job C (rest):                      wo   [K][N] fp32 -> woT_hi   [N][K] fp16
// ============================================================================
#define NB_A (M_ * DIM_ / 4 / 256)            // 8192
#define NB_B ((KDIM / 32) * (QKVN / 32))      // 64*96 = 6144
#define NB_C ((KDIM / 32) * (DIM_ / 32))      // 64*64 = 4096
#define NB_TOTAL (NB_A + NB_B + NB_C)         // 18432

__global__ __launch_bounds__(256) void conv_fused_kernel(
    const float* __restrict__ x, __half* __restrict__ Xh, __half* __restrict__ Xl,
    const float* __restrict__ wqkv, __half* __restrict__ WqT,
    const float* __restrict__ wo, __half* __restrict__ WoT)
{
    __shared__ float t[32][33];
    const int bid = blockIdx.x;
    const int tid = threadIdx.x;

    if (bid < NB_A) {
        // ---- x split ----
        int i = bid * 256 + tid;
        float4 v = *(const float4*)(x + (size_t)i * 4);
        float vv[4] = {v.x, v.y, v.z, v.w};
        __half h[4], l[4];
#pragma unroll
        for (int j = 0; j < 4; j++) {
            h[j] = __float2half_rn(vv[j]);
            l[j] = __float2half_rn(vv[j] - __half2float(h[j]));
        }
        *(uint2*)(Xh + (size_t)i * 4) = *(uint2*)h;
        *(uint2*)(Xl + (size_t)i * 4) = *(uint2*)l;
        return;
    }

    // ---- transpose-convert (shared body) ----
    const float* W;
    __half* T;
    int N, tb;
    if (bid < NB_A + NB_B) {
        W = wqkv; T = WqT; N = QKVN; tb = bid - NB_A;
    } else {
        W = wo; T = WoT; N = DIM_; tb = bid - NB_A - NB_B;
    }
    const int ntiles = N / 32;
    const int bx = tb % ntiles, by = tb / ntiles;
    const int k0 = by * 32, n0 = bx * 32;
    const int tx = tid & 31, ty = tid >> 5;
#pragma unroll
    for (int i = 0; i < 32; i += 8)
        t[ty + i][tx] = W[(size_t)(k0 + ty + i) * N + n0 + tx];
    __syncthreads();
#pragma unroll
    for (int i = 0; i < 32; i += 8) {
        float v = t[tx][ty + i];
        T[(size_t)(n0 + ty + i) * KDIM + k0 + tx] = __float2half_rn(v);
    }
}

// ============================================================================
// Flash attention: QK^T 1-term fp16, PV 1-term fp16, att out fp16.
// CTA: 64 q-rows x 1 head, 4 warps. kv tiles of 64, double buffer (Kh+Vh).
// ============================================================================
#define FSTR 144
#define FTILE (64 * FSTR)
#define FSTAGE (2 * FTILE)       // Kh, Vh
#define FSMEM (2 * FSTAGE)

__global__ __launch_bounds__(128) void flash_tc_kernel(
    const __half* __restrict__ Qh,
    const __half* __restrict__ Kh,
    const __half* __restrict__ Vh,
    __half* __restrict__ Oh)
{
    extern __shared__ char smem[];
    const uint32_t sb = smem_u32(smem);
    const int tid  = threadIdx.x;
    const int wid  = tid >> 5;
    const int lane = tid & 31;
    const int qtile = blockIdx.x;
    const int h     = blockIdx.y;
    const int b     = blockIdx.z;
    const int kvh   = h >> 2;
    const int q0    = qtile * 64;
    const int wm    = wid * 16;

    const __half* qhp = Qh + ((size_t)(b * NH_ + h) * S_ + q0) * HD_;
    const __half* khp = Kh + ((size_t)(b * NKV_ + kvh) * S_) * HD_;
    const __half* vhp = Vh + ((size_t)(b * NKV_ + kvh) * S_) * HD_;

    const int lr[4] = {(tid) >> 3, (tid + 128) >> 3, (tid + 256) >> 3, (tid + 384) >> 3};
    const int ls = tid & 7;

    // stage Q, build fragments
#pragma unroll
    for (int i = 0; i < 4; i++)
        cp_async16(sb + lr[i] * FSTR + ls * 16, qhp + (size_t)lr[i] * HD_ + ls * 8);
    cp_commit();
    cp_wait0();
    __syncthreads();

    const uint32_t aoff = (uint32_t)((lane & 15) * FSTR + (lane >> 4) * 16);
    const uint32_t boff = (uint32_t)(((lane & 7) + ((lane >> 4) * 8)) * FSTR
                                     + (((lane >> 3) & 1) * 16));
    const uint32_t voff = (uint32_t)(((lane & 7) + (((lane >> 3) & 1) * 8)) * FSTR
                                     + ((lane >> 4) * 16));

    uint32_t qf[4][4];
#pragma unroll
    for (int ks = 0; ks < 4; ks++) {
        uint32_t rowb = (uint32_t)(wm * FSTR + ks * 32);
        ldmatrix_x4(qf[ks][0], qf[ks][1], qf[ks][2], qf[ks][3], sb + rowb + aoff);
    }
    __syncthreads();

    auto load_kv = [&](int st, int j) {
        uint32_t base = sb + st * FSTAGE;
        size_t g0 = (size_t)(j * 64) * HD_;
#pragma unroll
        for (int i = 0; i < 4; i++) {
            uint32_t so = lr[i] * FSTR + ls * 16;
            size_t go = g0 + (size_t)lr[i] * HD_ + ls * 8;
            cp_async16(base + so, khp + go);
            cp_async16(base + FTILE + so, vhp + go);
        }
        cp_commit();
    };
    load_kv(0, 0);

    float m0 = -1e30f, m1 = -1e30f, l0 = 0.f, l1 = 0.f;
    float o[8][4];
#pragma unroll
    for (int nj = 0; nj < 8; nj++)
#pragma unroll
        for (int e = 0; e < 4; e++) o[nj][e] = 0.f;

    const int r0 = lane >> 2;
    const int tig = lane & 3;
    const int qg0 = q0 + wm + r0;
    const int qg1 = qg0 + 8;

    for (int j = 0; j <= qtile; j++) {
        cp_wait0();
        __syncthreads();
        if (j < qtile) load_kv((j + 1) & 1, j + 1);

        uint32_t base = sb + (j & 1) * FSTAGE;
        uint32_t bKh = base;
        uint32_t bVh = base + FTILE;

        float c[8][4];
#pragma unroll
        for (int nj = 0; nj < 8; nj++)
#pragma unroll
            for (int e = 0; e < 4; e++) c[nj][e] = 0.f;

#pragma unroll
        for (int ks = 0; ks < 4; ks++) {
            uint32_t kf[4][4];
#pragma unroll
            for (int njp = 0; njp < 4; njp++) {
                uint32_t off = (uint32_t)(njp * 16 * FSTR + ks * 32) + boff;
                ldmatrix_x4(kf[njp][0], kf[njp][1], kf[njp][2], kf[njp][3], bKh + off);
            }
#pragma unroll
            for (int njp = 0; njp < 4; njp++) {
                mma_fp16(c[2 * njp],     qf[ks][0], qf[ks][1], qf[ks][2], qf[ks][3], kf[njp][0], kf[njp][1]);
                mma_fp16(c[2 * njp + 1], qf[ks][0], qf[ks][1], qf[ks][2], qf[ks][3], kf[njp][2], kf[njp][3]);
            }
        }

        const bool diag = (j == qtile);
        float tm0 = -1e30f, tm1 = -1e30f;
#pragma unroll
        for (int nj = 0; nj < 8; nj++) {
            int colb = j * 64 + nj * 8 + 2 * tig;
#pragma unroll
            for (int e = 0; e < 4; e++) {
                float sv = c[nj][e] * 0.125f;
                if (diag) {
                    int colg = colb + (e & 1);
                    int rowg = (e < 2) ? qg0 : qg1;
                    if (colg > rowg) sv = -1e30f;
                }
                c[nj][e] = sv;
            }
            tm0 = fmaxf(tm0, fmaxf(c[nj][0], c[nj][1]));
            tm1 = fmaxf(tm1, fmaxf(c[nj][2], c[nj][3]));
        }
        tm0 = fmaxf(tm0, __shfl_xor_sync(0xffffffffu, tm0, 1));
        tm0 = fmaxf(tm0, __shfl_xor_sync(0xffffffffu, tm0, 2));
        tm1 = fmaxf(tm1, __shfl_xor_sync(0xffffffffu, tm1, 1));
        tm1 = fmaxf(tm1, __shfl_xor_sync(0xffffffffu, tm1, 2));

        float mn0 = fmaxf(m0, tm0), mn1 = fmaxf(m1, tm1);
        float sc0 = __expf(m0 - mn0), sc1 = __expf(m1 - mn1);
        m0 = mn0; m1 = mn1;

        float sum0 = 0.f, sum1 = 0.f;
#pragma unroll
        for (int nj = 0; nj < 8; nj++) {
            c[nj][0] = __expf(c[nj][0] - mn0);
            c[nj][1] = __expf(c[nj][1] - mn0);
            c[nj][2] = __expf(c[nj][2] - mn1);
            c[nj][3] = __expf(c[nj][3] - mn1);
            sum0 += c[nj][0] + c[nj][1];
            sum1 += c[nj][2] + c[nj][3];
        }
        sum0 += __shfl_xor_sync(0xffffffffu, sum0, 1);
        sum0 += __shfl_xor_sync(0xffffffffu, sum0, 2);
        sum1 += __shfl_xor_sync(0xffffffffu, sum1, 1);
        sum1 += __shfl_xor_sync(0xffffffffu, sum1, 2);
        l0 = l0 * sc0 + sum0;
        l1 = l1 * sc1 + sum1;

#pragma unroll
        for (int nj = 0; nj < 8; nj++) {
            o[nj][0] *= sc0; o[nj][1] *= sc0;
            o[nj][2] *= sc1; o[nj][3] *= sc1;
        }

#pragma unroll
        for (int ksv = 0; ksv < 4; ksv++) {
            uint32_t ap[4];
            ap[0] = pack_h2(c[2 * ksv][0], c[2 * ksv][1]);
            ap[1] = pack_h2(c[2 * ksv][2], c[2 * ksv][3]);
            ap[2] = pack_h2(c[2 * ksv + 1][0], c[2 * ksv + 1][1]);
            ap[3] = pack_h2(c[2 * ksv + 1][2], c[2 * ksv + 1][3]);
#pragma unroll
            for (int njp = 0; njp < 4; njp++) {
                uint32_t off = (uint32_t)(ksv * 16 * FSTR + njp * 32) + voff;
                uint32_t v0, v1, v2, v3;
                ldmatrix_x4_trans(v0, v1, v2, v3, bVh + off);
                mma_fp16(o[2 * njp],     ap[0], ap[1], ap[2], ap[3], v0, v1);
                mma_fp16(o[2 * njp + 1], ap[0], ap[1], ap[2], ap[3], v2, v3);
            }
        }
    }

    float inv0 = 1.f / l0, inv1 = 1.f / l1;
    size_t gr0 = (size_t)(b * S_ + q0 + wm + r0) * DIM_ + h * HD_ + 2 * tig;
    size_t gr1 = gr0 + (size_t)8 * DIM_;
#pragma unroll
    for (int nj = 0; nj < 8; nj++) {
        *(uint32_t*)(Oh + gr0 + nj * 8) = pack_h2(o[nj][0] * inv0, o[nj][1] * inv0);
        *(uint32_t*)(Oh + gr1 + nj * 8) = pack_h2(o[nj][2] * inv1, o[nj][3] * inv1);
    }
}

// ============================================================================
// launch
// ============================================================================
extern "C" void kernel_launch(void* const* d_in, const int* in_sizes, int n_in,
                              void* d_out, int out_size)
{
    const float* x    = (const float*)d_in[0];
    const float* fc   = (const float*)d_in[1];
    const float* wqkv = (const float*)d_in[2];
    const float* wo   = (const float*)d_in[3];
    float* out        = (float*)d_out;

    void *xh_p, *xl_p, *wqh_p, *woh_p, *ah_p;
    void *qh_p, *kh_p, *vh_p;
    cudaGetSymbolAddress(&xh_p, g_x_hi);
    cudaGetSymbolAddress(&xl_p, g_x_lo);
    cudaGetSymbolAddress(&wqh_p, g_wqkvT_hi);
    cudaGetSymbolAddress(&woh_p, g_woT_hi);
    cudaGetSymbolAddress(&ah_p, g_att_hi);
    cudaGetSymbolAddress(&qh_p, g_q_hi);
    cudaGetSymbolAddress(&kh_p, g_k_hi);
    cudaGetSymbolAddress(&vh_p, g_v_hi);

    cudaFuncSetAttribute(tc_gemm2_kernel, cudaFuncAttributeMaxDynamicSharedMemorySize,
                         G2SMEM);
    cudaFuncSetAttribute(tc_gemm1_kernel, cudaFuncAttributeMaxDynamicSharedMemorySize,
                         G1SMEM);
    cudaFuncSetAttribute(flash_tc_kernel, cudaFuncAttributeMaxDynamicSharedMemorySize,
                         FSMEM);

    // 1) all conversions in one launch (x split + both weight transposes)
    conv_fused_kernel<<<NB_TOTAL, 256>>>(
        x, (__half*)xh_p, (__half*)xl_p,
        wqkv, (__half*)wqh_p,
        wo, (__half*)woh_p);

    // 2) qkv projection (2-term) + fused rope epilogue -> Q/K/V fp16
    tc_gemm2_kernel<<<dim3(QKVN / GBN, M_ / GBM), 128, G2SMEM>>>(
        (const __half*)xh_p, (const __half*)xl_p,
        (const __half*)wqh_p, fc,
        (__half*)qh_p, (__half*)kh_p, (__half*)vh_p,
        QKVN, KDIM);

    // 3) flash attention (QK 1-term, PV 1-term) -> att fp16
    flash_tc_kernel<<<dim3(S_ / 64, NH_, B_), 128, FSMEM>>>(
        (const __half*)qh_p, (const __half*)kh_p, (const __half*)vh_p,
        (__half*)ah_p);

    // 4) out = att @ wo (1-term fp16)
    tc_gemm1_kernel<<<dim3(DIM_ / GBN, M_ / GBM), 128, G1SMEM>>>(
        (const __half*)ah_p, (const __half*)woh_p, out, DIM_, KDIM);
}

// round 12
// speedup vs baseline: 7.2832x; 1.0801x over previous
#include <cuda_runtime.h>
#include <cuda_fp16.h>
#include <cstdint>

// ---------------- problem constants ----------------
#define B_   2
#define S_   2048
#define DIM_ 2048
#define NH_  32
#define NKV_ 8
#define HD_  64
#define QKVN 3072
#define M_   (B_ * S_)
#define KDIM 2048

// ---------------- scratch (fp16) ----------------
__device__ __half g_x_hi[(size_t)M_ * DIM_];
__device__ __half g_x_lo[(size_t)M_ * DIM_];
__device__ __half g_wqkvT_hi[(size_t)QKVN * DIM_];
__device__ __half g_woT_hi[(size_t)DIM_ * DIM_];
__device__ __half g_att_hi[(size_t)M_ * DIM_];
__device__ __half g_q_hi[(size_t)B_ * NH_ * S_ * HD_];
__device__ __half g_k_hi[(size_t)B_ * NKV_ * S_ * HD_];
__device__ __half g_v_hi[(size_t)B_ * NKV_ * S_ * HD_];

// ============================================================================
// helpers (sm_80-compatible only)
// ============================================================================
__device__ __forceinline__ uint32_t smem_u32(const void* p) {
    uint32_t a;
    asm("{ .reg .u64 t; cvta.to.shared.u64 t, %1; cvt.u32.u64 %0, t; }"
        : "=r"(a) : "l"(p));
    return a;
}
__device__ __forceinline__ void cp_async16(uint32_t s, const void* g) {
    asm volatile("cp.async.cg.shared.global [%0], [%1], 16;" :: "r"(s), "l"(g));
}
__device__ __forceinline__ void cp_commit() {
    asm volatile("cp.async.commit_group;" ::: "memory");
}
__device__ __forceinline__ void cp_wait0() {
    asm volatile("cp.async.wait_group 0;" ::: "memory");
}
__device__ __forceinline__ void ldmatrix_x4(uint32_t& r0, uint32_t& r1,
                                            uint32_t& r2, uint32_t& r3, uint32_t a) {
    asm volatile("ldmatrix.sync.aligned.m8n8.x4.shared.b16 {%0,%1,%2,%3}, [%4];"
                 : "=r"(r0), "=r"(r1), "=r"(r2), "=r"(r3) : "r"(a));
}
__device__ __forceinline__ void ldmatrix_x4_trans(uint32_t& r0, uint32_t& r1,
                                                  uint32_t& r2, uint32_t& r3, uint32_t a) {
    asm volatile("ldmatrix.sync.aligned.m8n8.x4.trans.shared.b16 {%0,%1,%2,%3}, [%4];"
                 : "=r"(r0), "=r"(r1), "=r"(r2), "=r"(r3) : "r"(a));
}
__device__ __forceinline__ void mma_fp16(float* c, uint32_t a0, uint32_t a1,
                                         uint32_t a2, uint32_t a3,
                                         uint32_t b0, uint32_t b1) {
    asm volatile(
        "mma.sync.aligned.m16n8k16.row.col.f32.f16.f16.f32 "
        "{%0,%1,%2,%3}, {%4,%5,%6,%7}, {%8,%9}, {%0,%1,%2,%3};"
        : "+f"(c[0]), "+f"(c[1]), "+f"(c[2]), "+f"(c[3])
        : "r"(a0), "r"(a1), "r"(a2), "r"(a3), "r"(b0), "r"(b1));
}
__device__ __forceinline__ uint32_t pack_h2(float a, float b) {
    __half2 t = __floats2half2_rn(a, b);
    return *(uint32_t*)&t;
}

// ============================================================================
// GEMM tiling (64 M-rows per CTA for fine-grained wave balance)
// ============================================================================
#define GBM 64
#define GBN 128
#define GBK 32
#define GSTRIDE 80
#define GTILE_A (GBM * GSTRIDE)      // 5120 B (64 rows)
#define GTILE_B (GBN * GSTRIDE)      // 10240 B (128 rows)

// ---- tc_gemm2: C = (Ah+Al) @ Bh^T, fused rope + Q/K/V epilogue ----
#define G2STAGE (2 * GTILE_A + GTILE_B)   // 20480
#define G2SMEM (2 * G2STAGE)              // 40960

__global__ __launch_bounds__(128) void tc_gemm2_kernel(
    const __half* __restrict__ Ah, const __half* __restrict__ Al,
    const __half* __restrict__ Bh,
    const float* __restrict__ fc,
    __half* __restrict__ Qh,
    __half* __restrict__ Kh,
    __half* __restrict__ Vh,
    int N, int K)
{
    extern __shared__ char smem[];
    const uint32_t sb = smem_u32(smem);
    const int tid = threadIdx.x;
    const int wid = tid >> 5;
    const int lane = tid & 31;
    const int mb = blockIdx.y * GBM;
    const int nb = blockIdx.x * GBN;
    const int wm = (wid >> 1) * 32;    // warp tile 32x64
    const int wn = (wid & 1) * 64;

    auto load_stage = [&](int stage, int k0) {
        uint32_t base = sb + stage * G2STAGE;
        uint32_t sAh = base, sAl = base + GTILE_A, sB = base + 2 * GTILE_A;
        // A tiles: 64 rows x 4 chunks = 256 slots (2 per thread), both hi and lo
#pragma unroll
        for (int i = 0; i < 2; i++) {
            int slot = i * 128 + tid;
            int r = slot >> 2, sg = slot & 3;
            cp_async16(sAh + r * GSTRIDE + sg * 16, Ah + (size_t)(mb + r) * K + k0 + sg * 8);
            cp_async16(sAl + r * GSTRIDE + sg * 16, Al + (size_t)(mb + r) * K + k0 + sg * 8);
        }
        // B tile: 128 rows x 4 chunks = 512 slots (4 per thread)
#pragma unroll
        for (int i = 0; i < 4; i++) {
            int slot = i * 128 + tid;
            int r = slot >> 2, sg = slot & 3;
            cp_async16(sB + r * GSTRIDE + sg * 16, Bh + (size_t)(nb + r) * K + k0 + sg * 8);
        }
        cp_commit();
    };

    float acc[2][8][4];
#pragma unroll
    for (int i = 0; i < 2; i++)
#pragma unroll
        for (int j = 0; j < 8; j++)
#pragma unroll
            for (int e = 0; e < 4; e++) acc[i][j][e] = 0.f;

    const uint32_t aoff = (uint32_t)((lane & 15) * GSTRIDE + (lane >> 4) * 16);
    const uint32_t boff = (uint32_t)(((lane & 7) + ((lane >> 4) * 8)) * GSTRIDE
                                     + (((lane >> 3) & 1) * 16));

    load_stage(0, 0);
    const int niter = K / GBK;
    for (int it = 0; it < niter; it++) {
        cp_wait0();
        __syncthreads();
        if (it + 1 < niter) load_stage((it + 1) & 1, (it + 1) * GBK);

        uint32_t base = sb + (it & 1) * G2STAGE;
        uint32_t bAh = base, bAl = base + GTILE_A, bB = base + 2 * GTILE_A;

#pragma unroll
        for (int ks = 0; ks < 2; ks++) {
            uint32_t kb = (uint32_t)(ks * 32);
            uint32_t ah[2][4], al[2][4];
#pragma unroll
            for (int mi = 0; mi < 2; mi++) {
                uint32_t rowb = (uint32_t)((wm + mi * 16) * GSTRIDE) + kb;
                ldmatrix_x4(ah[mi][0], ah[mi][1], ah[mi][2], ah[mi][3], bAh + rowb + aoff);
                ldmatrix_x4(al[mi][0], al[mi][1], al[mi][2], al[mi][3], bAl + rowb + aoff);
            }
            uint32_t bf[8][2];
#pragma unroll
            for (int nj = 0; nj < 4; nj++) {
                uint32_t rowb = (uint32_t)((wn + nj * 16) * GSTRIDE) + kb;
                uint32_t t0, t1, t2, t3;
                ldmatrix_x4(t0, t1, t2, t3, bB + rowb + boff);
                bf[nj * 2][0] = t0; bf[nj * 2][1] = t1;
                bf[nj * 2 + 1][0] = t2; bf[nj * 2 + 1][1] = t3;
            }
#pragma unroll
            for (int mi = 0; mi < 2; mi++)
#pragma unroll
                for (int nj = 0; nj < 8; nj++) {
                    mma_fp16(acc[mi][nj], ah[mi][0], ah[mi][1], ah[mi][2], ah[mi][3],
                             bf[nj][0], bf[nj][1]);
                    mma_fp16(acc[mi][nj], al[mi][0], al[mi][1], al[mi][2], al[mi][3],
                             bf[nj][0], bf[nj][1]);
                }
        }
        __syncthreads();
    }

    const int g = lane >> 2, c = lane & 3;
#pragma unroll
    for (int mi = 0; mi < 2; mi++) {
#pragma unroll
        for (int nj = 0; nj < 8; nj++) {
            const int col = nb + wn + nj * 8 + 2 * c;
#pragma unroll
            for (int rr = 0; rr < 2; rr++) {
                const int row = mb + wm + mi * 16 + g + rr * 8;
                float v0 = acc[mi][nj][rr * 2 + 0];
                float v1 = acc[mi][nj][rr * 2 + 1];
                const int b = row >> 11, s = row & (S_ - 1);
                const int d = col & 63;
                if (col < DIM_ + NKV_ * HD_) {
                    float2 f = *(const float2*)(fc + (size_t)s * HD_ + d);
                    float rx = v0 * f.x - v1 * f.y;
                    float ry = v1 * f.x + v0 * f.y;
                    v0 = rx; v1 = ry;
                }
                if (col < DIM_) {
                    int h = col >> 6;
                    size_t o = ((size_t)(b * NH_ + h) * S_ + s) * HD_ + d;
                    *(uint32_t*)(Qh + o) = pack_h2(v0, v1);
                } else if (col < DIM_ + NKV_ * HD_) {
                    int kvh = (col - DIM_) >> 6;
                    size_t o = ((size_t)(b * NKV_ + kvh) * S_ + s) * HD_ + d;
                    *(uint32_t*)(Kh + o) = pack_h2(v0, v1);
                } else {
                    int kvh = (col - DIM_ - NKV_ * HD_) >> 6;
                    size_t o = ((size_t)(b * NKV_ + kvh) * S_ + s) * HD_ + d;
                    *(uint32_t*)(Vh + o) = pack_h2(v0, v1);
                }
            }
        }
    }
}

// ---- tc_gemm1: single-term fp16 GEMM (out = att @ woT^T) ----
#define G1STAGE (GTILE_A + GTILE_B)   // 15360
#define G1SMEM (2 * G1STAGE)          // 30720

__global__ __launch_bounds__(128) void tc_gemm1_kernel(
    const __half* __restrict__ A, const __half* __restrict__ B,
    float* __restrict__ C, int N, int K)
{
    extern __shared__ char smem[];
    const uint32_t sb = smem_u32(smem);
    const int tid = threadIdx.x;
    const int wid = tid >> 5;
    const int lane = tid & 31;
    const int mb = blockIdx.y * GBM;
    const int nb = blockIdx.x * GBN;
    const int wm = (wid >> 1) * 32;
    const int wn = (wid & 1) * 64;

    auto load_stage = [&](int stage, int k0) {
        uint32_t base = sb + stage * G1STAGE;
        uint32_t sA = base, sB = base + GTILE_A;
#pragma unroll
        for (int i = 0; i < 2; i++) {
            int slot = i * 128 + tid;
            int r = slot >> 2, sg = slot & 3;
            cp_async16(sA + r * GSTRIDE + sg * 16, A + (size_t)(mb + r) * K + k0 + sg * 8);
        }
#pragma unroll
        for (int i = 0; i < 4; i++) {
            int slot = i * 128 + tid;
            int r = slot >> 2, sg = slot & 3;
            cp_async16(sB + r * GSTRIDE + sg * 16, B + (size_t)(nb + r) * K + k0 + sg * 8);
        }
        cp_commit();
    };

    float acc[2][8][4];
#pragma unroll
    for (int i = 0; i < 2; i++)
#pragma unroll
        for (int j = 0; j < 8; j++)
#pragma unroll
            for (int e = 0; e < 4; e++) acc[i][j][e] = 0.f;

    const uint32_t aoff = (uint32_t)((lane & 15) * GSTRIDE + (lane >> 4) * 16);
    const uint32_t boff = (uint32_t)(((lane & 7) + ((lane >> 4) * 8)) * GSTRIDE
                                     + (((lane >> 3) & 1) * 16));

    load_stage(0, 0);
    const int niter = K / GBK;
    for (int it = 0; it < niter; it++) {
        cp_wait0();
        __syncthreads();
        if (it + 1 < niter) load_stage((it + 1) & 1, (it + 1) * GBK);

        uint32_t base = sb + (it & 1) * G1STAGE;
        uint32_t bA = base, bB = base + GTILE_A;

#pragma unroll
        for (int ks = 0; ks < 2; ks++) {
            uint32_t kb = (uint32_t)(ks * 32);
            uint32_t af[2][4];
#pragma unroll
            for (int mi = 0; mi < 2; mi++) {
                uint32_t rowb = (uint32_t)((wm + mi * 16) * GSTRIDE) + kb;
                ldmatrix_x4(af[mi][0], af[mi][1], af[mi][2], af[mi][3], bA + rowb + aoff);
            }
            uint32_t bf[8][2];
#pragma unroll
            for (int nj = 0; nj < 4; nj++) {
                uint32_t rowb = (uint32_t)((wn + nj * 16) * GSTRIDE) + kb;
                uint32_t t0, t1, t2, t3;
                ldmatrix_x4(t0, t1, t2, t3, bB + rowb + boff);
                bf[nj * 2][0] = t0; bf[nj * 2][1] = t1;
                bf[nj * 2 + 1][0] = t2; bf[nj * 2 + 1][1] = t3;
            }
#pragma unroll
            for (int mi = 0; mi < 2; mi++)
#pragma unroll
                for (int nj = 0; nj < 8; nj++)
                    mma_fp16(acc[mi][nj], af[mi][0], af[mi][1], af[mi][2], af[mi][3],
                             bf[nj][0], bf[nj][1]);
        }
        __syncthreads();
    }

    const int g = lane >> 2, c = lane & 3;
#pragma unroll
    for (int mi = 0; mi < 2; mi++) {
#pragma unroll
        for (int nj = 0; nj < 8; nj++) {
            float* cp0 = C + (size_t)(mb + wm + mi * 16 + g) * N + nb + wn + nj * 8 + 2 * c;
            float* cp1 = cp0 + (size_t)8 * N;
            *(float2*)cp0 = make_float2(acc[mi][nj][0], acc[mi][nj][1]);
            *(float2*)cp1 = make_float2(acc[mi][nj][2], acc[mi][nj][3]);
        }
    }
}

// ============================================================================
// Fused conversion kernel (unchanged from R11)
// ============================================================================
#define NB_A (M_ * DIM_ / 4 / 256)            // 8192
#define NB_B ((KDIM / 32) * (QKVN / 32))      // 6144
#define NB_C ((KDIM / 32) * (DIM_ / 32))      // 4096
#define NB_TOTAL (NB_A + NB_B + NB_C)         // 18432

__global__ __launch_bounds__(256) void conv_fused_kernel(
    const float* __restrict__ x, __half* __restrict__ Xh, __half* __restrict__ Xl,
    const float* __restrict__ wqkv, __half* __restrict__ WqT,
    const float* __restrict__ wo, __half* __restrict__ WoT)
{
    __shared__ float t[32][33];
    const int bid = blockIdx.x;
    const int tid = threadIdx.x;

    if (bid < NB_A) {
        int i = bid * 256 + tid;
        float4 v = *(const float4*)(x + (size_t)i * 4);
        float vv[4] = {v.x, v.y, v.z, v.w};
        __half h[4], l[4];
#pragma unroll
        for (int j = 0; j < 4; j++) {
            h[j] = __float2half_rn(vv[j]);
            l[j] = __float2half_rn(vv[j] - __half2float(h[j]));
        }
        *(uint2*)(Xh + (size_t)i * 4) = *(uint2*)h;
        *(uint2*)(Xl + (size_t)i * 4) = *(uint2*)l;
        return;
    }

    const float* W;
    __half* T;
    int N, tb;
    if (bid < NB_A + NB_B) {
        W = wqkv; T = WqT; N = QKVN; tb = bid - NB_A;
    } else {
        W = wo; T = WoT; N = DIM_; tb = bid - NB_A - NB_B;
    }
    const int ntiles = N / 32;
    const int bx = tb % ntiles, by = tb / ntiles;
    const int k0 = by * 32, n0 = bx * 32;
    const int tx = tid & 31, ty = tid >> 5;
#pragma unroll
    for (int i = 0; i < 32; i += 8)
        t[ty + i][tx] = W[(size_t)(k0 + ty + i) * N + n0 + tx];
    __syncthreads();
#pragma unroll
    for (int i = 0; i < 32; i += 8) {
        float v = t[tx][ty + i];
        T[(size_t)(n0 + ty + i) * KDIM + k0 + tx] = __float2half_rn(v);
    }
}

// ============================================================================
// Flash attention (unchanged from R10/R11)
// ============================================================================
#define FSTR 144
#define FTILE (64 * FSTR)
#define FSTAGE (2 * FTILE)
#define FSMEM (2 * FSTAGE)

__global__ __launch_bounds__(128) void flash_tc_kernel(
    const __half* __restrict__ Qh,
    const __half* __restrict__ Kh,
    const __half* __restrict__ Vh,
    __half* __restrict__ Oh)
{
    extern __shared__ char smem[];
    const uint32_t sb = smem_u32(smem);
    const int tid  = threadIdx.x;
    const int wid  = tid >> 5;
    const int lane = tid & 31;
    const int qtile = blockIdx.x;
    const int h     = blockIdx.y;
    const int b     = blockIdx.z;
    const int kvh   = h >> 2;
    const int q0    = qtile * 64;
    const int wm    = wid * 16;

    const __half* qhp = Qh + ((size_t)(b * NH_ + h) * S_ + q0) * HD_;
    const __half* khp = Kh + ((size_t)(b * NKV_ + kvh) * S_) * HD_;
    const __half* vhp = Vh + ((size_t)(b * NKV_ + kvh) * S_) * HD_;

    const int lr[4] = {(tid) >> 3, (tid + 128) >> 3, (tid + 256) >> 3, (tid + 384) >> 3};
    const int ls = tid & 7;

#pragma unroll
    for (int i = 0; i < 4; i++)
        cp_async16(sb + lr[i] * FSTR + ls * 16, qhp + (size_t)lr[i] * HD_ + ls * 8);
    cp_commit();
    cp_wait0();
    __syncthreads();

    const uint32_t aoff = (uint32_t)((lane & 15) * FSTR + (lane >> 4) * 16);
    const uint32_t boff = (uint32_t)(((lane & 7) + ((lane >> 4) * 8)) * FSTR
                                     + (((lane >> 3) & 1) * 16));
    const uint32_t voff = (uint32_t)(((lane & 7) + (((lane >> 3) & 1) * 8)) * FSTR
                                     + ((lane >> 4) * 16));

    uint32_t qf[4][4];
#pragma unroll
    for (int ks = 0; ks < 4; ks++) {
        uint32_t rowb = (uint32_t)(wm * FSTR + ks * 32);
        ldmatrix_x4(qf[ks][0], qf[ks][1], qf[ks][2], qf[ks][3], sb + rowb + aoff);
    }
    __syncthreads();

    auto load_kv = [&](int st, int j) {
        uint32_t base = sb + st * FSTAGE;
        size_t g0 = (size_t)(j * 64) * HD_;
#pragma unroll
        for (int i = 0; i < 4; i++) {
            uint32_t so = lr[i] * FSTR + ls * 16;
            size_t go = g0 + (size_t)lr[i] * HD_ + ls * 8;
            cp_async16(base + so, khp + go);
            cp_async16(base + FTILE + so, vhp + go);
        }
        cp_commit();
    };
    load_kv(0, 0);

    float m0 = -1e30f, m1 = -1e30f, l0 = 0.f, l1 = 0.f;
    float o[8][4];
#pragma unroll
    for (int nj = 0; nj < 8; nj++)
#pragma unroll
        for (int e = 0; e < 4; e++) o[nj][e] = 0.f;

    const int r0 = lane >> 2;
    const int tig = lane & 3;
    const int qg0 = q0 + wm + r0;
    const int qg1 = qg0 + 8;

    for (int j = 0; j <= qtile; j++) {
        cp_wait0();
        __syncthreads();
        if (j < qtile) load_kv((j + 1) & 1, j + 1);

        uint32_t base = sb + (j & 1) * FSTAGE;
        uint32_t bKh = base;
        uint32_t bVh = base + FTILE;

        float c[8][4];
#pragma unroll
        for (int nj = 0; nj < 8; nj++)
#pragma unroll
            for (int e = 0; e < 4; e++) c[nj][e] = 0.f;

#pragma unroll
        for (int ks = 0; ks < 4; ks++) {
            uint32_t kf[4][4];
#pragma unroll
            for (int njp = 0; njp < 4; njp++) {
                uint32_t off = (uint32_t)(njp * 16 * FSTR + ks * 32) + boff;
                ldmatrix_x4(kf[njp][0], kf[njp][1], kf[njp][2], kf[njp][3], bKh + off);
            }
#pragma unroll
            for (int njp = 0; njp < 4; njp++) {
                mma_fp16(c[2 * njp],     qf[ks][0], qf[ks][1], qf[ks][2], qf[ks][3], kf[njp][0], kf[njp][1]);
                mma_fp16(c[2 * njp + 1], qf[ks][0], qf[ks][1], qf[ks][2], qf[ks][3], kf[njp][2], kf[njp][3]);
            }
        }

        const bool diag = (j == qtile);
        float tm0 = -1e30f, tm1 = -1e30f;
#pragma unroll
        for (int nj = 0; nj < 8; nj++) {
            int colb = j * 64 + nj * 8 + 2 * tig;
#pragma unroll
            for (int e = 0; e < 4; e++) {
                float sv = c[nj][e] * 0.125f;
                if (diag) {
                    int colg = colb + (e & 1);
                    int rowg = (e < 2) ? qg0 : qg1;
                    if (colg > rowg) sv = -1e30f;
                }
                c[nj][e] = sv;
            }
            tm0 = fmaxf(tm0, fmaxf(c[nj][0], c[nj][1]));
            tm1 = fmaxf(tm1, fmaxf(c[nj][2], c[nj][3]));
        }
        tm0 = fmaxf(tm0, __shfl_xor_sync(0xffffffffu, tm0, 1));
        tm0 = fmaxf(tm0, __shfl_xor_sync(0xffffffffu, tm0, 2));
        tm1 = fmaxf(tm1, __shfl_xor_sync(0xffffffffu, tm1, 1));
        tm1 = fmaxf(tm1, __shfl_xor_sync(0xffffffffu, tm1, 2));

        float mn0 = fmaxf(m0, tm0), mn1 = fmaxf(m1, tm1);
        float sc0 = __expf(m0 - mn0), sc1 = __expf(m1 - mn1);
        m0 = mn0; m1 = mn1;

        float sum0 = 0.f, sum1 = 0.f;
#pragma unroll
        for (int nj = 0; nj < 8; nj++) {
            c[nj][0] = __expf(c[nj][0] - mn0);
            c[nj][1] = __expf(c[nj][1] - mn0);
            c[nj][2] = __expf(c[nj][2] - mn1);
            c[nj][3] = __expf(c[nj][3] - mn1);
            sum0 += c[nj][0] + c[nj][1];
            sum1 += c[nj][2] + c[nj][3];
        }
        sum0 += __shfl_xor_sync(0xffffffffu, sum0, 1);
        sum0 += __shfl_xor_sync(0xffffffffu, sum0, 2);
        sum1 += __shfl_xor_sync(0xffffffffu, sum1, 1);
        sum1 += __shfl_xor_sync(0xffffffffu, sum1, 2);
        l0 = l0 * sc0 + sum0;
        l1 = l1 * sc1 + sum1;

#pragma unroll
        for (int nj = 0; nj < 8; nj++) {
            o[nj][0] *= sc0; o[nj][1] *= sc0;
            o[nj][2] *= sc1; o[nj][3] *= sc1;
        }

#pragma unroll
        for (int ksv = 0; ksv < 4; ksv++) {
            uint32_t ap[4];
            ap[0] = pack_h2(c[2 * ksv][0], c[2 * ksv][1]);
            ap[1] = pack_h2(c[2 * ksv][2], c[2 * ksv][3]);
            ap[2] = pack_h2(c[2 * ksv + 1][0], c[2 * ksv + 1][1]);
            ap[3] = pack_h2(c[2 * ksv + 1][2], c[2 * ksv + 1][3]);
#pragma unroll
            for (int njp = 0; njp < 4; njp++) {
                uint32_t off = (uint32_t)(ksv * 16 * FSTR + njp * 32) + voff;
                uint32_t v0, v1, v2, v3;
                ldmatrix_x4_trans(v0, v1, v2, v3, bVh + off);
                mma_fp16(o[2 * njp],     ap[0], ap[1], ap[2], ap[3], v0, v1);
                mma_fp16(o[2 * njp + 1], ap[0], ap[1], ap[2], ap[3], v2, v3);
            }
        }
    }

    float inv0 = 1.f / l0, inv1 = 1.f / l1;
    size_t gr0 = (size_t)(b * S_ + q0 + wm + r0) * DIM_ + h * HD_ + 2 * tig;
    size_t gr1 = gr0 + (size_t)8 * DIM_;
#pragma unroll
    for (int nj = 0; nj < 8; nj++) {
        *(uint32_t*)(Oh + gr0 + nj * 8) = pack_h2(o[nj][0] * inv0, o[nj][1] * inv0);
        *(uint32_t*)(Oh + gr1 + nj * 8) = pack_h2(o[nj][2] * inv1, o[nj][3] * inv1);
    }
}

// ============================================================================
// launch
// ============================================================================
extern "C" void kernel_launch(void* const* d_in, const int* in_sizes, int n_in,
                              void* d_out, int out_size)
{
    const float* x    = (const float*)d_in[0];
    const float* fc   = (const float*)d_in[1];
    const float* wqkv = (const float*)d_in[2];
    const float* wo   = (const float*)d_in[3];
    float* out        = (float*)d_out;

    void *xh_p, *xl_p, *wqh_p, *woh_p, *ah_p;
    void *qh_p, *kh_p, *vh_p;
    cudaGetSymbolAddress(&xh_p, g_x_hi);
    cudaGetSymbolAddress(&xl_p, g_x_lo);
    cudaGetSymbolAddress(&wqh_p, g_wqkvT_hi);
    cudaGetSymbolAddress(&woh_p, g_woT_hi);
    cudaGetSymbolAddress(&ah_p, g_att_hi);
    cudaGetSymbolAddress(&qh_p, g_q_hi);
    cudaGetSymbolAddress(&kh_p, g_k_hi);
    cudaGetSymbolAddress(&vh_p, g_v_hi);

    cudaFuncSetAttribute(tc_gemm2_kernel, cudaFuncAttributeMaxDynamicSharedMemorySize,
                         G2SMEM);
    cudaFuncSetAttribute(tc_gemm1_kernel, cudaFuncAttributeMaxDynamicSharedMemorySize,
                         G1SMEM);
    cudaFuncSetAttribute(flash_tc_kernel, cudaFuncAttributeMaxDynamicSharedMemorySize,
                         FSMEM);

    // 1) all conversions in one launch
    conv_fused_kernel<<<NB_TOTAL, 256>>>(
        x, (__half*)xh_p, (__half*)xl_p,
        wqkv, (__half*)wqh_p,
        wo, (__half*)woh_p);

    // 2) qkv projection (2-term) + fused rope epilogue -> Q/K/V fp16
    tc_gemm2_kernel<<<dim3(QKVN / GBN, M_ / GBM), 128, G2SMEM>>>(
        (const __half*)xh_p, (const __half*)xl_p,
        (const __half*)wqh_p, fc,
        (__half*)qh_p, (__half*)kh_p, (__half*)vh_p,
        QKVN, KDIM);

    // 3) flash attention (QK 1-term, PV 1-term) -> att fp16
    flash_tc_kernel<<<dim3(S_ / 64, NH_, B_), 128, FSMEM>>>(
        (const __half*)qh_p, (const __half*)kh_p, (const __half*)vh_p,
        (__half*)ah_p);

    // 4) out = att @ wo (1-term fp16)
    tc_gemm1_kernel<<<dim3(DIM_ / GBN, M_ / GBM), 128, G1SMEM>>>(
        (const __half*)ah_p, (const __half*)woh_p, out, DIM_, KDIM);
}

// round 13
// speedup vs baseline: 7.4512x; 1.0231x over previous
#include <cuda_runtime.h>
#include <cuda_fp16.h>
#include <cstdint>

// ---------------- problem constants ----------------
#define B_   2
#define S_   2048
#define DIM_ 2048
#define NH_  32
#define NKV_ 8
#define HD_  64
#define QKVN 3072
#define M_   (B_ * S_)
#define KDIM 2048

// ---------------- scratch (fp16) ----------------
__device__ __half g_x_hi[(size_t)M_ * DIM_];
__device__ __half g_x_lo[(size_t)M_ * DIM_];
__device__ __half g_wqkvT_hi[(size_t)QKVN * DIM_];
__device__ __half g_woT_hi[(size_t)DIM_ * DIM_];
__device__ __half g_att_hi[(size_t)M_ * DIM_];
__device__ __half g_q_hi[(size_t)B_ * NH_ * S_ * HD_];
__device__ __half g_k_hi[(size_t)B_ * NKV_ * S_ * HD_];
__device__ __half g_v_hi[(size_t)B_ * NKV_ * S_ * HD_];

// ============================================================================
// helpers (sm_80-compatible only)
// ============================================================================
__device__ __forceinline__ uint32_t smem_u32(const void* p) {
    uint32_t a;
    asm("{ .reg .u64 t; cvta.to.shared.u64 t, %1; cvt.u32.u64 %0, t; }"
        : "=r"(a) : "l"(p));
    return a;
}
__device__ __forceinline__ void cp_async16(uint32_t s, const void* g) {
    asm volatile("cp.async.cg.shared.global [%0], [%1], 16;" :: "r"(s), "l"(g));
}
__device__ __forceinline__ void cp_commit() {
    asm volatile("cp.async.commit_group;" ::: "memory");
}
__device__ __forceinline__ void cp_wait0() {
    asm volatile("cp.async.wait_group 0;" ::: "memory");
}
__device__ __forceinline__ void ldmatrix_x4(uint32_t& r0, uint32_t& r1,
                                            uint32_t& r2, uint32_t& r3, uint32_t a) {
    asm volatile("ldmatrix.sync.aligned.m8n8.x4.shared.b16 {%0,%1,%2,%3}, [%4];"
                 : "=r"(r0), "=r"(r1), "=r"(r2), "=r"(r3) : "r"(a));
}
__device__ __forceinline__ void ldmatrix_x4_trans(uint32_t& r0, uint32_t& r1,
                                                  uint32_t& r2, uint32_t& r3, uint32_t a) {
    asm volatile("ldmatrix.sync.aligned.m8n8.x4.trans.shared.b16 {%0,%1,%2,%3}, [%4];"
                 : "=r"(r0), "=r"(r1), "=r"(r2), "=r"(r3) : "r"(a));
}
__device__ __forceinline__ void mma_fp16(float* c, uint32_t a0, uint32_t a1,
                                         uint32_t a2, uint32_t a3,
                                         uint32_t b0, uint32_t b1) {
    asm volatile(
        "mma.sync.aligned.m16n8k16.row.col.f32.f16.f16.f32 "
        "{%0,%1,%2,%3}, {%4,%5,%6,%7}, {%8,%9}, {%0,%1,%2,%3};"
        : "+f"(c[0]), "+f"(c[1]), "+f"(c[2]), "+f"(c[3])
        : "r"(a0), "r"(a1), "r"(a2), "r"(a3), "r"(b0), "r"(b1));
}
__device__ __forceinline__ uint32_t pack_h2(float a, float b) {
    __half2 t = __floats2half2_rn(a, b);
    return *(uint32_t*)&t;
}

// ============================================================================
// GEMM tiling: 64 M-rows per CTA, BK=64 (32 iterations, 4 k-steps each)
// ============================================================================
#define GBM 64
#define GBN 128
#define GBK 64
#define GSTRIDE 144                   // 64 halves (128B) + 16B pad
#define GTILE_A (GBM * GSTRIDE)       // 9216 B
#define GTILE_B (GBN * GSTRIDE)       // 18432 B

// ---- tc_gemm2: C = (Ah+Al) @ Bh^T, fused rope + Q/K/V epilogue ----
#define G2STAGE (2 * GTILE_A + GTILE_B)   // 36864
#define G2SMEM (2 * G2STAGE)              // 73728

__global__ __launch_bounds__(128) void tc_gemm2_kernel(
    const __half* __restrict__ Ah, const __half* __restrict__ Al,
    const __half* __restrict__ Bh,
    const float* __restrict__ fc,
    __half* __restrict__ Qh,
    __half* __restrict__ Kh,
    __half* __restrict__ Vh,
    int N, int K)
{
    extern __shared__ char smem[];
    const uint32_t sb = smem_u32(smem);
    const int tid = threadIdx.x;
    const int wid = tid >> 5;
    const int lane = tid & 31;
    const int mb = blockIdx.y * GBM;
    const int nb = blockIdx.x * GBN;
    const int wm = (wid >> 1) * 32;    // warp tile 32x64
    const int wn = (wid & 1) * 64;

    auto load_stage = [&](int stage, int k0) {
        uint32_t base = sb + stage * G2STAGE;
        uint32_t sAh = base, sAl = base + GTILE_A, sB = base + 2 * GTILE_A;
        // A tiles: 64 rows x 8 chunks = 512 slots (4 per thread), hi and lo
#pragma unroll
        for (int i = 0; i < 4; i++) {
            int slot = i * 128 + tid;
            int r = slot >> 3, sg = slot & 7;
            cp_async16(sAh + r * GSTRIDE + sg * 16, Ah + (size_t)(mb + r) * K + k0 + sg * 8);
            cp_async16(sAl + r * GSTRIDE + sg * 16, Al + (size_t)(mb + r) * K + k0 + sg * 8);
        }
        // B tile: 128 rows x 8 chunks = 1024 slots (8 per thread)
#pragma unroll
        for (int i = 0; i < 8; i++) {
            int slot = i * 128 + tid;
            int r = slot >> 3, sg = slot & 7;
            cp_async16(sB + r * GSTRIDE + sg * 16, Bh + (size_t)(nb + r) * K + k0 + sg * 8);
        }
        cp_commit();
    };

    float acc[2][8][4];
#pragma unroll
    for (int i = 0; i < 2; i++)
#pragma unroll
        for (int j = 0; j < 8; j++)
#pragma unroll
            for (int e = 0; e < 4; e++) acc[i][j][e] = 0.f;

    const uint32_t aoff = (uint32_t)((lane & 15) * GSTRIDE + (lane >> 4) * 16);
    const uint32_t boff = (uint32_t)(((lane & 7) + ((lane >> 4) * 8)) * GSTRIDE
                                     + (((lane >> 3) & 1) * 16));

    load_stage(0, 0);
    const int niter = K / GBK;
    for (int it = 0; it < niter; it++) {
        cp_wait0();
        __syncthreads();
        if (it + 1 < niter) load_stage((it + 1) & 1, (it + 1) * GBK);

        uint32_t base = sb + (it & 1) * G2STAGE;
        uint32_t bAh = base, bAl = base + GTILE_A, bB = base + 2 * GTILE_A;

#pragma unroll
        for (int ks = 0; ks < 4; ks++) {
            uint32_t kb = (uint32_t)(ks * 32);
            uint32_t ah[2][4], al[2][4];
#pragma unroll
            for (int mi = 0; mi < 2; mi++) {
                uint32_t rowb = (uint32_t)((wm + mi * 16) * GSTRIDE) + kb;
                ldmatrix_x4(ah[mi][0], ah[mi][1], ah[mi][2], ah[mi][3], bAh + rowb + aoff);
                ldmatrix_x4(al[mi][0], al[mi][1], al[mi][2], al[mi][3], bAl + rowb + aoff);
            }
            uint32_t bf[8][2];
#pragma unroll
            for (int nj = 0; nj < 4; nj++) {
                uint32_t rowb = (uint32_t)((wn + nj * 16) * GSTRIDE) + kb;
                uint32_t t0, t1, t2, t3;
                ldmatrix_x4(t0, t1, t2, t3, bB + rowb + boff);
                bf[nj * 2][0] = t0; bf[nj * 2][1] = t1;
                bf[nj * 2 + 1][0] = t2; bf[nj * 2 + 1][1] = t3;
            }
#pragma unroll
            for (int mi = 0; mi < 2; mi++)
#pragma unroll
                for (int nj = 0; nj < 8; nj++) {
                    mma_fp16(acc[mi][nj], ah[mi][0], ah[mi][1], ah[mi][2], ah[mi][3],
                             bf[nj][0], bf[nj][1]);
                    mma_fp16(acc[mi][nj], al[mi][0], al[mi][1], al[mi][2], al[mi][3],
                             bf[nj][0], bf[nj][1]);
                }
        }
        __syncthreads();
    }

    const int g = lane >> 2, c = lane & 3;
#pragma unroll
    for (int mi = 0; mi < 2; mi++) {
#pragma unroll
        for (int nj = 0; nj < 8; nj++) {
            const int col = nb + wn + nj * 8 + 2 * c;
#pragma unroll
            for (int rr = 0; rr < 2; rr++) {
                const int row = mb + wm + mi * 16 + g + rr * 8;
                float v0 = acc[mi][nj][rr * 2 + 0];
                float v1 = acc[mi][nj][rr * 2 + 1];
                const int b = row >> 11, s = row & (S_ - 1);
                const int d = col & 63;
                if (col < DIM_ + NKV_ * HD_) {
                    float2 f = *(const float2*)(fc + (size_t)s * HD_ + d);
                    float rx = v0 * f.x - v1 * f.y;
                    float ry = v1 * f.x + v0 * f.y;
                    v0 = rx; v1 = ry;
                }
                if (col < DIM_) {
                    int h = col >> 6;
                    size_t o = ((size_t)(b * NH_ + h) * S_ + s) * HD_ + d;
                    *(uint32_t*)(Qh + o) = pack_h2(v0, v1);
                } else if (col < DIM_ + NKV_ * HD_) {
                    int kvh = (col - DIM_) >> 6;
                    size_t o = ((size_t)(b * NKV_ + kvh) * S_ + s) * HD_ + d;
                    *(uint32_t*)(Kh + o) = pack_h2(v0, v1);
                } else {
                    int kvh = (col - DIM_ - NKV_ * HD_) >> 6;
                    size_t o = ((size_t)(b * NKV_ + kvh) * S_ + s) * HD_ + d;
                    *(uint32_t*)(Vh + o) = pack_h2(v0, v1);
                }
            }
        }
    }
}

// ---- tc_gemm1: single-term fp16 GEMM (out = att @ woT^T), BK=64 ----
#define G1STAGE (GTILE_A + GTILE_B)   // 27648
#define G1SMEM (2 * G1STAGE)          // 55296

__global__ __launch_bounds__(128) void tc_gemm1_kernel(
    const __half* __restrict__ A, const __half* __restrict__ B,
    float* __restrict__ C, int N, int K)
{
    extern __shared__ char smem[];
    const uint32_t sb = smem_u32(smem);
    const int tid = threadIdx.x;
    const int wid = tid >> 5;
    const int lane = tid & 31;
    const int mb = blockIdx.y * GBM;
    const int nb = blockIdx.x * GBN;
    const int wm = (wid >> 1) * 32;
    const int wn = (wid & 1) * 64;

    auto load_stage = [&](int stage, int k0) {
        uint32_t base = sb + stage * G1STAGE;
        uint32_t sA = base, sB = base + GTILE_A;
#pragma unroll
        for (int i = 0; i < 4; i++) {
            int slot = i * 128 + tid;
            int r = slot >> 3, sg = slot & 7;
            cp_async16(sA + r * GSTRIDE + sg * 16, A + (size_t)(mb + r) * K + k0 + sg * 8);
        }
#pragma unroll
        for (int i = 0; i < 8; i++) {
            int slot = i * 128 + tid;
            int r = slot >> 3, sg = slot & 7;
            cp_async16(sB + r * GSTRIDE + sg * 16, B + (size_t)(nb + r) * K + k0 + sg * 8);
        }
        cp_commit();
    };

    float acc[2][8][4];
#pragma unroll
    for (int i = 0; i < 2; i++)
#pragma unroll
        for (int j = 0; j < 8; j++)
#pragma unroll
            for (int e = 0; e < 4; e++) acc[i][j][e] = 0.f;

    const uint32_t aoff = (uint32_t)((lane & 15) * GSTRIDE + (lane >> 4) * 16);
    const uint32_t boff = (uint32_t)(((lane & 7) + ((lane >> 4) * 8)) * GSTRIDE
                                     + (((lane >> 3) & 1) * 16));

    load_stage(0, 0);
    const int niter = K / GBK;
    for (int it = 0; it < niter; it++) {
        cp_wait0();
        __syncthreads();
        if (it + 1 < niter) load_stage((it + 1) & 1, (it + 1) * GBK);

        uint32_t base = sb + (it & 1) * G1STAGE;
        uint32_t bA = base, bB = base + GTILE_A;

#pragma unroll
        for (int ks = 0; ks < 4; ks++) {
            uint32_t kb = (uint32_t)(ks * 32);
            uint32_t af[2][4];
#pragma unroll
            for (int mi = 0; mi < 2; mi++) {
                uint32_t rowb = (uint32_t)((wm + mi * 16) * GSTRIDE) + kb;
                ldmatrix_x4(af[mi][0], af[mi][1], af[mi][2], af[mi][3], bA + rowb + aoff);
            }
            uint32_t bf[8][2];
#pragma unroll
            for (int nj = 0; nj < 4; nj++) {
                uint32_t rowb = (uint32_t)((wn + nj * 16) * GSTRIDE) + kb;
                uint32_t t0, t1, t2, t3;
                ldmatrix_x4(t0, t1, t2, t3, bB + rowb + boff);
                bf[nj * 2][0] = t0; bf[nj * 2][1] = t1;
                bf[nj * 2 + 1][0] = t2; bf[nj * 2 + 1][1] = t3;
            }
#pragma unroll
            for (int mi = 0; mi < 2; mi++)
#pragma unroll
                for (int nj = 0; nj < 8; nj++)
                    mma_fp16(acc[mi][nj], af[mi][0], af[mi][1], af[mi][2], af[mi][3],
                             bf[nj][0], bf[nj][1]);
        }
        __syncthreads();
    }

    const int g = lane >> 2, c = lane & 3;
#pragma unroll
    for (int mi = 0; mi < 2; mi++) {
#pragma unroll
        for (int nj = 0; nj < 8; nj++) {
            float* cp0 = C + (size_t)(mb + wm + mi * 16 + g) * N + nb + wn + nj * 8 + 2 * c;
            float* cp1 = cp0 + (size_t)8 * N;
            *(float2*)cp0 = make_float2(acc[mi][nj][0], acc[mi][nj][1]);
            *(float2*)cp1 = make_float2(acc[mi][nj][2], acc[mi][nj][3]);
        }
    }
}

// ============================================================================
// Fused conversion kernel (unchanged)
// ============================================================================
#define NB_A (M_ * DIM_ / 4 / 256)            // 8192
#define NB_B ((KDIM / 32) * (QKVN / 32))      // 6144
#define NB_C ((KDIM / 32) * (DIM_ / 32))      // 4096
#define NB_TOTAL (NB_A + NB_B + NB_C)         // 18432

__global__ __launch_bounds__(256) void conv_fused_kernel(
    const float* __restrict__ x, __half* __restrict__ Xh, __half* __restrict__ Xl,
    const float* __restrict__ wqkv, __half* __restrict__ WqT,
    const float* __restrict__ wo, __half* __restrict__ WoT)
{
    __shared__ float t[32][33];
    const int bid = blockIdx.x;
    const int tid = threadIdx.x;

    if (bid < NB_A) {
        int i = bid * 256 + tid;
        float4 v = *(const float4*)(x + (size_t)i * 4);
        float vv[4] = {v.x, v.y, v.z, v.w};
        __half h[4], l[4];
#pragma unroll
        for (int j = 0; j < 4; j++) {
            h[j] = __float2half_rn(vv[j]);
            l[j] = __float2half_rn(vv[j] - __half2float(h[j]));
        }
        *(uint2*)(Xh + (size_t)i * 4) = *(uint2*)h;
        *(uint2*)(Xl + (size_t)i * 4) = *(uint2*)l;
        return;
    }

    const float* W;
    __half* T;
    int N, tb;
    if (bid < NB_A + NB_B) {
        W = wqkv; T = WqT; N = QKVN; tb = bid - NB_A;
    } else {
        W = wo; T = WoT; N = DIM_; tb = bid - NB_A - NB_B;
    }
    const int ntiles = N / 32;
    const int bx = tb % ntiles, by = tb / ntiles;
    const int k0 = by * 32, n0 = bx * 32;
    const int tx = tid & 31, ty = tid >> 5;
#pragma unroll
    for (int i = 0; i < 32; i += 8)
        t[ty + i][tx] = W[(size_t)(k0 + ty + i) * N + n0 + tx];
    __syncthreads();
#pragma unroll
    for (int i = 0; i < 32; i += 8) {
        float v = t[tx][ty + i];
        T[(size_t)(n0 + ty + i) * KDIM + k0 + tx] = __float2half_rn(v);
    }
}

// ============================================================================
// Flash attention (unchanged)
// ============================================================================
#define FSTR 144
#define FTILE (64 * FSTR)
#define FSTAGE (2 * FTILE)
#define FSMEM (2 * FSTAGE)

__global__ __launch_bounds__(128) void flash_tc_kernel(
    const __half* __restrict__ Qh,
    const __half* __restrict__ Kh,
    const __half* __restrict__ Vh,
    __half* __restrict__ Oh)
{
    extern __shared__ char smem[];
    const uint32_t sb = smem_u32(smem);
    const int tid  = threadIdx.x;
    const int wid  = tid >> 5;
    const int lane = tid & 31;
    const int qtile = blockIdx.x;
    const int h     = blockIdx.y;
    const int b     = blockIdx.z;
    const int kvh   = h >> 2;
    const int q0    = qtile * 64;
    const int wm    = wid * 16;

    const __half* qhp = Qh + ((size_t)(b * NH_ + h) * S_ + q0) * HD_;
    const __half* khp = Kh + ((size_t)(b * NKV_ + kvh) * S_) * HD_;
    const __half* vhp = Vh + ((size_t)(b * NKV_ + kvh) * S_) * HD_;

    const int lr[4] = {(tid) >> 3, (tid + 128) >> 3, (tid + 256) >> 3, (tid + 384) >> 3};
    const int ls = tid & 7;

#pragma unroll
    for (int i = 0; i < 4; i++)
        cp_async16(sb + lr[i] * FSTR + ls * 16, qhp + (size_t)lr[i] * HD_ + ls * 8);
    cp_commit();
    cp_wait0();
    __syncthreads();

    const uint32_t aoff = (uint32_t)((lane & 15) * FSTR + (lane >> 4) * 16);
    const uint32_t boff = (uint32_t)(((lane & 7) + ((lane >> 4) * 8)) * FSTR
                                     + (((lane >> 3) & 1) * 16));
    const uint32_t voff = (uint32_t)(((lane & 7) + (((lane >> 3) & 1) * 8)) * FSTR
                                     + ((lane >> 4) * 16));

    uint32_t qf[4][4];
#pragma unroll
    for (int ks = 0; ks < 4; ks++) {
        uint32_t rowb = (uint32_t)(wm * FSTR + ks * 32);
        ldmatrix_x4(qf[ks][0], qf[ks][1], qf[ks][2], qf[ks][3], sb + rowb + aoff);
    }
    __syncthreads();

    auto load_kv = [&](int st, int j) {
        uint32_t base = sb + st * FSTAGE;
        size_t g0 = (size_t)(j * 64) * HD_;
#pragma unroll
        for (int i = 0; i < 4; i++) {
            uint32_t so = lr[i] * FSTR + ls * 16;
            size_t go = g0 + (size_t)lr[i] * HD_ + ls * 8;
            cp_async16(base + so, khp + go);
            cp_async16(base + FTILE + so, vhp + go);
        }
        cp_commit();
    };
    load_kv(0, 0);

    float m0 = -1e30f, m1 = -1e30f, l0 = 0.f, l1 = 0.f;
    float o[8][4];
#pragma unroll
    for (int nj = 0; nj < 8; nj++)
#pragma unroll
        for (int e = 0; e < 4; e++) o[nj][e] = 0.f;

    const int r0 = lane >> 2;
    const int tig = lane & 3;
    const int qg0 = q0 + wm + r0;
    const int qg1 = qg0 + 8;

    for (int j = 0; j <= qtile; j++) {
        cp_wait0();
        __syncthreads();
        if (j < qtile) load_kv((j + 1) & 1, j + 1);

        uint32_t base = sb + (j & 1) * FSTAGE;
        uint32_t bKh = base;
        uint32_t bVh = base + FTILE;

        float c[8][4];
#pragma unroll
        for (int nj = 0; nj < 8; nj++)
#pragma unroll
            for (int e = 0; e < 4; e++) c[nj][e] = 0.f;

#pragma unroll
        for (int ks = 0; ks < 4; ks++) {
            uint32_t kf[4][4];
#pragma unroll
            for (int njp = 0; njp < 4; njp++) {
                uint32_t off = (uint32_t)(njp * 16 * FSTR + ks * 32) + boff;
                ldmatrix_x4(kf[njp][0], kf[njp][1], kf[njp][2], kf[njp][3], bKh + off);
            }
#pragma unroll
            for (int njp = 0; njp < 4; njp++) {
                mma_fp16(c[2 * njp],     qf[ks][0], qf[ks][1], qf[ks][2], qf[ks][3], kf[njp][0], kf[njp][1]);
                mma_fp16(c[2 * njp + 1], qf[ks][0], qf[ks][1], qf[ks][2], qf[ks][3], kf[njp][2], kf[njp][3]);
            }
        }

        const bool diag = (j == qtile);
        float tm0 = -1e30f, tm1 = -1e30f;
#pragma unroll
        for (int nj = 0; nj < 8; nj++) {
            int colb = j * 64 + nj * 8 + 2 * tig;
#pragma unroll
            for (int e = 0; e < 4; e++) {
                float sv = c[nj][e] * 0.125f;
                if (diag) {
                    int colg = colb + (e & 1);
                    int rowg = (e < 2) ? qg0 : qg1;
                    if (colg > rowg) sv = -1e30f;
                }
                c[nj][e] = sv;
            }
            tm0 = fmaxf(tm0, fmaxf(c[nj][0], c[nj][1]));
            tm1 = fmaxf(tm1, fmaxf(c[nj][2], c[nj][3]));
        }
        tm0 = fmaxf(tm0, __shfl_xor_sync(0xffffffffu, tm0, 1));
        tm0 = fmaxf(tm0, __shfl_xor_sync(0xffffffffu, tm0, 2));
        tm1 = fmaxf(tm1, __shfl_xor_sync(0xffffffffu, tm1, 1));
        tm1 = fmaxf(tm1, __shfl_xor_sync(0xffffffffu, tm1, 2));

        float mn0 = fmaxf(m0, tm0), mn1 = fmaxf(m1, tm1);
        float sc0 = __expf(m0 - mn0), sc1 = __expf(m1 - mn1);
        m0 = mn0; m1 = mn1;

        float sum0 = 0.f, sum1 = 0.f;
#pragma unroll
        for (int nj = 0; nj < 8; nj++) {
            c[nj][0] = __expf(c[nj][0] - mn0);
            c[nj][1] = __expf(c[nj][1] - mn0);
            c[nj][2] = __expf(c[nj][2] - mn1);
            c[nj][3] = __expf(c[nj][3] - mn1);
            sum0 += c[nj][0] + c[nj][1];
            sum1 += c[nj][2] + c[nj][3];
        }
        sum0 += __shfl_xor_sync(0xffffffffu, sum0, 1);
        sum0 += __shfl_xor_sync(0xffffffffu, sum0, 2);
        sum1 += __shfl_xor_sync(0xffffffffu, sum1, 1);
        sum1 += __shfl_xor_sync(0xffffffffu, sum1, 2);
        l0 = l0 * sc0 + sum0;
        l1 = l1 * sc1 + sum1;

#pragma unroll
        for (int nj = 0; nj < 8; nj++) {
            o[nj][0] *= sc0; o[nj][1] *= sc0;
            o[nj][2] *= sc1; o[nj][3] *= sc1;
        }

#pragma unroll
        for (int ksv = 0; ksv < 4; ksv++) {
            uint32_t ap[4];
            ap[0] = pack_h2(c[2 * ksv][0], c[2 * ksv][1]);
            ap[1] = pack_h2(c[2 * ksv][2], c[2 * ksv][3]);
            ap[2] = pack_h2(c[2 * ksv + 1][0], c[2 * ksv + 1][1]);
            ap[3] = pack_h2(c[2 * ksv + 1][2], c[2 * ksv + 1][3]);
#pragma unroll
            for (int njp = 0; njp < 4; njp++) {
                uint32_t off = (uint32_t)(ksv * 16 * FSTR + njp * 32) + voff;
                uint32_t v0, v1, v2, v3;
                ldmatrix_x4_trans(v0, v1, v2, v3, bVh + off);
                mma_fp16(o[2 * njp],     ap[0], ap[1], ap[2], ap[3], v0, v1);
                mma_fp16(o[2 * njp + 1], ap[0], ap[1], ap[2], ap[3], v2, v3);
            }
        }
    }

    float inv0 = 1.f / l0, inv1 = 1.f / l1;
    size_t gr0 = (size_t)(b * S_ + q0 + wm + r0) * DIM_ + h * HD_ + 2 * tig;
    size_t gr1 = gr0 + (size_t)8 * DIM_;
#pragma unroll
    for (int nj = 0; nj < 8; nj++) {
        *(uint32_t*)(Oh + gr0 + nj * 8) = pack_h2(o[nj][0] * inv0, o[nj][1] * inv0);
        *(uint32_t*)(Oh + gr1 + nj * 8) = pack_h2(o[nj][2] * inv1, o[nj][3] * inv1);
    }
}

// ============================================================================
// launch
// ============================================================================
extern "C" void kernel_launch(void* const* d_in, const int* in_sizes, int n_in,
                              void* d_out, int out_size)
{
    const float* x    = (const float*)d_in[0];
    const float* fc   = (const float*)d_in[1];
    const float* wqkv = (const float*)d_in[2];
    const float* wo   = (const float*)d_in[3];
    float* out        = (float*)d_out;

    void *xh_p, *xl_p, *wqh_p, *woh_p, *ah_p;
    void *qh_p, *kh_p, *vh_p;
    cudaGetSymbolAddress(&xh_p, g_x_hi);
    cudaGetSymbolAddress(&xl_p, g_x_lo);
    cudaGetSymbolAddress(&wqh_p, g_wqkvT_hi);
    cudaGetSymbolAddress(&woh_p, g_woT_hi);
    cudaGetSymbolAddress(&ah_p, g_att_hi);
    cudaGetSymbolAddress(&qh_p, g_q_hi);
    cudaGetSymbolAddress(&kh_p, g_k_hi);
    cudaGetSymbolAddress(&vh_p, g_v_hi);

    cudaFuncSetAttribute(tc_gemm2_kernel, cudaFuncAttributeMaxDynamicSharedMemorySize,
                         G2SMEM);
    cudaFuncSetAttribute(tc_gemm1_kernel, cudaFuncAttributeMaxDynamicSharedMemorySize,
                         G1SMEM);
    cudaFuncSetAttribute(flash_tc_kernel, cudaFuncAttributeMaxDynamicSharedMemorySize,
                         FSMEM);

    // 1) all conversions in one launch
    conv_fused_kernel<<<NB_TOTAL, 256>>>(
        x, (__half*)xh_p, (__half*)xl_p,
        wqkv, (__half*)wqh_p,
        wo, (__half*)woh_p);

    // 2) qkv projection (2-term) + fused rope epilogue -> Q/K/V fp16
    tc_gemm2_kernel<<<dim3(QKVN / GBN, M_ / GBM), 128, G2SMEM>>>(
        (const __half*)xh_p, (const __half*)xl_p,
        (const __half*)wqh_p, fc,
        (__half*)qh_p, (__half*)kh_p, (__half*)vh_p,
        QKVN, KDIM);

    // 3) flash attention (QK 1-term, PV 1-term) -> att fp16
    flash_tc_kernel<<<dim3(S_ / 64, NH_, B_), 128, FSMEM>>>(
        (const __half*)qh_p, (const __half*)kh_p, (const __half*)vh_p,
        (__half*)ah_p);

    // 4) out = att @ wo (1-term fp16)
    tc_gemm1_kernel<<<dim3(DIM_ / GBN, M_ / GBM), 128, G1SMEM>>>(
        (const __half*)ah_p, (const __half*)woh_p, out, DIM_, KDIM);
}